// round 1
// baseline (speedup 1.0000x reference)
#include <cuda_runtime.h>
#include <math.h>

#define NB 8
#define NN 2000
#define HH 64
#define DD 16
#define OUTC 4096

// ---------------- scratch (static __device__ — no allocations) ----------------
__device__ float d_h  [NB*NN*HH];            // hidden after relu      (B,N,H)
__device__ float d_e1 [NB*NN];
__device__ float d_e2 [NB*NN];
__device__ float d_A  [(size_t)NN*NN];       // adaptive adjacency     (N,N)
__device__ float d_T  [(size_t)NB*NN*NN];    // sigmoid(prod+bs)       (B,N,N)
__device__ float d_L  [(size_t)NB*NN*NN];    // logits -> E in place   (B,N,N)
__device__ float d_Ah [NB*NN*HH];            // A @ h                  (B,N,H)
__device__ float d_xg0[NB*NN*HH];            // E @ h
__device__ float d_xg1[NB*NN*HH];            // E @ (A @ h)
__device__ float d_wn [(size_t)NN*128*HH];   // per-node weights       (N,128,64)
__device__ float d_g  [NB*NN*HH];            // graph-conv output      (B,N,H)

// ---------------- K1: h = relu(z @ W_in^T + b_in), e1 = h.w1, e2 = h.w2 -------
__global__ void k_hidden(const float* __restrict__ z, const float* __restrict__ Win,
                         const float* __restrict__ bin, const float* __restrict__ w1,
                         const float* __restrict__ w2) {
    __shared__ float zs[64];
    __shared__ float Ws[64*64];   // transposed: Ws[c*64+h]
    __shared__ float r1s[2], r2s[2];
    int row = blockIdx.x;
    int tid = threadIdx.x;
    zs[tid] = z[(size_t)row*64 + tid];
    for (int i = tid; i < 4096; i += 64) {
        int h = i >> 6, c = i & 63;
        Ws[c*64 + h] = Win[i];
    }
    __syncthreads();
    float acc = bin[tid];
#pragma unroll 16
    for (int c = 0; c < 64; c++) acc += zs[c] * Ws[c*64 + tid];
    float hv = fmaxf(acc, 0.f);
    d_h[(size_t)row*64 + tid] = hv;
    float p1 = hv * w1[tid], p2 = hv * w2[tid];
#pragma unroll
    for (int o = 16; o > 0; o >>= 1) {
        p1 += __shfl_down_sync(0xffffffffu, p1, o);
        p2 += __shfl_down_sync(0xffffffffu, p2, o);
    }
    int warp = tid >> 5;
    if ((tid & 31) == 0) { r1s[warp] = p1; r2s[warp] = p2; }
    __syncthreads();
    if (tid == 0) { d_e1[row] = r1s[0] + r1s[1]; d_e2[row] = r2s[0] + r2s[1]; }
}

// ---------------- K2: A = softmax(relu(emb @ emb^T), axis=1) ------------------
__global__ void k_adj(const float* __restrict__ emb) {
    __shared__ float buf[NN];
    __shared__ float red[256];
    __shared__ float ei[16];
    int i = blockIdx.x, tid = threadIdx.x;
    if (tid < 16) ei[tid] = emb[i*16 + tid];
    __syncthreads();
    float mx = -1e30f;
    for (int j = tid; j < NN; j += 256) {
        const float* er = emb + (size_t)j*16;
        float dsum = 0.f;
#pragma unroll
        for (int d = 0; d < 16; d++) dsum += ei[d]*er[d];
        dsum = fmaxf(dsum, 0.f);
        buf[j] = dsum;
        mx = fmaxf(mx, dsum);
    }
    red[tid] = mx; __syncthreads();
    for (int s = 128; s > 0; s >>= 1) { if (tid < s) red[tid] = fmaxf(red[tid], red[tid+s]); __syncthreads(); }
    mx = red[0]; __syncthreads();
    float sum = 0.f;
    for (int j = tid; j < NN; j += 256) { float v = expf(buf[j]-mx); buf[j] = v; sum += v; }
    red[tid] = sum; __syncthreads();
    for (int s = 128; s > 0; s >>= 1) { if (tid < s) red[tid] += red[tid+s]; __syncthreads(); }
    float inv = 1.f/red[0];
    for (int j = tid; j < NN; j += 256) d_A[(size_t)i*NN + j] = buf[j]*inv;
}

// ---------------- K3: T[b,m,p] = sigmoid(e1[b,m]*e2[b,p] + bs[m,p]) -----------
__global__ void k_T(const float* __restrict__ bs) {
    int p = blockIdx.x*256 + threadIdx.x;
    int m = blockIdx.y;
    if (p >= NN) return;
    float bsv = bs[(size_t)m*NN + p];
#pragma unroll
    for (int b = 0; b < NB; b++) {
        float x = d_e1[b*NN+m]*d_e2[b*NN+p] + bsv;
        d_T[((size_t)b*NN + m)*NN + p] = 1.f/(1.f + expf(-x));
    }
}

// ---------------- K4: L[b] = vs @ T[b]   (the dominant N^3 GEMM) --------------
__global__ void __launch_bounds__(256) k_biggemm(const float* __restrict__ vsM) {
    __shared__ float As[16][128];
    __shared__ float Bs[16][128];
    int b = blockIdx.z;
    const float* Bm = d_T + (size_t)b*NN*NN;
    float*       Cm = d_L + (size_t)b*NN*NN;
    int m0 = blockIdx.y*128, n0 = blockIdx.x*128;
    int tid = threadIdx.x;
    int ty = tid>>4, tx = tid&15;
    float acc[8][8];
#pragma unroll
    for (int i=0;i<8;i++)
#pragma unroll
        for (int j=0;j<8;j++) acc[i][j]=0.f;

    for (int k0 = 0; k0 < NN; k0 += 16) {
#pragma unroll
        for (int l = 0; l < 2; l++) {
            int i = tid + l*256;
            int row = i>>2, k4 = (i&3)*4;
            float4 v = make_float4(0.f,0.f,0.f,0.f);
            int gm = m0+row;
            if (gm < NN) v = *(const float4*)&vsM[(size_t)gm*NN + k0 + k4];
            As[k4  ][row]=v.x; As[k4+1][row]=v.y; As[k4+2][row]=v.z; As[k4+3][row]=v.w;
        }
#pragma unroll
        for (int l = 0; l < 2; l++) {
            int i = tid + l*256;
            int kr = i>>5, n4 = (i&31)*4;
            float4 v = make_float4(0.f,0.f,0.f,0.f);
            int gn = n0+n4;
            if (gn < NN) v = *(const float4*)&Bm[(size_t)(k0+kr)*NN + gn];
            *(float4*)&Bs[kr][n4] = v;
        }
        __syncthreads();
#pragma unroll
        for (int k=0;k<16;k++){
            float ra[8], rb[8];
#pragma unroll
            for (int i=0;i<8;i++) ra[i]=As[k][ty*8+i];
#pragma unroll
            for (int j=0;j<8;j++) rb[j]=Bs[k][tx*8+j];
#pragma unroll
            for (int i=0;i<8;i++)
#pragma unroll
                for (int j=0;j<8;j++) acc[i][j] += ra[i]*rb[j];
        }
        __syncthreads();
    }
#pragma unroll
    for (int i=0;i<8;i++){
        int gm = m0+ty*8+i;
        if (gm >= NN) continue;
#pragma unroll
        for (int j=0;j<8;j+=4){
            int gn = n0+tx*8+j;
            if (gn < NN)
                *(float4*)&Cm[(size_t)gm*NN+gn] =
                    make_float4(acc[i][j],acc[i][j+1],acc[i][j+2],acc[i][j+3]);
        }
    }
}

// ---------------- K5: row softmax of L -> E (in place) ------------------------
__global__ void k_softmax(float* __restrict__ L) {
    __shared__ float buf[NN];
    __shared__ float red[256];
    int r = blockIdx.x, tid = threadIdx.x;
    float* row = L + (size_t)r*NN;
    float mx = -1e30f;
    for (int j = tid; j < NN; j += 256) { float v = row[j]; buf[j] = v; mx = fmaxf(mx, v); }
    red[tid] = mx; __syncthreads();
    for (int s = 128; s > 0; s >>= 1) { if (tid < s) red[tid] = fmaxf(red[tid], red[tid+s]); __syncthreads(); }
    mx = red[0]; __syncthreads();
    float sum = 0.f;
    for (int j = tid; j < NN; j += 256) { float v = expf(buf[j]-mx); buf[j] = v; sum += v; }
    red[tid] = sum; __syncthreads();
    for (int s = 128; s > 0; s >>= 1) { if (tid < s) red[tid] += red[tid+s]; __syncthreads(); }
    float inv = 1.f/red[0];
    for (int j = tid; j < NN; j += 256) row[j] = buf[j]*inv;
}

// ---------------- K6a: Ah[b] = A @ h[b]   (2000x2000 @ 2000x64) ---------------
__global__ void k_Ah() {
    __shared__ float As[16][64];
    __shared__ float Bs[16][64];
    int b = blockIdx.z;
    int m0 = blockIdx.x*64;
    int tid = threadIdx.x;
    int ty = tid>>4, tx = tid&15;
    const float* hB = d_h + (size_t)b*NN*HH;
    float acc[4][4];
#pragma unroll
    for (int i=0;i<4;i++)
#pragma unroll
        for (int j=0;j<4;j++) acc[i][j]=0.f;
    for (int k0 = 0; k0 < NN; k0 += 16) {
        { int rowi = tid>>2, k4 = (tid&3)*4;
          float4 v = make_float4(0.f,0.f,0.f,0.f);
          if (m0+rowi < NN) v = *(const float4*)&d_A[(size_t)(m0+rowi)*NN + k0 + k4];
          As[k4][rowi]=v.x; As[k4+1][rowi]=v.y; As[k4+2][rowi]=v.z; As[k4+3][rowi]=v.w; }
        { int kr = tid>>4, c4 = (tid&15)*4;
          *(float4*)&Bs[kr][c4] = *(const float4*)&hB[(size_t)(k0+kr)*HH + c4]; }
        __syncthreads();
#pragma unroll
        for (int k=0;k<16;k++){
            float ra[4], rb[4];
#pragma unroll
            for (int i=0;i<4;i++) ra[i]=As[k][ty*4+i];
#pragma unroll
            for (int j=0;j<4;j++) rb[j]=Bs[k][tx*4+j];
#pragma unroll
            for (int i=0;i<4;i++)
#pragma unroll
                for (int j=0;j<4;j++) acc[i][j] += ra[i]*rb[j];
        }
        __syncthreads();
    }
#pragma unroll
    for (int i=0;i<4;i++){
        int m = m0+ty*4+i;
        if (m >= NN) continue;
#pragma unroll
        for (int j=0;j<4;j++)
            d_Ah[((size_t)b*NN + m)*HH + tx*4+j] = acc[i][j];
    }
}

// ---------------- K6b: xg0[b]=E[b]@h[b], xg1[b]=E[b]@Ah[b] (fused) ------------
__global__ void k_xg() {
    __shared__ float Es[16][64];
    __shared__ float B0[16][64];
    __shared__ float B1[16][64];
    int b = blockIdx.z;
    int m0 = blockIdx.x*64;
    int tid = threadIdx.x;
    int ty = tid>>4, tx = tid&15;
    const float* Em = d_L + (size_t)b*NN*NN;
    const float* hB = d_h  + (size_t)b*NN*HH;
    const float* aB = d_Ah + (size_t)b*NN*HH;
    float a0[4][4], a1[4][4];
#pragma unroll
    for (int i=0;i<4;i++)
#pragma unroll
        for (int j=0;j<4;j++){ a0[i][j]=0.f; a1[i][j]=0.f; }
    for (int k0 = 0; k0 < NN; k0 += 16) {
        { int rowi = tid>>2, k4 = (tid&3)*4;
          float4 v = make_float4(0.f,0.f,0.f,0.f);
          if (m0+rowi < NN) v = *(const float4*)&Em[(size_t)(m0+rowi)*NN + k0 + k4];
          Es[k4][rowi]=v.x; Es[k4+1][rowi]=v.y; Es[k4+2][rowi]=v.z; Es[k4+3][rowi]=v.w; }
        { int kr = tid>>4, c4 = (tid&15)*4;
          *(float4*)&B0[kr][c4] = *(const float4*)&hB[(size_t)(k0+kr)*HH + c4];
          *(float4*)&B1[kr][c4] = *(const float4*)&aB[(size_t)(k0+kr)*HH + c4]; }
        __syncthreads();
#pragma unroll
        for (int k=0;k<16;k++){
            float ra[4], rb0[4], rb1[4];
#pragma unroll
            for (int i=0;i<4;i++) ra[i]=Es[k][ty*4+i];
#pragma unroll
            for (int j=0;j<4;j++){ rb0[j]=B0[k][tx*4+j]; rb1[j]=B1[k][tx*4+j]; }
#pragma unroll
            for (int i=0;i<4;i++)
#pragma unroll
                for (int j=0;j<4;j++){ a0[i][j] += ra[i]*rb0[j]; a1[i][j] += ra[i]*rb1[j]; }
        }
        __syncthreads();
    }
#pragma unroll
    for (int i=0;i<4;i++){
        int m = m0+ty*4+i;
        if (m >= NN) continue;
#pragma unroll
        for (int j=0;j<4;j++){
            d_xg0[((size_t)b*NN + m)*HH + tx*4+j] = a0[i][j];
            d_xg1[((size_t)b*NN + m)*HH + tx*4+j] = a1[i][j];
        }
    }
}

// ---------------- K7: weights = emb @ wp_flat   (2000x16 @ 16x8192) -----------
__global__ void k_wn(const float* __restrict__ emb, const float* __restrict__ wp) {
    __shared__ float Es[64][16];
    __shared__ float Ws[16][128];
    int n0 = blockIdx.y*64, c0 = blockIdx.x*128;
    int tid = threadIdx.x;
    for (int i=tid;i<1024;i+=256){ int r=i>>4, d=i&15; int n=n0+r; Es[r][d] = (n<NN)? emb[(size_t)n*16+d] : 0.f; }
    for (int i=tid;i<2048;i+=256){ int kr=i>>7, c=i&127; Ws[kr][c] = wp[(size_t)kr*8192 + c0 + c]; }
    __syncthreads();
    int ty=tid>>4, tx=tid&15;
    float acc[4][8];
#pragma unroll
    for (int i=0;i<4;i++)
#pragma unroll
        for (int j=0;j<8;j++) acc[i][j]=0.f;
#pragma unroll
    for (int d=0; d<16; d++){
        float ev[4], wv[8];
#pragma unroll
        for (int i=0;i<4;i++) ev[i]=Es[ty*4+i][d];
#pragma unroll
        for (int j=0;j<8;j++) wv[j]=Ws[d][tx*8+j];
#pragma unroll
        for (int i=0;i<4;i++)
#pragma unroll
            for (int j=0;j<8;j++) acc[i][j] += ev[i]*wv[j];
    }
#pragma unroll
    for (int i=0;i<4;i++){
        int n = n0+ty*4+i;
        if (n >= NN) continue;
#pragma unroll
        for (int j=0;j<8;j++)
            d_wn[(size_t)n*8192 + c0 + tx*8 + j] = acc[i][j];
    }
}

// ---------------- K8: g[b,n,:] = xg_cat[b,n,:] @ W_n + bias_n -----------------
__global__ void k_g(const float* __restrict__ emb, const float* __restrict__ bp) {
    __shared__ float Wns[8192];
    __shared__ float xgs[8][128];
    __shared__ float bias_s[64];
    __shared__ float es[16];
    int n = blockIdx.x, tid = threadIdx.x;
    if (tid < 16) es[tid] = emb[(size_t)n*16+tid];
    for (int i=tid;i<8192;i+=256) Wns[i] = d_wn[(size_t)n*8192 + i];
    for (int i=tid;i<1024;i+=256){
        int b=i>>7, ki=i&127;
        xgs[b][ki] = (ki<64) ? d_xg0[((size_t)b*NN+n)*HH+ki]
                             : d_xg1[((size_t)b*NN+n)*HH+ki-64];
    }
    __syncthreads();
    if (tid < 64) {
        float bv = 0.f;
#pragma unroll
        for (int d=0; d<16; d++) bv += es[d]*bp[d*64+tid];
        bias_s[tid] = bv;
    }
    __syncthreads();
    int o = tid & 63;
#pragma unroll
    for (int rep=0; rep<2; rep++){
        int b = (tid>>6) + rep*4;
        float acc = bias_s[o];
#pragma unroll 8
        for (int ki=0; ki<128; ki++) acc += xgs[b][ki]*Wns[ki*64+o];
        d_g[((size_t)b*NN+n)*HH+o] = acc;
    }
}

// ---------------- K9: out = 0.1*tanh(g @ W_out^T + b_out) ---------------------
__global__ void k_out(const float* __restrict__ Wout, const float* __restrict__ bout,
                      float* __restrict__ out) {
    __shared__ float Wth[64*132];   // h-major, padded
    __shared__ float Gsh[64*36];    // h-major, padded
    __shared__ float bo[128];
    int r0 = blockIdx.x*32, o0 = blockIdx.y*128;
    int tid = threadIdx.x;
    for (int i=tid;i<8192;i+=256){ int ol=i>>6, h=i&63; Wth[h*132+ol] = Wout[(size_t)(o0+ol)*64 + h]; }
    for (int i=tid;i<2048;i+=256){ int rr=i>>6, h=i&63; Gsh[h*36+rr]  = d_g[(size_t)(r0+rr)*64 + h]; }
    if (tid<128) bo[tid] = bout[o0+tid];
    __syncthreads();
    int cg = tid & 31, rg = tid >> 5;
    float acc[4][4];
#pragma unroll
    for (int i=0;i<4;i++)
#pragma unroll
        for (int j=0;j<4;j++) acc[i][j]=0.f;
#pragma unroll
    for (int h=0; h<64; h++){
        float4 wv = *(const float4*)&Wth[h*132 + cg*4];
        float4 gv = *(const float4*)&Gsh[h*36 + rg*4];
        float gw[4]={gv.x,gv.y,gv.z,gv.w};
        float ww[4]={wv.x,wv.y,wv.z,wv.w};
#pragma unroll
        for (int i=0;i<4;i++)
#pragma unroll
            for (int j=0;j<4;j++) acc[i][j] += gw[i]*ww[j];
    }
#pragma unroll
    for (int i=0;i<4;i++){
        size_t rowoff = (size_t)(r0 + rg*4 + i)*OUTC + o0 + cg*4;
        float4 v;
        v.x = 0.1f * tanhf(acc[i][0] + bo[cg*4+0]);
        v.y = 0.1f * tanhf(acc[i][1] + bo[cg*4+1]);
        v.z = 0.1f * tanhf(acc[i][2] + bo[cg*4+2]);
        v.w = 0.1f * tanhf(acc[i][3] + bo[cg*4+3]);
        *(float4*)&out[rowoff] = v;
    }
}

// ---------------- launch ------------------------------------------------------
extern "C" void kernel_launch(void* const* d_in, const int* in_sizes, int n_in,
                              void* d_out, int out_size) {
    const float* z    = (const float*)d_in[0];
    const float* Win  = (const float*)d_in[1];
    const float* bin  = (const float*)d_in[2];
    const float* Wout = (const float*)d_in[3];
    const float* bout = (const float*)d_in[4];
    const float* emb  = (const float*)d_in[5];
    const float* wp   = (const float*)d_in[6];
    const float* bp   = (const float*)d_in[7];
    const float* w1   = (const float*)d_in[8];
    const float* w2   = (const float*)d_in[9];
    const float* vsM  = (const float*)d_in[10];
    const float* bs   = (const float*)d_in[11];
    float* out = (float*)d_out;
    (void)in_sizes; (void)n_in; (void)out_size;

    k_hidden<<<NB*NN, 64>>>(z, Win, bin, w1, w2);
    k_adj<<<NN, 256>>>(emb);
    k_T<<<dim3((NN+255)/256, NN), 256>>>(bs);
    k_biggemm<<<dim3((NN+127)/128, (NN+127)/128, NB), 256>>>(vsM);

    float* dLptr = nullptr;
    cudaGetSymbolAddress((void**)&dLptr, d_L);
    k_softmax<<<NB*NN, 256>>>(dLptr);

    k_Ah<<<dim3((NN+63)/64, 1, NB), 256>>>();
    k_xg<<<dim3((NN+63)/64, 1, NB), 256>>>();
    k_wn<<<dim3(8192/128, (NN+63)/64), 256>>>(emb, wp);
    k_g<<<NN, 256>>>(emb, bp);
    k_out<<<dim3((NB*NN)/32, OUTC/128), 256>>>(Wout, bout, out);
}

// round 3
// speedup vs baseline: 1.6753x; 1.6753x over previous
#include <cuda_runtime.h>
#include <cuda_bf16.h>
#include <math.h>
#include <stdint.h>

#define NB 8
#define NN 2000
#define HH 64
#define DD 16
#define OUTC 4096

// padded GEMM dims
#define MP 2048
#define NP 2048
#define KP 6144          // 3 segments of 2048: [hi | lo | hi] x [Thi ; Thi ; Tlo]
#define KCHUNK 64
#define NCHUNK (KP/KCHUNK)   // 96

// ---------------- scratch (static __device__ — no allocations) ----------------
__device__ float d_h  [NB*NN*HH];
__device__ float d_e1 [NB*NN];
__device__ float d_e2 [NB*NN];
__device__ float d_A  [(size_t)NN*NN];
__device__ __align__(16) float d_L  [(size_t)NB*NN*NN];  // logits -> E in place
__device__ float d_Ah [NB*NN*HH];
__device__ float d_xg0[NB*NN*HH];
__device__ float d_xg1[NB*NN*HH];
__device__ float d_wn [(size_t)NN*128*HH];
__device__ float d_g  [NB*NN*HH];
// bf16 GEMM operands (zero-padded)
__device__ __align__(16) __nv_bfloat16 d_Abf[(size_t)MP*KP];
__device__ __align__(16) __nv_bfloat16 d_Bbf[(size_t)NB*NP*KP];

// ======================= portable PTX helpers (base sm_103 OK) ================
__device__ __forceinline__ uint32_t smem_u32(const void* p) {
    uint32_t a;
    asm("{ .reg .u64 t; cvta.to.shared.u64 t, %1; cvt.u32.u64 %0, t; }" : "=r"(a) : "l"(p));
    return a;
}
__device__ __forceinline__ void cp16(uint32_t s, const void* g) {
    asm volatile("cp.async.cg.shared.global [%0], [%1], 16;" :: "r"(s), "l"(g));
}
#define CP_COMMIT() asm volatile("cp.async.commit_group;" ::: "memory")
#define CP_WAIT1()  asm volatile("cp.async.wait_group 1;" ::: "memory")
__device__ __forceinline__ void ldm_x4(uint32_t* r, uint32_t addr) {
    asm volatile("ldmatrix.sync.aligned.m8n8.x4.shared.b16 {%0,%1,%2,%3}, [%4];"
        : "=r"(r[0]), "=r"(r[1]), "=r"(r[2]), "=r"(r[3]) : "r"(addr));
}
__device__ __forceinline__ void ldm_x2(uint32_t* r, uint32_t addr) {
    asm volatile("ldmatrix.sync.aligned.m8n8.x2.shared.b16 {%0,%1}, [%2];"
        : "=r"(r[0]), "=r"(r[1]) : "r"(addr));
}
__device__ __forceinline__ void mma_bf16(float* c, const uint32_t* a, const uint32_t* b) {
    asm volatile(
        "mma.sync.aligned.m16n8k16.row.col.f32.bf16.bf16.f32 "
        "{%0,%1,%2,%3}, {%4,%5,%6,%7}, {%8,%9}, {%0,%1,%2,%3};"
        : "+f"(c[0]), "+f"(c[1]), "+f"(c[2]), "+f"(c[3])
        : "r"(a[0]), "r"(a[1]), "r"(a[2]), "r"(a[3]), "r"(b[0]), "r"(b[1]));
}

// ---------------- K1: h = relu(z @ W_in^T + b_in), e1 = h.w1, e2 = h.w2 -------
__global__ void k_hidden(const float* __restrict__ z, const float* __restrict__ Win,
                         const float* __restrict__ bin, const float* __restrict__ w1,
                         const float* __restrict__ w2) {
    __shared__ float zs[64];
    __shared__ float Ws[64*64];
    __shared__ float r1s[2], r2s[2];
    int row = blockIdx.x;
    int tid = threadIdx.x;
    zs[tid] = z[(size_t)row*64 + tid];
    for (int i = tid; i < 4096; i += 64) {
        int h = i >> 6, c = i & 63;
        Ws[c*64 + h] = Win[i];
    }
    __syncthreads();
    float acc = bin[tid];
#pragma unroll 16
    for (int c = 0; c < 64; c++) acc += zs[c] * Ws[c*64 + tid];
    float hv = fmaxf(acc, 0.f);
    d_h[(size_t)row*64 + tid] = hv;
    float p1 = hv * w1[tid], p2 = hv * w2[tid];
#pragma unroll
    for (int o = 16; o > 0; o >>= 1) {
        p1 += __shfl_down_sync(0xffffffffu, p1, o);
        p2 += __shfl_down_sync(0xffffffffu, p2, o);
    }
    int warp = tid >> 5;
    if ((tid & 31) == 0) { r1s[warp] = p1; r2s[warp] = p2; }
    __syncthreads();
    if (tid == 0) { d_e1[row] = r1s[0] + r1s[1]; d_e2[row] = r2s[0] + r2s[1]; }
}

// ---------------- K2: A = softmax(relu(emb @ emb^T), axis=1) ------------------
__global__ void k_adj(const float* __restrict__ emb) {
    __shared__ float buf[NN];
    __shared__ float red[256];
    __shared__ float ei[16];
    int i = blockIdx.x, tid = threadIdx.x;
    if (tid < 16) ei[tid] = emb[i*16 + tid];
    __syncthreads();
    float mx = -1e30f;
    for (int j = tid; j < NN; j += 256) {
        const float* er = emb + (size_t)j*16;
        float dsum = 0.f;
#pragma unroll
        for (int d = 0; d < 16; d++) dsum += ei[d]*er[d];
        dsum = fmaxf(dsum, 0.f);
        buf[j] = dsum;
        mx = fmaxf(mx, dsum);
    }
    red[tid] = mx; __syncthreads();
    for (int s = 128; s > 0; s >>= 1) { if (tid < s) red[tid] = fmaxf(red[tid], red[tid+s]); __syncthreads(); }
    mx = red[0]; __syncthreads();
    float sum = 0.f;
    for (int j = tid; j < NN; j += 256) { float v = expf(buf[j]-mx); buf[j] = v; sum += v; }
    red[tid] = sum; __syncthreads();
    for (int s = 128; s > 0; s >>= 1) { if (tid < s) red[tid] += red[tid+s]; __syncthreads(); }
    float inv = 1.f/red[0];
    for (int j = tid; j < NN; j += 256) d_A[(size_t)i*NN + j] = buf[j]*inv;
}

// ---- K3a: vs -> bf16 split, padded, K-layout [hi | lo | hi] ------------------
__global__ void k_Avs(const float* __restrict__ vsM) {
    int k = blockIdx.x*256 + threadIdx.x;
    int m = blockIdx.y;
    float t = (m < NN && k < NN) ? vsM[(size_t)m*NN + k] : 0.f;
    __nv_bfloat16 hi = __float2bfloat16(t);
    __nv_bfloat16 lo = __float2bfloat16(t - __bfloat162float(hi));
    size_t base = (size_t)m*KP;
    d_Abf[base + k]        = hi;
    d_Abf[base + 2048 + k] = lo;
    d_Abf[base + 4096 + k] = hi;
}

// ---- K3b: B'[b][n][k] = split(sigmoid(e1[b,k]*e2[b,n] + bs[k,n])) ------------
__global__ void k_T2(const float* __restrict__ bs) {
    __shared__ float sbs[32][33];
    int k0 = blockIdx.x*32, n0 = blockIdx.y*32;
    int tid = threadIdx.x;
#pragma unroll
    for (int l = 0; l < 4; l++) {
        int kk = (tid >> 5) + l*8, nn = tid & 31;
        int gk = k0 + kk, gn = n0 + nn;
        sbs[kk][nn] = (gk < NN && gn < NN) ? bs[(size_t)gk*NN + gn] : 0.f;
    }
    __syncthreads();
    int nnl = tid >> 4;
    int kl  = (tid & 15) * 2;
#pragma unroll
    for (int half = 0; half < 2; half++) {
        int nn = nnl + half*16;
        int gn = n0 + nn;
        bool nok = gn < NN;
        int gk0 = k0 + kl, gk1 = gk0 + 1;
        float b0 = sbs[kl][nn], b1 = sbs[kl+1][nn];
#pragma unroll
        for (int b = 0; b < NB; b++) {
            float v0 = 0.f, v1 = 0.f;
            if (nok) {
                float e2v = d_e2[b*NN + gn];
                if (gk0 < NN) { float x = d_e1[b*NN + gk0]*e2v + b0; v0 = 1.f/(1.f + expf(-x)); }
                if (gk1 < NN) { float x = d_e1[b*NN + gk1]*e2v + b1; v1 = 1.f/(1.f + expf(-x)); }
            }
            __nv_bfloat16 h0 = __float2bfloat16(v0), h1 = __float2bfloat16(v1);
            __nv_bfloat16 l0 = __float2bfloat16(v0 - __bfloat162float(h0));
            __nv_bfloat16 l1 = __float2bfloat16(v1 - __bfloat162float(h1));
            __nv_bfloat162 hv = __halves2bfloat162(h0, h1);
            __nv_bfloat162 lv = __halves2bfloat162(l0, l1);
            size_t base = ((size_t)b*NP + gn)*KP + gk0;
            *(__nv_bfloat162*)&d_Bbf[base]        = hv;
            *(__nv_bfloat162*)&d_Bbf[base + 2048] = hv;
            *(__nv_bfloat162*)&d_Bbf[base + 4096] = lv;
        }
    }
}

// ---- K4: L[b] = A' @ B'^T via mma.sync bf16, CTA tile 128x256 ----------------
// smem: A bufs 2 x 128x72 bf16 (18432B each), B bufs 2 x 256x72 bf16 (36864B each)
#define AROW 144                       // bytes per padded A/B smem row (72 bf16)
#define ABUF 18432
#define BBUF 36864
#define SMEM_MMA (2*ABUF + 2*BBUF)     // 110592

__global__ void __launch_bounds__(256, 1) k_mma() {
    extern __shared__ __align__(16) char smem[];
    uint32_t sb = smem_u32(smem);
    int tid = threadIdx.x, lane = tid & 31, w = tid >> 5;
    int b  = blockIdx.z;
    int m0 = blockIdx.y * 128;
    int n0 = blockIdx.x * 256;
    const __nv_bfloat16* Ag = d_Abf + (size_t)m0*KP;
    const __nv_bfloat16* Bg = d_Bbf + ((size_t)b*NP + n0)*KP;

    // chunk loader: A 128x64, B 256x64 into buf
    auto issue = [&](int kc, int buf) {
        uint32_t sA = sb + buf*ABUF;
        uint32_t sB = sb + 2*ABUF + buf*BBUF;
#pragma unroll
        for (int l = 0; l < 4; l++) {
            int seg = tid + l*256;
            int row = seg >> 3, c = seg & 7;
            cp16(sA + row*AROW + c*16, Ag + (size_t)row*KP + kc*KCHUNK + c*8);
        }
#pragma unroll
        for (int l = 0; l < 8; l++) {
            int seg = tid + l*256;
            int row = seg >> 3, c = seg & 7;
            cp16(sB + row*AROW + c*16, Bg + (size_t)row*KP + kc*KCHUNK + c*8);
        }
        CP_COMMIT();
    };

    issue(0, 0);
    issue(1, 1);

    float c[4][8][4];
#pragma unroll
    for (int mi = 0; mi < 4; mi++)
#pragma unroll
        for (int nj = 0; nj < 8; nj++)
#pragma unroll
            for (int q = 0; q < 4; q++) c[mi][nj][q] = 0.f;

    int wm = w & 1, wn = w >> 1;          // warp -> 64x64 subtile of 128x256
    // ldmatrix lane addressing components
    int a_row = (lane & 15), a_kh = (lane >> 4) * 16;           // bytes
    int b_row = (lane & 7),  b_kh = ((lane >> 3) & 1) * 16;     // bytes

    for (int kc = 0; kc < NCHUNK; kc++) {
        CP_WAIT1();
        __syncthreads();
        int buf = kc & 1;
        uint32_t sA = sb + buf*ABUF      + (wm*64 + a_row)*AROW + a_kh;
        uint32_t sB = sb + 2*ABUF + buf*BBUF + (wn*64 + b_row)*AROW + b_kh;
#pragma unroll
        for (int ks = 0; ks < 4; ks++) {
            uint32_t af[4][4], bf[8][2];
#pragma unroll
            for (int mi = 0; mi < 4; mi++)
                ldm_x4(af[mi], sA + mi*16*AROW + ks*32);
#pragma unroll
            for (int nj = 0; nj < 8; nj++)
                ldm_x2(bf[nj], sB + nj*8*AROW + ks*32);
#pragma unroll
            for (int mi = 0; mi < 4; mi++)
#pragma unroll
                for (int nj = 0; nj < 8; nj++)
                    mma_bf16(c[mi][nj], af[mi], bf[nj]);
        }
        __syncthreads();
        if (kc + 2 < NCHUNK) issue(kc + 2, buf);
        else CP_COMMIT();                 // keep group accounting uniform
    }

    // epilogue: direct fp32 stores
    float* Cb = d_L + (size_t)b*NN*NN;
    int gid = lane >> 2, tig = lane & 3;
#pragma unroll
    for (int mi = 0; mi < 4; mi++) {
        int gm = m0 + wm*64 + mi*16 + gid;
#pragma unroll
        for (int nj = 0; nj < 8; nj++) {
            int gn = n0 + wn*64 + nj*8 + tig*2;
            if (gn < NN) {
                if (gm < NN)
                    *(float2*)&Cb[(size_t)gm*NN + gn]     = make_float2(c[mi][nj][0], c[mi][nj][1]);
                if (gm + 8 < NN)
                    *(float2*)&Cb[(size_t)(gm+8)*NN + gn] = make_float2(c[mi][nj][2], c[mi][nj][3]);
            }
        }
    }
}

// ---------------- K5: row softmax of L -> E (in place) ------------------------
__global__ void k_softmax(float* __restrict__ L) {
    __shared__ float buf[NN];
    __shared__ float red[256];
    int r = blockIdx.x, tid = threadIdx.x;
    float* row = L + (size_t)r*NN;
    float mx = -1e30f;
    for (int j = tid; j < NN; j += 256) { float v = row[j]; buf[j] = v; mx = fmaxf(mx, v); }
    red[tid] = mx; __syncthreads();
    for (int s = 128; s > 0; s >>= 1) { if (tid < s) red[tid] = fmaxf(red[tid], red[tid+s]); __syncthreads(); }
    mx = red[0]; __syncthreads();
    float sum = 0.f;
    for (int j = tid; j < NN; j += 256) { float v = expf(buf[j]-mx); buf[j] = v; sum += v; }
    red[tid] = sum; __syncthreads();
    for (int s = 128; s > 0; s >>= 1) { if (tid < s) red[tid] += red[tid+s]; __syncthreads(); }
    float inv = 1.f/red[0];
    for (int j = tid; j < NN; j += 256) row[j] = buf[j]*inv;
}

// ---------------- K6a: Ah[b] = A @ h[b] ---------------------------------------
__global__ void k_Ah() {
    __shared__ float As[16][64];
    __shared__ float Bs[16][64];
    int b = blockIdx.z;
    int m0 = blockIdx.x*64;
    int tid = threadIdx.x;
    int ty = tid>>4, tx = tid&15;
    const float* hB = d_h + (size_t)b*NN*HH;
    float acc[4][4];
#pragma unroll
    for (int i=0;i<4;i++)
#pragma unroll
        for (int j=0;j<4;j++) acc[i][j]=0.f;
    for (int k0 = 0; k0 < NN; k0 += 16) {
        { int rowi = tid>>2, k4 = (tid&3)*4;
          float4 v = make_float4(0.f,0.f,0.f,0.f);
          if (m0+rowi < NN) v = *(const float4*)&d_A[(size_t)(m0+rowi)*NN + k0 + k4];
          As[k4][rowi]=v.x; As[k4+1][rowi]=v.y; As[k4+2][rowi]=v.z; As[k4+3][rowi]=v.w; }
        { int kr = tid>>4, c4 = (tid&15)*4;
          *(float4*)&Bs[kr][c4] = *(const float4*)&hB[(size_t)(k0+kr)*HH + c4]; }
        __syncthreads();
#pragma unroll
        for (int k=0;k<16;k++){
            float ra[4], rb[4];
#pragma unroll
            for (int i=0;i<4;i++) ra[i]=As[k][ty*4+i];
#pragma unroll
            for (int j=0;j<4;j++) rb[j]=Bs[k][tx*4+j];
#pragma unroll
            for (int i=0;i<4;i++)
#pragma unroll
                for (int j=0;j<4;j++) acc[i][j] += ra[i]*rb[j];
        }
        __syncthreads();
    }
#pragma unroll
    for (int i=0;i<4;i++){
        int m = m0+ty*4+i;
        if (m >= NN) continue;
#pragma unroll
        for (int j=0;j<4;j++)
            d_Ah[((size_t)b*NN + m)*HH + tx*4+j] = acc[i][j];
    }
}

// ---------------- K6b: xg0[b]=E[b]@h[b], xg1[b]=E[b]@Ah[b] --------------------
__global__ void k_xg() {
    __shared__ float Es[16][64];
    __shared__ float B0[16][64];
    __shared__ float B1[16][64];
    int b = blockIdx.z;
    int m0 = blockIdx.x*64;
    int tid = threadIdx.x;
    int ty = tid>>4, tx = tid&15;
    const float* Em = d_L + (size_t)b*NN*NN;
    const float* hB = d_h  + (size_t)b*NN*HH;
    const float* aB = d_Ah + (size_t)b*NN*HH;
    float a0[4][4], a1[4][4];
#pragma unroll
    for (int i=0;i<4;i++)
#pragma unroll
        for (int j=0;j<4;j++){ a0[i][j]=0.f; a1[i][j]=0.f; }
    for (int k0 = 0; k0 < NN; k0 += 16) {
        { int rowi = tid>>2, k4 = (tid&3)*4;
          float4 v = make_float4(0.f,0.f,0.f,0.f);
          if (m0+rowi < NN) v = *(const float4*)&Em[(size_t)(m0+rowi)*NN + k0 + k4];
          Es[k4][rowi]=v.x; Es[k4+1][rowi]=v.y; Es[k4+2][rowi]=v.z; Es[k4+3][rowi]=v.w; }
        { int kr = tid>>4, c4 = (tid&15)*4;
          *(float4*)&B0[kr][c4] = *(const float4*)&hB[(size_t)(k0+kr)*HH + c4];
          *(float4*)&B1[kr][c4] = *(const float4*)&aB[(size_t)(k0+kr)*HH + c4]; }
        __syncthreads();
#pragma unroll
        for (int k=0;k<16;k++){
            float ra[4], rb0[4], rb1[4];
#pragma unroll
            for (int i=0;i<4;i++) ra[i]=Es[k][ty*4+i];
#pragma unroll
            for (int j=0;j<4;j++){ rb0[j]=B0[k][tx*4+j]; rb1[j]=B1[k][tx*4+j]; }
#pragma unroll
            for (int i=0;i<4;i++)
#pragma unroll
                for (int j=0;j<4;j++){ a0[i][j] += ra[i]*rb0[j]; a1[i][j] += ra[i]*rb1[j]; }
        }
        __syncthreads();
    }
#pragma unroll
    for (int i=0;i<4;i++){
        int m = m0+ty*4+i;
        if (m >= NN) continue;
#pragma unroll
        for (int j=0;j<4;j++){
            d_xg0[((size_t)b*NN + m)*HH + tx*4+j] = a0[i][j];
            d_xg1[((size_t)b*NN + m)*HH + tx*4+j] = a1[i][j];
        }
    }
}

// ---------------- K7: weights = emb @ wp_flat ---------------------------------
__global__ void k_wn(const float* __restrict__ emb, const float* __restrict__ wp) {
    __shared__ float Es[64][16];
    __shared__ float Ws[16][128];
    int n0 = blockIdx.y*64, c0 = blockIdx.x*128;
    int tid = threadIdx.x;
    for (int i=tid;i<1024;i+=256){ int r=i>>4, d=i&15; int n=n0+r; Es[r][d] = (n<NN)? emb[(size_t)n*16+d] : 0.f; }
    for (int i=tid;i<2048;i+=256){ int kr=i>>7, c=i&127; Ws[kr][c] = wp[(size_t)kr*8192 + c0 + c]; }
    __syncthreads();
    int ty=tid>>4, tx=tid&15;
    float acc[4][8];
#pragma unroll
    for (int i=0;i<4;i++)
#pragma unroll
        for (int j=0;j<8;j++) acc[i][j]=0.f;
#pragma unroll
    for (int d=0; d<16; d++){
        float ev[4], wv[8];
#pragma unroll
        for (int i=0;i<4;i++) ev[i]=Es[ty*4+i][d];
#pragma unroll
        for (int j=0;j<8;j++) wv[j]=Ws[d][tx*8+j];
#pragma unroll
        for (int i=0;i<4;i++)
#pragma unroll
            for (int j=0;j<8;j++) acc[i][j] += ev[i]*wv[j];
    }
#pragma unroll
    for (int i=0;i<4;i++){
        int n = n0+ty*4+i;
        if (n >= NN) continue;
#pragma unroll
        for (int j=0;j<8;j++)
            d_wn[(size_t)n*8192 + c0 + tx*8 + j] = acc[i][j];
    }
}

// ---------------- K8: g[b,n,:] = xg_cat[b,n,:] @ W_n + bias_n -----------------
__global__ void k_g(const float* __restrict__ emb, const float* __restrict__ bp) {
    __shared__ float Wns[8192];
    __shared__ float xgs[8][128];
    __shared__ float bias_s[64];
    __shared__ float es[16];
    int n = blockIdx.x, tid = threadIdx.x;
    if (tid < 16) es[tid] = emb[(size_t)n*16+tid];
    for (int i=tid;i<8192;i+=256) Wns[i] = d_wn[(size_t)n*8192 + i];
    for (int i=tid;i<1024;i+=256){
        int b=i>>7, ki=i&127;
        xgs[b][ki] = (ki<64) ? d_xg0[((size_t)b*NN+n)*HH+ki]
                             : d_xg1[((size_t)b*NN+n)*HH+ki-64];
    }
    __syncthreads();
    if (tid < 64) {
        float bv = 0.f;
#pragma unroll
        for (int d=0; d<16; d++) bv += es[d]*bp[d*64+tid];
        bias_s[tid] = bv;
    }
    __syncthreads();
    int o = tid & 63;
#pragma unroll
    for (int rep=0; rep<2; rep++){
        int b = (tid>>6) + rep*4;
        float acc = bias_s[o];
#pragma unroll 8
        for (int ki=0; ki<128; ki++) acc += xgs[b][ki]*Wns[ki*64+o];
        d_g[((size_t)b*NN+n)*HH+o] = acc;
    }
}

// ---------------- K9: out = 0.1*tanh(g @ W_out^T + b_out) ---------------------
__global__ void k_out(const float* __restrict__ Wout, const float* __restrict__ bout,
                      float* __restrict__ out) {
    __shared__ float Wth[64*132];
    __shared__ float Gsh[64*36];
    __shared__ float bo[128];
    int r0 = blockIdx.x*32, o0 = blockIdx.y*128;
    int tid = threadIdx.x;
    for (int i=tid;i<8192;i+=256){ int ol=i>>6, h=i&63; Wth[h*132+ol] = Wout[(size_t)(o0+ol)*64 + h]; }
    for (int i=tid;i<2048;i+=256){ int rr=i>>6, h=i&63; Gsh[h*36+rr]  = d_g[(size_t)(r0+rr)*64 + h]; }
    if (tid<128) bo[tid] = bout[o0+tid];
    __syncthreads();
    int cg = tid & 31, rg = tid >> 5;
    float acc[4][4];
#pragma unroll
    for (int i=0;i<4;i++)
#pragma unroll
        for (int j=0;j<4;j++) acc[i][j]=0.f;
#pragma unroll
    for (int h=0; h<64; h++){
        float4 wv = *(const float4*)&Wth[h*132 + cg*4];
        float4 gv = *(const float4*)&Gsh[h*36 + rg*4];
        float gw[4]={gv.x,gv.y,gv.z,gv.w};
        float ww[4]={wv.x,wv.y,wv.z,wv.w};
#pragma unroll
        for (int i=0;i<4;i++)
#pragma unroll
            for (int j=0;j<4;j++) acc[i][j] += gw[i]*ww[j];
    }
#pragma unroll
    for (int i=0;i<4;i++){
        size_t rowoff = (size_t)(r0 + rg*4 + i)*OUTC + o0 + cg*4;
        float4 v;
        v.x = 0.1f * tanhf(acc[i][0] + bo[cg*4+0]);
        v.y = 0.1f * tanhf(acc[i][1] + bo[cg*4+1]);
        v.z = 0.1f * tanhf(acc[i][2] + bo[cg*4+2]);
        v.w = 0.1f * tanhf(acc[i][3] + bo[cg*4+3]);
        *(float4*)&out[rowoff] = v;
    }
}

// ---------------- launch ------------------------------------------------------
extern "C" void kernel_launch(void* const* d_in, const int* in_sizes, int n_in,
                              void* d_out, int out_size) {
    const float* z    = (const float*)d_in[0];
    const float* Win  = (const float*)d_in[1];
    const float* bin  = (const float*)d_in[2];
    const float* Wout = (const float*)d_in[3];
    const float* bout = (const float*)d_in[4];
    const float* emb  = (const float*)d_in[5];
    const float* wp   = (const float*)d_in[6];
    const float* bp   = (const float*)d_in[7];
    const float* w1   = (const float*)d_in[8];
    const float* w2   = (const float*)d_in[9];
    const float* vsM  = (const float*)d_in[10];
    const float* bs   = (const float*)d_in[11];
    float* out = (float*)d_out;
    (void)in_sizes; (void)n_in; (void)out_size;

    cudaFuncSetAttribute(k_mma, cudaFuncAttributeMaxDynamicSharedMemorySize, SMEM_MMA);

    k_hidden<<<NB*NN, 64>>>(z, Win, bin, w1, w2);
    k_adj<<<NN, 256>>>(emb);
    k_Avs<<<dim3(MP/256, MP), 256>>>(vsM);
    k_T2<<<dim3(NP/32, NP/32), 256>>>(bs);
    k_mma<<<dim3(NP/256, MP/128, NB), 256, SMEM_MMA>>>();

    float* dLptr = nullptr;
    cudaGetSymbolAddress((void**)&dLptr, d_L);
    k_softmax<<<NB*NN, 256>>>(dLptr);

    k_Ah<<<dim3((NN+63)/64, 1, NB), 256>>>();
    k_xg<<<dim3((NN+63)/64, 1, NB), 256>>>();
    k_wn<<<dim3(8192/128, (NN+63)/64), 256>>>(emb, wp);
    k_g<<<NN, 256>>>(emb, bp);
    k_out<<<dim3((NB*NN)/32, OUTC/128), 256>>>(Wout, bout, out);
}

// round 4
// speedup vs baseline: 1.9903x; 1.1880x over previous
#include <cuda_runtime.h>
#include <cuda_fp16.h>
#include <math.h>
#include <stdint.h>

#define NB 8
#define NN 2000
#define HH 64
#define DD 16
#define OUTC 4096

// padded GEMM dims
#define MP 2048
#define NP 2048
#define KSEG 2048            // one K segment
#define KPB  4096            // B has 2 segments: [Thi | Tlo]; A (fp16(vs)) wraps
#define KCHUNK 64
#define NCHUNK (KPB/KCHUNK)  // 64

// ---------------- scratch (static __device__ — no allocations) ----------------
__device__ float d_h  [NB*NN*HH];
__device__ float d_e1 [NB*NN];
__device__ float d_e2 [NB*NN];
__device__ float d_A  [(size_t)NN*NN];
__device__ __align__(16) float d_L  [(size_t)NB*NN*NN];  // logits -> E in place
__device__ float d_Ah [NB*NN*HH];
__device__ float d_xg0[NB*NN*HH];
__device__ float d_xg1[NB*NN*HH];
__device__ float d_wn [(size_t)NN*128*HH];
__device__ float d_g  [NB*NN*HH];
// fp16 GEMM operands (zero-padded)
__device__ __align__(16) __half d_Abf[(size_t)MP*KSEG];        // 8.4 MB
__device__ __align__(16) __half d_Bbf[(size_t)NB*NP*KPB];      // 134 MB

// ======================= portable PTX helpers (base sm_103 OK) ================
__device__ __forceinline__ uint32_t smem_u32(const void* p) {
    uint32_t a;
    asm("{ .reg .u64 t; cvta.to.shared.u64 t, %1; cvt.u32.u64 %0, t; }" : "=r"(a) : "l"(p));
    return a;
}
__device__ __forceinline__ void cp16(uint32_t s, const void* g) {
    asm volatile("cp.async.cg.shared.global [%0], [%1], 16;" :: "r"(s), "l"(g));
}
#define CP_COMMIT() asm volatile("cp.async.commit_group;" ::: "memory")
#define CP_WAIT1()  asm volatile("cp.async.wait_group 1;" ::: "memory")
__device__ __forceinline__ void ldm_x4(uint32_t* r, uint32_t addr) {
    asm volatile("ldmatrix.sync.aligned.m8n8.x4.shared.b16 {%0,%1,%2,%3}, [%4];"
        : "=r"(r[0]), "=r"(r[1]), "=r"(r[2]), "=r"(r[3]) : "r"(addr));
}
__device__ __forceinline__ void ldm_x2(uint32_t* r, uint32_t addr) {
    asm volatile("ldmatrix.sync.aligned.m8n8.x2.shared.b16 {%0,%1}, [%2];"
        : "=r"(r[0]), "=r"(r[1]) : "r"(addr));
}
__device__ __forceinline__ void mma_f16(float* c, const uint32_t* a, const uint32_t* b) {
    asm volatile(
        "mma.sync.aligned.m16n8k16.row.col.f32.f16.f16.f32 "
        "{%0,%1,%2,%3}, {%4,%5,%6,%7}, {%8,%9}, {%0,%1,%2,%3};"
        : "+f"(c[0]), "+f"(c[1]), "+f"(c[2]), "+f"(c[3])
        : "r"(a[0]), "r"(a[1]), "r"(a[2]), "r"(a[3]), "r"(b[0]), "r"(b[1]));
}

// ---------------- K1: h = relu(z @ W_in^T + b_in), e1 = h.w1, e2 = h.w2 -------
__global__ void k_hidden(const float* __restrict__ z, const float* __restrict__ Win,
                         const float* __restrict__ bin, const float* __restrict__ w1,
                         const float* __restrict__ w2) {
    __shared__ float zs[64];
    __shared__ float Ws[64*64];
    __shared__ float r1s[2], r2s[2];
    int row = blockIdx.x;
    int tid = threadIdx.x;
    zs[tid] = z[(size_t)row*64 + tid];
    for (int i = tid; i < 4096; i += 64) {
        int h = i >> 6, c = i & 63;
        Ws[c*64 + h] = Win[i];
    }
    __syncthreads();
    float acc = bin[tid];
#pragma unroll 16
    for (int c = 0; c < 64; c++) acc += zs[c] * Ws[c*64 + tid];
    float hv = fmaxf(acc, 0.f);
    d_h[(size_t)row*64 + tid] = hv;
    float p1 = hv * w1[tid], p2 = hv * w2[tid];
#pragma unroll
    for (int o = 16; o > 0; o >>= 1) {
        p1 += __shfl_down_sync(0xffffffffu, p1, o);
        p2 += __shfl_down_sync(0xffffffffu, p2, o);
    }
    int warp = tid >> 5;
    if ((tid & 31) == 0) { r1s[warp] = p1; r2s[warp] = p2; }
    __syncthreads();
    if (tid == 0) { d_e1[row] = r1s[0] + r1s[1]; d_e2[row] = r2s[0] + r2s[1]; }
}

// ---------------- K2: A = softmax(relu(emb @ emb^T), axis=1) ------------------
__global__ void k_adj(const float* __restrict__ emb) {
    __shared__ float buf[NN];
    __shared__ float red[256];
    __shared__ float ei[16];
    int i = blockIdx.x, tid = threadIdx.x;
    if (tid < 16) ei[tid] = emb[i*16 + tid];
    __syncthreads();
    float mx = -1e30f;
    for (int j = tid; j < NN; j += 256) {
        const float* er = emb + (size_t)j*16;
        float dsum = 0.f;
#pragma unroll
        for (int d = 0; d < 16; d++) dsum += ei[d]*er[d];
        dsum = fmaxf(dsum, 0.f);
        buf[j] = dsum;
        mx = fmaxf(mx, dsum);
    }
    red[tid] = mx; __syncthreads();
    for (int s = 128; s > 0; s >>= 1) { if (tid < s) red[tid] = fmaxf(red[tid], red[tid+s]); __syncthreads(); }
    mx = red[0]; __syncthreads();
    float sum = 0.f;
    for (int j = tid; j < NN; j += 256) { float v = expf(buf[j]-mx); buf[j] = v; sum += v; }
    red[tid] = sum; __syncthreads();
    for (int s = 128; s > 0; s >>= 1) { if (tid < s) red[tid] += red[tid+s]; __syncthreads(); }
    float inv = 1.f/red[0];
    for (int j = tid; j < NN; j += 256) d_A[(size_t)i*NN + j] = buf[j]*inv;
}

// ---- K3a: A = fp16(vs), zero-padded ------------------------------------------
__global__ void k_Avs(const float* __restrict__ vsM) {
    int k = blockIdx.x*256 + threadIdx.x;
    int m = blockIdx.y;
    float t = (m < NN && k < NN) ? vsM[(size_t)m*NN + k] : 0.f;
    d_Abf[(size_t)m*KSEG + k] = __float2half_rn(t);
}

// ---- K3b: B'[b][n][k] = fp16 split of sigmoid(e1[b,k]*e2[b,n] + bs[k,n]) -----
// layout along k: [Thi(2048) | Tlo(2048)], transposed via smem tile
__global__ void k_T2(const float* __restrict__ bs) {
    __shared__ float sbs[32][33];
    int k0 = blockIdx.x*32, n0 = blockIdx.y*32;
    int tid = threadIdx.x;
#pragma unroll
    for (int l = 0; l < 4; l++) {
        int kk = (tid >> 5) + l*8, nn = tid & 31;
        int gk = k0 + kk, gn = n0 + nn;
        sbs[kk][nn] = (gk < NN && gn < NN) ? bs[(size_t)gk*NN + gn] : 0.f;
    }
    __syncthreads();
    int nnl = tid >> 4;
    int kl  = (tid & 15) * 2;
#pragma unroll
    for (int half = 0; half < 2; half++) {
        int nn = nnl + half*16;
        int gn = n0 + nn;
        bool nok = gn < NN;
        int gk0 = k0 + kl, gk1 = gk0 + 1;
        float b0 = sbs[kl][nn], b1 = sbs[kl+1][nn];
#pragma unroll
        for (int b = 0; b < NB; b++) {
            float v0 = 0.f, v1 = 0.f;
            if (nok) {
                float e2v = d_e2[b*NN + gn];
                if (gk0 < NN) { float x = d_e1[b*NN + gk0]*e2v + b0; v0 = 1.f/(1.f + expf(-x)); }
                if (gk1 < NN) { float x = d_e1[b*NN + gk1]*e2v + b1; v1 = 1.f/(1.f + expf(-x)); }
            }
            __half h0 = __float2half_rn(v0), h1 = __float2half_rn(v1);
            __half l0 = __float2half_rn(v0 - __half2float(h0));
            __half l1 = __float2half_rn(v1 - __half2float(h1));
            size_t base = ((size_t)b*NP + gn)*KPB + gk0;
            *(__half2*)&d_Bbf[base]        = __halves2half2(h0, h1);
            *(__half2*)&d_Bbf[base + KSEG] = __halves2half2(l0, l1);
        }
    }
}

// ---- K4: L[b] = A' @ B'^T via mma.sync fp16, CTA tile 128x256, K=4096 --------
#define AROW 144                       // bytes per padded A/B smem row (72 fp16)
#define ABUF 18432
#define BBUF 36864
#define SMEM_MMA (2*ABUF + 2*BBUF)     // 110592

__global__ void __launch_bounds__(256, 1) k_mma() {
    extern __shared__ __align__(16) char smem[];
    uint32_t sb = smem_u32(smem);
    int tid = threadIdx.x, lane = tid & 31, w = tid >> 5;
    int b  = blockIdx.z;
    int m0 = blockIdx.y * 128;
    int n0 = blockIdx.x * 256;
    const __half* Ag = d_Abf + (size_t)m0*KSEG;
    const __half* Bg = d_Bbf + ((size_t)b*NP + n0)*KPB;

    // chunk loader: A 128x64 (K wraps mod KSEG), B 256x64
    auto issue = [&](int kc, int buf) {
        uint32_t sA = sb + buf*ABUF;
        uint32_t sB = sb + 2*ABUF + buf*BBUF;
        int ka = (kc & 31) * KCHUNK;      // A wraps: 32 chunks per segment
#pragma unroll
        for (int l = 0; l < 4; l++) {
            int seg = tid + l*256;
            int row = seg >> 3, c = seg & 7;
            cp16(sA + row*AROW + c*16, Ag + (size_t)row*KSEG + ka + c*8);
        }
#pragma unroll
        for (int l = 0; l < 8; l++) {
            int seg = tid + l*256;
            int row = seg >> 3, c = seg & 7;
            cp16(sB + row*AROW + c*16, Bg + (size_t)row*KPB + kc*KCHUNK + c*8);
        }
        CP_COMMIT();
    };

    issue(0, 0);
    issue(1, 1);

    float c[4][8][4];
#pragma unroll
    for (int mi = 0; mi < 4; mi++)
#pragma unroll
        for (int nj = 0; nj < 8; nj++)
#pragma unroll
            for (int q = 0; q < 4; q++) c[mi][nj][q] = 0.f;

    int wm = w & 1, wn = w >> 1;          // warp -> 64x64 subtile of 128x256
    int a_row = (lane & 15), a_kh = (lane >> 4) * 16;
    int b_row = (lane & 7),  b_kh = ((lane >> 3) & 1) * 16;

    for (int kc = 0; kc < NCHUNK; kc++) {
        CP_WAIT1();
        __syncthreads();
        int buf = kc & 1;
        uint32_t sA = sb + buf*ABUF           + (wm*64 + a_row)*AROW + a_kh;
        uint32_t sB = sb + 2*ABUF + buf*BBUF  + (wn*64 + b_row)*AROW + b_kh;
#pragma unroll
        for (int ks = 0; ks < 4; ks++) {
            uint32_t af[4][4], bf[8][2];
#pragma unroll
            for (int mi = 0; mi < 4; mi++)
                ldm_x4(af[mi], sA + mi*16*AROW + ks*32);
#pragma unroll
            for (int nj = 0; nj < 8; nj++)
                ldm_x2(bf[nj], sB + nj*8*AROW + ks*32);
#pragma unroll
            for (int mi = 0; mi < 4; mi++)
#pragma unroll
                for (int nj = 0; nj < 8; nj++)
                    mma_f16(c[mi][nj], af[mi], bf[nj]);
        }
        __syncthreads();
        if (kc + 2 < NCHUNK) issue(kc + 2, buf);
        else CP_COMMIT();
    }

    // epilogue: direct fp32 stores
    float* Cb = d_L + (size_t)b*NN*NN;
    int gid = lane >> 2, tig = lane & 3;
#pragma unroll
    for (int mi = 0; mi < 4; mi++) {
        int gm = m0 + wm*64 + mi*16 + gid;
#pragma unroll
        for (int nj = 0; nj < 8; nj++) {
            int gn = n0 + wn*64 + nj*8 + tig*2;
            if (gn < NN) {
                if (gm < NN)
                    *(float2*)&Cb[(size_t)gm*NN + gn]     = make_float2(c[mi][nj][0], c[mi][nj][1]);
                if (gm + 8 < NN)
                    *(float2*)&Cb[(size_t)(gm+8)*NN + gn] = make_float2(c[mi][nj][2], c[mi][nj][3]);
            }
        }
    }
}

// ---------------- K5: row softmax of L -> E (in place) ------------------------
__global__ void k_softmax(float* __restrict__ L) {
    __shared__ float buf[NN];
    __shared__ float red[256];
    int r = blockIdx.x, tid = threadIdx.x;
    float* row = L + (size_t)r*NN;
    float mx = -1e30f;
    for (int j = tid; j < NN; j += 256) { float v = row[j]; buf[j] = v; mx = fmaxf(mx, v); }
    red[tid] = mx; __syncthreads();
    for (int s = 128; s > 0; s >>= 1) { if (tid < s) red[tid] = fmaxf(red[tid], red[tid+s]); __syncthreads(); }
    mx = red[0]; __syncthreads();
    float sum = 0.f;
    for (int j = tid; j < NN; j += 256) { float v = expf(buf[j]-mx); buf[j] = v; sum += v; }
    red[tid] = sum; __syncthreads();
    for (int s = 128; s > 0; s >>= 1) { if (tid < s) red[tid] += red[tid+s]; __syncthreads(); }
    float inv = 1.f/red[0];
    for (int j = tid; j < NN; j += 256) row[j] = buf[j]*inv;
}

// ---------------- K6a: Ah[b] = A @ h[b] ---------------------------------------
__global__ void k_Ah() {
    __shared__ float As[16][64];
    __shared__ float Bs[16][64];
    int b = blockIdx.z;
    int m0 = blockIdx.x*64;
    int tid = threadIdx.x;
    int ty = tid>>4, tx = tid&15;
    const float* hB = d_h + (size_t)b*NN*HH;
    float acc[4][4];
#pragma unroll
    for (int i=0;i<4;i++)
#pragma unroll
        for (int j=0;j<4;j++) acc[i][j]=0.f;
    for (int k0 = 0; k0 < NN; k0 += 16) {
        { int rowi = tid>>2, k4 = (tid&3)*4;
          float4 v = make_float4(0.f,0.f,0.f,0.f);
          if (m0+rowi < NN) v = *(const float4*)&d_A[(size_t)(m0+rowi)*NN + k0 + k4];
          As[k4][rowi]=v.x; As[k4+1][rowi]=v.y; As[k4+2][rowi]=v.z; As[k4+3][rowi]=v.w; }
        { int kr = tid>>4, c4 = (tid&15)*4;
          *(float4*)&Bs[kr][c4] = *(const float4*)&hB[(size_t)(k0+kr)*HH + c4]; }
        __syncthreads();
#pragma unroll
        for (int k=0;k<16;k++){
            float ra[4], rb[4];
#pragma unroll
            for (int i=0;i<4;i++) ra[i]=As[k][ty*4+i];
#pragma unroll
            for (int j=0;j<4;j++) rb[j]=Bs[k][tx*4+j];
#pragma unroll
            for (int i=0;i<4;i++)
#pragma unroll
                for (int j=0;j<4;j++) acc[i][j] += ra[i]*rb[j];
        }
        __syncthreads();
    }
#pragma unroll
    for (int i=0;i<4;i++){
        int m = m0+ty*4+i;
        if (m >= NN) continue;
#pragma unroll
        for (int j=0;j<4;j++)
            d_Ah[((size_t)b*NN + m)*HH + tx*4+j] = acc[i][j];
    }
}

// ---------------- K6b: xg0[b]=E[b]@h[b], xg1[b]=E[b]@Ah[b] --------------------
__global__ void k_xg() {
    __shared__ float Es[16][64];
    __shared__ float B0[16][64];
    __shared__ float B1[16][64];
    int b = blockIdx.z;
    int m0 = blockIdx.x*64;
    int tid = threadIdx.x;
    int ty = tid>>4, tx = tid&15;
    const float* Em = d_L + (size_t)b*NN*NN;
    const float* hB = d_h  + (size_t)b*NN*HH;
    const float* aB = d_Ah + (size_t)b*NN*HH;
    float a0[4][4], a1[4][4];
#pragma unroll
    for (int i=0;i<4;i++)
#pragma unroll
        for (int j=0;j<4;j++){ a0[i][j]=0.f; a1[i][j]=0.f; }
    for (int k0 = 0; k0 < NN; k0 += 16) {
        { int rowi = tid>>2, k4 = (tid&3)*4;
          float4 v = make_float4(0.f,0.f,0.f,0.f);
          if (m0+rowi < NN) v = *(const float4*)&Em[(size_t)(m0+rowi)*NN + k0 + k4];
          Es[k4][rowi]=v.x; Es[k4+1][rowi]=v.y; Es[k4+2][rowi]=v.z; Es[k4+3][rowi]=v.w; }
        { int kr = tid>>4, c4 = (tid&15)*4;
          *(float4*)&B0[kr][c4] = *(const float4*)&hB[(size_t)(k0+kr)*HH + c4];
          *(float4*)&B1[kr][c4] = *(const float4*)&aB[(size_t)(k0+kr)*HH + c4]; }
        __syncthreads();
#pragma unroll
        for (int k=0;k<16;k++){
            float ra[4], rb0[4], rb1[4];
#pragma unroll
            for (int i=0;i<4;i++) ra[i]=Es[k][ty*4+i];
#pragma unroll
            for (int j=0;j<4;j++){ rb0[j]=B0[k][tx*4+j]; rb1[j]=B1[k][tx*4+j]; }
#pragma unroll
            for (int i=0;i<4;i++)
#pragma unroll
                for (int j=0;j<4;j++){ a0[i][j] += ra[i]*rb0[j]; a1[i][j] += ra[i]*rb1[j]; }
        }
        __syncthreads();
    }
#pragma unroll
    for (int i=0;i<4;i++){
        int m = m0+ty*4+i;
        if (m >= NN) continue;
#pragma unroll
        for (int j=0;j<4;j++){
            d_xg0[((size_t)b*NN + m)*HH + tx*4+j] = a0[i][j];
            d_xg1[((size_t)b*NN + m)*HH + tx*4+j] = a1[i][j];
        }
    }
}

// ---------------- K7: weights = emb @ wp_flat ---------------------------------
__global__ void k_wn(const float* __restrict__ emb, const float* __restrict__ wp) {
    __shared__ float Es[64][16];
    __shared__ float Ws[16][128];
    int n0 = blockIdx.y*64, c0 = blockIdx.x*128;
    int tid = threadIdx.x;
    for (int i=tid;i<1024;i+=256){ int r=i>>4, d=i&15; int n=n0+r; Es[r][d] = (n<NN)? emb[(size_t)n*16+d] : 0.f; }
    for (int i=tid;i<2048;i+=256){ int kr=i>>7, c=i&127; Ws[kr][c] = wp[(size_t)kr*8192 + c0 + c]; }
    __syncthreads();
    int ty=tid>>4, tx=tid&15;
    float acc[4][8];
#pragma unroll
    for (int i=0;i<4;i++)
#pragma unroll
        for (int j=0;j<8;j++) acc[i][j]=0.f;
#pragma unroll
    for (int d=0; d<16; d++){
        float ev[4], wv[8];
#pragma unroll
        for (int i=0;i<4;i++) ev[i]=Es[ty*4+i][d];
#pragma unroll
        for (int j=0;j<8;j++) wv[j]=Ws[d][tx*8+j];
#pragma unroll
        for (int i=0;i<4;i++)
#pragma unroll
            for (int j=0;j<8;j++) acc[i][j] += ev[i]*wv[j];
    }
#pragma unroll
    for (int i=0;i<4;i++){
        int n = n0+ty*4+i;
        if (n >= NN) continue;
#pragma unroll
        for (int j=0;j<8;j++)
            d_wn[(size_t)n*8192 + c0 + tx*8 + j] = acc[i][j];
    }
}

// ---------------- K8: g[b,n,:] = xg_cat[b,n,:] @ W_n + bias_n -----------------
__global__ void k_g(const float* __restrict__ emb, const float* __restrict__ bp) {
    __shared__ float Wns[8192];
    __shared__ float xgs[8][128];
    __shared__ float bias_s[64];
    __shared__ float es[16];
    int n = blockIdx.x, tid = threadIdx.x;
    if (tid < 16) es[tid] = emb[(size_t)n*16+tid];
    for (int i=tid;i<8192;i+=256) Wns[i] = d_wn[(size_t)n*8192 + i];
    for (int i=tid;i<1024;i+=256){
        int b=i>>7, ki=i&127;
        xgs[b][ki] = (ki<64) ? d_xg0[((size_t)b*NN+n)*HH+ki]
                             : d_xg1[((size_t)b*NN+n)*HH+ki-64];
    }
    __syncthreads();
    if (tid < 64) {
        float bv = 0.f;
#pragma unroll
        for (int d=0; d<16; d++) bv += es[d]*bp[d*64+tid];
        bias_s[tid] = bv;
    }
    __syncthreads();
    int o = tid & 63;
#pragma unroll
    for (int rep=0; rep<2; rep++){
        int b = (tid>>6) + rep*4;
        float acc = bias_s[o];
#pragma unroll 8
        for (int ki=0; ki<128; ki++) acc += xgs[b][ki]*Wns[ki*64+o];
        d_g[((size_t)b*NN+n)*HH+o] = acc;
    }
}

// ---------------- K9: out = 0.1*tanh(g @ W_out^T + b_out) ---------------------
__global__ void k_out(const float* __restrict__ Wout, const float* __restrict__ bout,
                      float* __restrict__ out) {
    __shared__ float Wth[64*132];
    __shared__ float Gsh[64*36];
    __shared__ float bo[128];
    int r0 = blockIdx.x*32, o0 = blockIdx.y*128;
    int tid = threadIdx.x;
    for (int i=tid;i<8192;i+=256){ int ol=i>>6, h=i&63; Wth[h*132+ol] = Wout[(size_t)(o0+ol)*64 + h]; }
    for (int i=tid;i<2048;i+=256){ int rr=i>>6, h=i&63; Gsh[h*36+rr]  = d_g[(size_t)(r0+rr)*64 + h]; }
    if (tid<128) bo[tid] = bout[o0+tid];
    __syncthreads();
    int cg = tid & 31, rg = tid >> 5;
    float acc[4][4];
#pragma unroll
    for (int i=0;i<4;i++)
#pragma unroll
        for (int j=0;j<4;j++) acc[i][j]=0.f;
#pragma unroll
    for (int h=0; h<64; h++){
        float4 wv = *(const float4*)&Wth[h*132 + cg*4];
        float4 gv = *(const float4*)&Gsh[h*36 + rg*4];
        float gw[4]={gv.x,gv.y,gv.z,gv.w};
        float ww[4]={wv.x,wv.y,wv.z,wv.w};
#pragma unroll
        for (int i=0;i<4;i++)
#pragma unroll
            for (int j=0;j<4;j++) acc[i][j] += gw[i]*ww[j];
    }
#pragma unroll
    for (int i=0;i<4;i++){
        size_t rowoff = (size_t)(r0 + rg*4 + i)*OUTC + o0 + cg*4;
        float4 v;
        v.x = 0.1f * tanhf(acc[i][0] + bo[cg*4+0]);
        v.y = 0.1f * tanhf(acc[i][1] + bo[cg*4+1]);
        v.z = 0.1f * tanhf(acc[i][2] + bo[cg*4+2]);
        v.w = 0.1f * tanhf(acc[i][3] + bo[cg*4+3]);
        *(float4*)&out[rowoff] = v;
    }
}

// ---------------- launch ------------------------------------------------------
extern "C" void kernel_launch(void* const* d_in, const int* in_sizes, int n_in,
                              void* d_out, int out_size) {
    const float* z    = (const float*)d_in[0];
    const float* Win  = (const float*)d_in[1];
    const float* bin  = (const float*)d_in[2];
    const float* Wout = (const float*)d_in[3];
    const float* bout = (const float*)d_in[4];
    const float* emb  = (const float*)d_in[5];
    const float* wp   = (const float*)d_in[6];
    const float* bp   = (const float*)d_in[7];
    const float* w1   = (const float*)d_in[8];
    const float* w2   = (const float*)d_in[9];
    const float* vsM  = (const float*)d_in[10];
    const float* bs   = (const float*)d_in[11];
    float* out = (float*)d_out;
    (void)in_sizes; (void)n_in; (void)out_size;

    cudaFuncSetAttribute(k_mma, cudaFuncAttributeMaxDynamicSharedMemorySize, SMEM_MMA);

    k_hidden<<<NB*NN, 64>>>(z, Win, bin, w1, w2);
    k_adj<<<NN, 256>>>(emb);
    k_Avs<<<dim3(MP/256, MP), 256>>>(vsM);
    k_T2<<<dim3(NP/32, NP/32), 256>>>(bs);
    k_mma<<<dim3(NP/256, MP/128, NB), 256, SMEM_MMA>>>();

    float* dLptr = nullptr;
    cudaGetSymbolAddress((void**)&dLptr, d_L);
    k_softmax<<<NB*NN, 256>>>(dLptr);

    k_Ah<<<dim3((NN+63)/64, 1, NB), 256>>>();
    k_xg<<<dim3((NN+63)/64, 1, NB), 256>>>();
    k_wn<<<dim3(8192/128, (NN+63)/64), 256>>>(emb, wp);
    k_g<<<NN, 256>>>(emb, bp);
    k_out<<<dim3((NB*NN)/32, OUTC/128), 256>>>(Wout, bout, out);
}

// round 5
// speedup vs baseline: 3.5256x; 1.7714x over previous
#include <cuda_runtime.h>
#include <cuda_fp16.h>
#include <math.h>
#include <stdint.h>

#define NB 8
#define NN 2000
#define HH 64
#define DD 16
#define OUTC 4096

// padded GEMM dims
#define MP 2048
#define NP 2048
#define KSEG 2048            // K for the big GEMM (T_hi only)
#define KCHUNK 64
#define NCHUNK (KSEG/KCHUNK) // 32

// ---------------- scratch (static __device__ — zero-initialized) --------------
__device__ float d_e1 [NB*NN];
__device__ float d_e2 [NB*NN];
__device__ __align__(16) float d_L  [(size_t)NB*NN*NN];   // big-GEMM logits (fp32)
__device__ __align__(16) float d_xg [(size_t)NB*NN*128];  // [b][node][128] fp32
__device__ float d_wn [(size_t)NN*128*HH];
// fp16 operands (pads never written -> stay zero from module init)
__device__ __align__(16) __half d_Abf  [(size_t)MP*KSEG];        // fp16(vs)
__device__ __align__(16) __half d_Bbf  [(size_t)NB*NP*KSEG];     // T_hi, [b][n][k]
__device__ __align__(16) __half d_Ebf  [(size_t)NB*MP*KSEG];     // fp16(E), [b][m][k]
__device__ __align__(16) __half d_Adjbf[(size_t)MP*KSEG];        // fp16(A adj), [m][k]
__device__ __align__(16) __half d_hcat [(size_t)NB*MP*128];      // [b][node][0:64=h,64:128=Ah]
__device__ __align__(16) __half d_gcat [(size_t)NB*NN*192];      // [m][gh|gl|gh]
__device__ __align__(16) __half d_WoutT[(size_t)192*OUTC];       // [Wh;Wh;Wl] rows k, cols o

// ======================= portable PTX helpers (base sm_103 OK) ================
__device__ __forceinline__ uint32_t smem_u32(const void* p) {
    uint32_t a;
    asm("{ .reg .u64 t; cvta.to.shared.u64 t, %1; cvt.u32.u64 %0, t; }" : "=r"(a) : "l"(p));
    return a;
}
__device__ __forceinline__ void cp16(uint32_t s, const void* g) {
    asm volatile("cp.async.cg.shared.global [%0], [%1], 16;" :: "r"(s), "l"(g));
}
#define CP_COMMIT() asm volatile("cp.async.commit_group;" ::: "memory")
#define CP_WAIT1()  asm volatile("cp.async.wait_group 1;" ::: "memory")
#define CP_WAIT0()  asm volatile("cp.async.wait_group 0;" ::: "memory")
__device__ __forceinline__ void ldm_x4(uint32_t* r, uint32_t addr) {
    asm volatile("ldmatrix.sync.aligned.m8n8.x4.shared.b16 {%0,%1,%2,%3}, [%4];"
        : "=r"(r[0]), "=r"(r[1]), "=r"(r[2]), "=r"(r[3]) : "r"(addr));
}
__device__ __forceinline__ void ldm_x2(uint32_t* r, uint32_t addr) {
    asm volatile("ldmatrix.sync.aligned.m8n8.x2.shared.b16 {%0,%1}, [%2];"
        : "=r"(r[0]), "=r"(r[1]) : "r"(addr));
}
__device__ __forceinline__ void ldm_x2_t(uint32_t* r, uint32_t addr) {
    asm volatile("ldmatrix.sync.aligned.m8n8.x2.trans.shared.b16 {%0,%1}, [%2];"
        : "=r"(r[0]), "=r"(r[1]) : "r"(addr));
}
__device__ __forceinline__ void mma_f16(float* c, const uint32_t* a, const uint32_t* b) {
    asm volatile(
        "mma.sync.aligned.m16n8k16.row.col.f32.f16.f16.f32 "
        "{%0,%1,%2,%3}, {%4,%5,%6,%7}, {%8,%9}, {%0,%1,%2,%3};"
        : "+f"(c[0]), "+f"(c[1]), "+f"(c[2]), "+f"(c[3])
        : "r"(a[0]), "r"(a[1]), "r"(a[2]), "r"(a[3]), "r"(b[0]), "r"(b[1]));
}

// ---------------- K1: h = relu(z@W_in^T + b_in) -> hcat[:,0:64] fp16 ----------
__global__ void k_hidden(const float* __restrict__ z, const float* __restrict__ Win,
                         const float* __restrict__ bin, const float* __restrict__ w1,
                         const float* __restrict__ w2) {
    __shared__ float zs[64];
    __shared__ float Ws[64*64];
    __shared__ float r1s[2], r2s[2];
    int row = blockIdx.x;                 // b*NN + node
    int tid = threadIdx.x;
    zs[tid] = z[(size_t)row*64 + tid];
    for (int i = tid; i < 4096; i += 64) {
        int h = i >> 6, c = i & 63;
        Ws[c*64 + h] = Win[i];
    }
    __syncthreads();
    float acc = bin[tid];
#pragma unroll 16
    for (int c = 0; c < 64; c++) acc += zs[c] * Ws[c*64 + tid];
    float hv = fmaxf(acc, 0.f);
    int b = row / NN, node = row % NN;
    d_hcat[((size_t)b*MP + node)*128 + tid] = __float2half_rn(hv);
    float p1 = hv * w1[tid], p2 = hv * w2[tid];
#pragma unroll
    for (int o = 16; o > 0; o >>= 1) {
        p1 += __shfl_down_sync(0xffffffffu, p1, o);
        p2 += __shfl_down_sync(0xffffffffu, p2, o);
    }
    int warp = tid >> 5;
    if ((tid & 31) == 0) { r1s[warp] = p1; r2s[warp] = p2; }
    __syncthreads();
    if (tid == 0) { d_e1[row] = r1s[0] + r1s[1]; d_e2[row] = r2s[0] + r2s[1]; }
}

// ---------------- K2: Adj = softmax(relu(emb@emb^T)) -> fp16 ------------------
__global__ void k_adj(const float* __restrict__ emb) {
    __shared__ float buf[NN];
    __shared__ float red[256];
    __shared__ float ei[16];
    int i = blockIdx.x, tid = threadIdx.x;
    if (tid < 16) ei[tid] = emb[i*16 + tid];
    __syncthreads();
    float mx = -1e30f;
    for (int j = tid; j < NN; j += 256) {
        const float* er = emb + (size_t)j*16;
        float dsum = 0.f;
#pragma unroll
        for (int d = 0; d < 16; d++) dsum += ei[d]*er[d];
        dsum = fmaxf(dsum, 0.f);
        buf[j] = dsum;
        mx = fmaxf(mx, dsum);
    }
    red[tid] = mx; __syncthreads();
    for (int s = 128; s > 0; s >>= 1) { if (tid < s) red[tid] = fmaxf(red[tid], red[tid+s]); __syncthreads(); }
    mx = red[0]; __syncthreads();
    float sum = 0.f;
    for (int j = tid; j < NN; j += 256) { float v = expf(buf[j]-mx); buf[j] = v; sum += v; }
    red[tid] = sum; __syncthreads();
    for (int s = 128; s > 0; s >>= 1) { if (tid < s) red[tid] += red[tid+s]; __syncthreads(); }
    float inv = 1.f/red[0];
    for (int j = tid; j < NN; j += 256)
        d_Adjbf[(size_t)i*KSEG + j] = __float2half_rn(buf[j]*inv);
}

// ---- K3a: A = fp16(vs) -------------------------------------------------------
__global__ void k_Avs(const float* __restrict__ vsM) {
    int k = blockIdx.x*256 + threadIdx.x;
    int m = blockIdx.y;
    float t = (m < NN && k < NN) ? vsM[(size_t)m*NN + k] : 0.f;
    d_Abf[(size_t)m*KSEG + k] = __float2half_rn(t);
}

// ---- K3b: B[b][n][k] = fp16(sigmoid(e1[b,k]*e2[b,n] + bs[k,n])) --------------
__global__ void k_T2(const float* __restrict__ bs) {
    __shared__ float sbs[32][33];
    int k0 = blockIdx.x*32, n0 = blockIdx.y*32;
    int tid = threadIdx.x;
#pragma unroll
    for (int l = 0; l < 4; l++) {
        int kk = (tid >> 5) + l*8, nn = tid & 31;
        int gk = k0 + kk, gn = n0 + nn;
        sbs[kk][nn] = (gk < NN && gn < NN) ? bs[(size_t)gk*NN + gn] : 0.f;
    }
    __syncthreads();
    int nnl = tid >> 4;
    int kl  = (tid & 15) * 2;
#pragma unroll
    for (int half = 0; half < 2; half++) {
        int nn = nnl + half*16;
        int gn = n0 + nn;
        bool nok = gn < NN;
        int gk0 = k0 + kl, gk1 = gk0 + 1;
        float b0 = sbs[kl][nn], b1 = sbs[kl+1][nn];
#pragma unroll
        for (int b = 0; b < NB; b++) {
            float v0 = 0.f, v1 = 0.f;
            if (nok) {
                float e2v = d_e2[b*NN + gn];
                if (gk0 < NN) { float x = d_e1[b*NN + gk0]*e2v + b0; v0 = 1.f/(1.f + expf(-x)); }
                if (gk1 < NN) { float x = d_e1[b*NN + gk1]*e2v + b1; v1 = 1.f/(1.f + expf(-x)); }
            }
            size_t base = ((size_t)b*NP + gn)*KSEG + gk0;
            *(__half2*)&d_Bbf[base] = __halves2half2(__float2half_rn(v0), __float2half_rn(v1));
        }
    }
}

// ---- K4: L[b] = A @ B^T via mma.sync fp16, CTA tile 128x256, K=2048 ----------
#define AROW 144
#define ABUF 18432
#define BBUF 36864
#define SMEM_MMA (2*ABUF + 2*BBUF)     // 110592

__global__ void __launch_bounds__(256, 1) k_mma() {
    extern __shared__ __align__(16) char smem[];
    uint32_t sb = smem_u32(smem);
    int tid = threadIdx.x, lane = tid & 31, w = tid >> 5;
    int b  = blockIdx.z;
    int m0 = blockIdx.y * 128;
    int n0 = blockIdx.x * 256;
    const __half* Ag = d_Abf + (size_t)m0*KSEG;
    const __half* Bg = d_Bbf + ((size_t)b*NP + n0)*KSEG;

    auto issue = [&](int kc, int buf) {
        uint32_t sA = sb + buf*ABUF;
        uint32_t sB = sb + 2*ABUF + buf*BBUF;
        int ka = kc * KCHUNK;
#pragma unroll
        for (int l = 0; l < 4; l++) {
            int seg = tid + l*256;
            int row = seg >> 3, c = seg & 7;
            cp16(sA + row*AROW + c*16, Ag + (size_t)row*KSEG + ka + c*8);
        }
#pragma unroll
        for (int l = 0; l < 8; l++) {
            int seg = tid + l*256;
            int row = seg >> 3, c = seg & 7;
            cp16(sB + row*AROW + c*16, Bg + (size_t)row*KSEG + ka + c*8);
        }
        CP_COMMIT();
    };

    issue(0, 0);
    issue(1, 1);

    float c[4][8][4];
#pragma unroll
    for (int mi = 0; mi < 4; mi++)
#pragma unroll
        for (int nj = 0; nj < 8; nj++)
#pragma unroll
            for (int q = 0; q < 4; q++) c[mi][nj][q] = 0.f;

    int wm = w & 1, wn = w >> 1;
    int a_row = (lane & 15), a_kh = (lane >> 4) * 16;
    int b_row = (lane & 7),  b_kh = ((lane >> 3) & 1) * 16;

    for (int kc = 0; kc < NCHUNK; kc++) {
        CP_WAIT1();
        __syncthreads();
        int buf = kc & 1;
        uint32_t sA = sb + buf*ABUF           + (wm*64 + a_row)*AROW + a_kh;
        uint32_t sB = sb + 2*ABUF + buf*BBUF  + (wn*64 + b_row)*AROW + b_kh;
#pragma unroll
        for (int ks = 0; ks < 4; ks++) {
            uint32_t af[4][4], bf[8][2];
#pragma unroll
            for (int mi = 0; mi < 4; mi++)
                ldm_x4(af[mi], sA + mi*16*AROW + ks*32);
#pragma unroll
            for (int nj = 0; nj < 8; nj++)
                ldm_x2(bf[nj], sB + nj*8*AROW + ks*32);
#pragma unroll
            for (int mi = 0; mi < 4; mi++)
#pragma unroll
                for (int nj = 0; nj < 8; nj++)
                    mma_f16(c[mi][nj], af[mi], bf[nj]);
        }
        __syncthreads();
        if (kc + 2 < NCHUNK) issue(kc + 2, buf);
        else CP_COMMIT();
    }

    float* Cb = d_L + (size_t)b*NN*NN;
    int gid = lane >> 2, tig = lane & 3;
#pragma unroll
    for (int mi = 0; mi < 4; mi++) {
        int gm = m0 + wm*64 + mi*16 + gid;
#pragma unroll
        for (int nj = 0; nj < 8; nj++) {
            int gn = n0 + wn*64 + nj*8 + tig*2;
            if (gn < NN) {
                if (gm < NN)
                    *(float2*)&Cb[(size_t)gm*NN + gn]     = make_float2(c[mi][nj][0], c[mi][nj][1]);
                if (gm + 8 < NN)
                    *(float2*)&Cb[(size_t)(gm+8)*NN + gn] = make_float2(c[mi][nj][2], c[mi][nj][3]);
            }
        }
    }
}

// ---------------- K5: row softmax of L -> E fp16 ------------------------------
__global__ void k_softmax(const float* __restrict__ L) {
    __shared__ float buf[NN];
    __shared__ float red[256];
    int r = blockIdx.x, tid = threadIdx.x;
    const float* row = L + (size_t)r*NN;
    float mx = -1e30f;
    for (int j = tid; j < NN; j += 256) { float v = row[j]; buf[j] = v; mx = fmaxf(mx, v); }
    red[tid] = mx; __syncthreads();
    for (int s = 128; s > 0; s >>= 1) { if (tid < s) red[tid] = fmaxf(red[tid], red[tid+s]); __syncthreads(); }
    mx = red[0]; __syncthreads();
    float sum = 0.f;
    for (int j = tid; j < NN; j += 256) { float v = expf(buf[j]-mx); buf[j] = v; sum += v; }
    red[tid] = sum; __syncthreads();
    for (int s = 128; s > 0; s >>= 1) { if (tid < s) red[tid] += red[tid+s]; __syncthreads(); }
    float inv = 1.f/red[0];
    int b = r / NN, m = r % NN;
    __half* erow = d_Ebf + ((size_t)b*MP + m)*KSEG;
    for (int j = tid; j < NN; j += 256) erow[j] = __float2half_rn(buf[j]*inv);
}

// ---- K6a: hcat[:,64:128] = Adj @ h   (fp16 mma, tile 128x64) -----------------
#define AH_BROW 144
#define AH_BBUF (64*AH_BROW)               // 9216
#define AH_STAGE (ABUF + AH_BBUF)          // 27648
#define AH_SMEM (2*AH_STAGE)               // 55296

__global__ void __launch_bounds__(256) k_Ahmma() {
    extern __shared__ __align__(16) char smem[];
    uint32_t sb = smem_u32(smem);
    int tid = threadIdx.x, lane = tid & 31, w = tid >> 5;
    int b = blockIdx.y;
    int m0 = blockIdx.x * 128;
    const __half* Ag = d_Adjbf + (size_t)m0*KSEG;
    const __half* Bg = d_hcat + (size_t)b*MP*128;    // rows k, cols 0..63 (h)

    auto issue = [&](int kc, int buf) {
        uint32_t sA = sb + buf*AH_STAGE;
        uint32_t sB = sA + ABUF;
#pragma unroll
        for (int l = 0; l < 4; l++) {
            int seg = tid + l*256;
            int row = seg >> 3, c = seg & 7;
            cp16(sA + row*AROW + c*16, Ag + (size_t)row*KSEG + kc*KCHUNK + c*8);
        }
#pragma unroll
        for (int l = 0; l < 2; l++) {
            int seg = tid + l*256;
            int row = seg >> 3, c = seg & 7;
            cp16(sB + row*AH_BROW + c*16, Bg + (size_t)(kc*KCHUNK + row)*128 + c*8);
        }
        CP_COMMIT();
    };

    issue(0, 0);
    issue(1, 1);

    float c[2][4][4];
#pragma unroll
    for (int mi = 0; mi < 2; mi++)
#pragma unroll
        for (int nj = 0; nj < 4; nj++)
#pragma unroll
            for (int q = 0; q < 4; q++) c[mi][nj][q] = 0.f;

    int wm = w >> 1, wn = w & 1;      // 4x2 warp grid, warp tile 32x32
    for (int kc = 0; kc < NCHUNK; kc++) {
        CP_WAIT1();
        __syncthreads();
        int buf = kc & 1;
        uint32_t sA = sb + buf*AH_STAGE + (wm*32 + (lane & 15))*AROW + (lane >> 4)*16;
        uint32_t sB = sb + buf*AH_STAGE + ABUF;
#pragma unroll
        for (int ks = 0; ks < 4; ks++) {
            uint32_t af[2][4], bf[4][2];
#pragma unroll
            for (int mi = 0; mi < 2; mi++)
                ldm_x4(af[mi], sA + mi*16*AROW + ks*32);
#pragma unroll
            for (int nj = 0; nj < 4; nj++)
                ldm_x2_t(bf[nj], sB + (ks*16 + (lane & 15))*AH_BROW + (wn*32 + nj*8)*2);
#pragma unroll
            for (int mi = 0; mi < 2; mi++)
#pragma unroll
                for (int nj = 0; nj < 4; nj++)
                    mma_f16(c[mi][nj], af[mi], bf[nj]);
        }
        __syncthreads();
        if (kc + 2 < NCHUNK) issue(kc + 2, buf);
        else CP_COMMIT();
    }

    int gid = lane >> 2, tig = lane & 3;
#pragma unroll
    for (int mi = 0; mi < 2; mi++) {
        int gm = m0 + wm*32 + mi*16 + gid;
#pragma unroll
        for (int nj = 0; nj < 4; nj++) {
            int gn = wn*32 + nj*8 + tig*2;
            if (gm < NN)
                *(__half2*)&d_hcat[((size_t)b*MP + gm)*128 + 64 + gn] =
                    __halves2half2(__float2half_rn(c[mi][nj][0]), __float2half_rn(c[mi][nj][1]));
            if (gm + 8 < NN)
                *(__half2*)&d_hcat[((size_t)b*MP + gm + 8)*128 + 64 + gn] =
                    __halves2half2(__float2half_rn(c[mi][nj][2]), __float2half_rn(c[mi][nj][3]));
        }
    }
}

// ---- K6b: xg = E @ hcat   (fp16 mma, tile 128x128) ---------------------------
#define XG_BROW 272
#define XG_BBUF (64*XG_BROW)               // 17408
#define XG_STAGE (ABUF + XG_BBUF)          // 35840
#define XG_SMEM (2*XG_STAGE)               // 71680

__global__ void __launch_bounds__(256) k_xgmma() {
    extern __shared__ __align__(16) char smem[];
    uint32_t sb = smem_u32(smem);
    int tid = threadIdx.x, lane = tid & 31, w = tid >> 5;
    int b = blockIdx.y;
    int m0 = blockIdx.x * 128;
    const __half* Ag = d_Ebf + ((size_t)b*MP + m0)*KSEG;
    const __half* Bg = d_hcat + (size_t)b*MP*128;

    auto issue = [&](int kc, int buf) {
        uint32_t sA = sb + buf*XG_STAGE;
        uint32_t sB = sA + ABUF;
#pragma unroll
        for (int l = 0; l < 4; l++) {
            int seg = tid + l*256;
            int row = seg >> 3, c = seg & 7;
            cp16(sA + row*AROW + c*16, Ag + (size_t)row*KSEG + kc*KCHUNK + c*8);
        }
#pragma unroll
        for (int l = 0; l < 4; l++) {
            int seg = tid + l*256;
            int row = seg >> 4, c = seg & 15;
            cp16(sB + row*XG_BROW + c*16, Bg + (size_t)(kc*KCHUNK + row)*128 + c*8);
        }
        CP_COMMIT();
    };

    issue(0, 0);
    issue(1, 1);

    float c[2][8][4];
#pragma unroll
    for (int mi = 0; mi < 2; mi++)
#pragma unroll
        for (int nj = 0; nj < 8; nj++)
#pragma unroll
            for (int q = 0; q < 4; q++) c[mi][nj][q] = 0.f;

    int wm = w >> 1, wn = w & 1;      // 4x2 warp grid, warp tile 32x64
    for (int kc = 0; kc < NCHUNK; kc++) {
        CP_WAIT1();
        __syncthreads();
        int buf = kc & 1;
        uint32_t sA = sb + buf*XG_STAGE + (wm*32 + (lane & 15))*AROW + (lane >> 4)*16;
        uint32_t sB = sb + buf*XG_STAGE + ABUF;
#pragma unroll
        for (int ks = 0; ks < 4; ks++) {
            uint32_t af[2][4], bf[8][2];
#pragma unroll
            for (int mi = 0; mi < 2; mi++)
                ldm_x4(af[mi], sA + mi*16*AROW + ks*32);
#pragma unroll
            for (int nj = 0; nj < 8; nj++)
                ldm_x2_t(bf[nj], sB + (ks*16 + (lane & 15))*XG_BROW + (wn*64 + nj*8)*2);
#pragma unroll
            for (int mi = 0; mi < 2; mi++)
#pragma unroll
                for (int nj = 0; nj < 8; nj++)
                    mma_f16(c[mi][nj], af[mi], bf[nj]);
        }
        __syncthreads();
        if (kc + 2 < NCHUNK) issue(kc + 2, buf);
        else CP_COMMIT();
    }

    int gid = lane >> 2, tig = lane & 3;
#pragma unroll
    for (int mi = 0; mi < 2; mi++) {
        int gm = m0 + wm*32 + mi*16 + gid;
#pragma unroll
        for (int nj = 0; nj < 8; nj++) {
            int gn = wn*64 + nj*8 + tig*2;
            if (gm < NN)
                *(float2*)&d_xg[((size_t)b*NN + gm)*128 + gn] = make_float2(c[mi][nj][0], c[mi][nj][1]);
            if (gm + 8 < NN)
                *(float2*)&d_xg[((size_t)b*NN + gm + 8)*128 + gn] = make_float2(c[mi][nj][2], c[mi][nj][3]);
        }
    }
}

// ---------------- K7: weights = emb @ wp_flat ---------------------------------
__global__ void k_wn(const float* __restrict__ emb, const float* __restrict__ wp) {
    __shared__ float Es[64][16];
    __shared__ float Ws[16][128];
    int n0 = blockIdx.y*64, c0 = blockIdx.x*128;
    int tid = threadIdx.x;
    for (int i=tid;i<1024;i+=256){ int r=i>>4, d=i&15; int n=n0+r; Es[r][d] = (n<NN)? emb[(size_t)n*16+d] : 0.f; }
    for (int i=tid;i<2048;i+=256){ int kr=i>>7, c=i&127; Ws[kr][c] = wp[(size_t)kr*8192 + c0 + c]; }
    __syncthreads();
    int ty=tid>>4, tx=tid&15;
    float acc[4][8];
#pragma unroll
    for (int i=0;i<4;i++)
#pragma unroll
        for (int j=0;j<8;j++) acc[i][j]=0.f;
#pragma unroll
    for (int d=0; d<16; d++){
        float ev[4], wv[8];
#pragma unroll
        for (int i=0;i<4;i++) ev[i]=Es[ty*4+i][d];
#pragma unroll
        for (int j=0;j<8;j++) wv[j]=Ws[d][tx*8+j];
#pragma unroll
        for (int i=0;i<4;i++)
#pragma unroll
            for (int j=0;j<8;j++) acc[i][j] += ev[i]*wv[j];
    }
#pragma unroll
    for (int i=0;i<4;i++){
        int n = n0+ty*4+i;
        if (n >= NN) continue;
#pragma unroll
        for (int j=0;j<8;j++)
            d_wn[(size_t)n*8192 + c0 + tx*8 + j] = acc[i][j];
    }
}

// ---------------- K8: g = xg @ W_n + bias_n -> gcat fp16 [gh|gl|gh] -----------
__global__ void k_g(const float* __restrict__ emb, const float* __restrict__ bp) {
    __shared__ float Wns[8192];
    __shared__ float xgs[8][128];
    __shared__ float bias_s[64];
    __shared__ float es[16];
    int n = blockIdx.x, tid = threadIdx.x;
    if (tid < 16) es[tid] = emb[(size_t)n*16+tid];
    for (int i=tid;i<8192;i+=256) Wns[i] = d_wn[(size_t)n*8192 + i];
    for (int i=tid;i<1024;i+=256){
        int b=i>>7, ki=i&127;
        xgs[b][ki] = d_xg[((size_t)b*NN+n)*128 + ki];
    }
    __syncthreads();
    if (tid < 64) {
        float bv = 0.f;
#pragma unroll
        for (int d=0; d<16; d++) bv += es[d]*bp[d*64+tid];
        bias_s[tid] = bv;
    }
    __syncthreads();
    int o = tid & 63;
#pragma unroll
    for (int rep=0; rep<2; rep++){
        int b = (tid>>6) + rep*4;
        float acc = bias_s[o];
#pragma unroll 8
        for (int ki=0; ki<128; ki++) acc += xgs[b][ki]*Wns[ki*64+o];
        __half gh = __float2half_rn(acc);
        __half gl = __float2half_rn(acc - __half2float(gh));
        size_t base = ((size_t)b*NN + n)*192;
        d_gcat[base + o]       = gh;
        d_gcat[base + 64 + o]  = gl;
        d_gcat[base + 128 + o] = gh;
    }
}

// ---------------- K9a: WoutT = [Wh;Wh;Wl] fp16 --------------------------------
__global__ void k_wprep(const float* __restrict__ Wout) {
    int o = blockIdx.x*256 + threadIdx.x;     // 0..4095
    int h = blockIdx.y;                        // 0..63
    float w = Wout[(size_t)o*64 + h];
    __half wh = __float2half_rn(w);
    __half wl = __float2half_rn(w - __half2float(wh));
    d_WoutT[(size_t)h*OUTC + o]         = wh;
    d_WoutT[(size_t)(64+h)*OUTC + o]    = wh;
    d_WoutT[(size_t)(128+h)*OUTC + o]   = wl;
}

// ---------------- K9b: out = 0.1*tanh(gcat @ WoutT + b_out) -------------------
#define O_AROW 400
#define O_ABUF (128*O_AROW)    // 51200
#define O_BROW 272
#define O_BBUF (192*O_BROW)    // 52224
#define O_SMEM (O_ABUF + O_BBUF)

__global__ void __launch_bounds__(256) k_outmma(const float* __restrict__ bout,
                                                float* __restrict__ out) {
    extern __shared__ __align__(16) char smem[];
    uint32_t sb = smem_u32(smem);
    int tid = threadIdx.x, lane = tid & 31, w = tid >> 5;
    int n0 = blockIdx.x * 128;
    int m0 = blockIdx.y * 128;
    // A: 128 rows x 24 segs (192 fp16 per row)
#pragma unroll
    for (int l = 0; l < 12; l++) {
        int seg = tid + l*256;
        int row = seg / 24, c = seg % 24;
        cp16(sb + row*O_AROW + c*16, d_gcat + (size_t)(m0+row)*192 + c*8);
    }
    // B: 192 rows x 16 segs (128 fp16 per row slice)
#pragma unroll
    for (int l = 0; l < 12; l++) {
        int seg = tid + l*256;
        int row = seg >> 4, c = seg & 15;
        cp16(sb + O_ABUF + row*O_BROW + c*16, d_WoutT + (size_t)row*OUTC + n0 + c*8);
    }
    CP_COMMIT();
    CP_WAIT0();
    __syncthreads();

    int wm = w >> 1, wn = w & 1;      // warp tile 32x64
    float c[2][8][4];
#pragma unroll
    for (int mi = 0; mi < 2; mi++)
#pragma unroll
        for (int nj = 0; nj < 8; nj++)
#pragma unroll
            for (int q = 0; q < 4; q++) c[mi][nj][q] = 0.f;

    uint32_t sA = sb + (wm*32 + (lane & 15))*O_AROW + (lane >> 4)*16;
    uint32_t sB = sb + O_ABUF;
#pragma unroll
    for (int kk = 0; kk < 12; kk++) {
        uint32_t af[2][4], bf[8][2];
#pragma unroll
        for (int mi = 0; mi < 2; mi++)
            ldm_x4(af[mi], sA + mi*16*O_AROW + kk*32);
#pragma unroll
        for (int nj = 0; nj < 8; nj++)
            ldm_x2_t(bf[nj], sB + (kk*16 + (lane & 15))*O_BROW + (wn*64 + nj*8)*2);
#pragma unroll
        for (int mi = 0; mi < 2; mi++)
#pragma unroll
            for (int nj = 0; nj < 8; nj++)
                mma_f16(c[mi][nj], af[mi], bf[nj]);
    }

    int gid = lane >> 2, tig = lane & 3;
#pragma unroll
    for (int mi = 0; mi < 2; mi++) {
        int gm = m0 + wm*32 + mi*16 + gid;
#pragma unroll
        for (int nj = 0; nj < 8; nj++) {
            int gn = n0 + wn*64 + nj*8 + tig*2;
            float b0 = bout[gn], b1 = bout[gn+1];
            float2 v0 = make_float2(0.1f*tanhf(c[mi][nj][0] + b0), 0.1f*tanhf(c[mi][nj][1] + b1));
            float2 v1 = make_float2(0.1f*tanhf(c[mi][nj][2] + b0), 0.1f*tanhf(c[mi][nj][3] + b1));
            *(float2*)&out[(size_t)gm*OUTC + gn]       = v0;
            *(float2*)&out[(size_t)(gm+8)*OUTC + gn]   = v1;
        }
    }
}

// ---------------- launch ------------------------------------------------------
extern "C" void kernel_launch(void* const* d_in, const int* in_sizes, int n_in,
                              void* d_out, int out_size) {
    const float* z    = (const float*)d_in[0];
    const float* Win  = (const float*)d_in[1];
    const float* bin  = (const float*)d_in[2];
    const float* Wout = (const float*)d_in[3];
    const float* bout = (const float*)d_in[4];
    const float* emb  = (const float*)d_in[5];
    const float* wp   = (const float*)d_in[6];
    const float* bp   = (const float*)d_in[7];
    const float* w1   = (const float*)d_in[8];
    const float* w2   = (const float*)d_in[9];
    const float* vsM  = (const float*)d_in[10];
    const float* bs   = (const float*)d_in[11];
    float* out = (float*)d_out;
    (void)in_sizes; (void)n_in; (void)out_size;

    cudaFuncSetAttribute(k_mma,    cudaFuncAttributeMaxDynamicSharedMemorySize, SMEM_MMA);
    cudaFuncSetAttribute(k_Ahmma,  cudaFuncAttributeMaxDynamicSharedMemorySize, AH_SMEM);
    cudaFuncSetAttribute(k_xgmma,  cudaFuncAttributeMaxDynamicSharedMemorySize, XG_SMEM);
    cudaFuncSetAttribute(k_outmma, cudaFuncAttributeMaxDynamicSharedMemorySize, O_SMEM);

    k_hidden<<<NB*NN, 64>>>(z, Win, bin, w1, w2);
    k_adj<<<NN, 256>>>(emb);
    k_Avs<<<dim3(MP/256, MP), 256>>>(vsM);
    k_T2<<<dim3(NP/32, NP/32), 256>>>(bs);
    k_wprep<<<dim3(OUTC/256, 64), 256>>>(Wout);
    k_mma<<<dim3(NP/256, MP/128, NB), 256, SMEM_MMA>>>();

    float* dLptr = nullptr;
    cudaGetSymbolAddress((void**)&dLptr, d_L);
    k_softmax<<<NB*NN, 256>>>(dLptr);

    k_Ahmma<<<dim3(MP/128, NB), 256, AH_SMEM>>>();
    k_xgmma<<<dim3(MP/128, NB), 256, XG_SMEM>>>();
    k_wn<<<dim3(8192/128, (NN+63)/64), 256>>>(emb, wp);
    k_g<<<NN, 256>>>(emb, bp);
    k_outmma<<<dim3(OUTC/128, (NB*NN)/128), 256, O_SMEM>>>(bout, out);
}

// round 6
// speedup vs baseline: 4.2964x; 1.2186x over previous
#include <cuda_runtime.h>
#include <cuda_fp16.h>
#include <math.h>
#include <stdint.h>

#define NB 8
#define NN 2000
#define HH 64
#define DD 16
#define OUTC 4096

// padded GEMM dims
#define MP 2048
#define NP 2048
#define KSEG 2048            // K for the big GEMM (T_hi only)
#define KCHUNK 64
#define NCHUNK (KSEG/KCHUNK) // 32

// ---------------- scratch (static __device__ — zero-initialized) --------------
__device__ float d_e1 [NB*NN];
__device__ float d_e2 [NB*NN];
__device__ __align__(16) __half d_L16[(size_t)NB*NN*NN];  // big-GEMM logits (fp16)
__device__ __align__(16) float d_xg [(size_t)NB*NN*128];  // [b][node][128] fp32
__device__ float d_wn [(size_t)NN*128*HH];
// fp16 operands (pads never written -> stay zero from module init)
__device__ __align__(16) __half d_Abf  [(size_t)MP*KSEG];        // fp16(vs)
__device__ __align__(16) __half d_Bbf  [(size_t)NB*NP*KSEG];     // T_hi, [b][n][k]
__device__ __align__(16) __half d_Ebf  [(size_t)NB*MP*KSEG];     // fp16(E), [b][m][k]
__device__ __align__(16) __half d_Adjbf[(size_t)MP*KSEG];        // fp16(A adj), [m][k]
__device__ __align__(16) __half d_hcat [(size_t)NB*MP*128];      // [b][node][0:64=h,64:128=Ah]
__device__ __align__(16) __half d_gcat [(size_t)NB*NN*192];      // [m][gh|gl|gh]
__device__ __align__(16) __half d_WoutT[(size_t)192*OUTC];       // [Wh;Wh;Wl] rows k, cols o

// ======================= portable PTX helpers (base sm_103 OK) ================
__device__ __forceinline__ uint32_t smem_u32(const void* p) {
    uint32_t a;
    asm("{ .reg .u64 t; cvta.to.shared.u64 t, %1; cvt.u32.u64 %0, t; }" : "=r"(a) : "l"(p));
    return a;
}
__device__ __forceinline__ void cp16(uint32_t s, const void* g) {
    asm volatile("cp.async.cg.shared.global [%0], [%1], 16;" :: "r"(s), "l"(g));
}
#define CP_COMMIT() asm volatile("cp.async.commit_group;" ::: "memory")
#define CP_WAIT1()  asm volatile("cp.async.wait_group 1;" ::: "memory")
#define CP_WAIT2()  asm volatile("cp.async.wait_group 2;" ::: "memory")
#define CP_WAIT0()  asm volatile("cp.async.wait_group 0;" ::: "memory")
__device__ __forceinline__ void ldm_x4(uint32_t* r, uint32_t addr) {
    asm volatile("ldmatrix.sync.aligned.m8n8.x4.shared.b16 {%0,%1,%2,%3}, [%4];"
        : "=r"(r[0]), "=r"(r[1]), "=r"(r[2]), "=r"(r[3]) : "r"(addr));
}
__device__ __forceinline__ void ldm_x2(uint32_t* r, uint32_t addr) {
    asm volatile("ldmatrix.sync.aligned.m8n8.x2.shared.b16 {%0,%1}, [%2];"
        : "=r"(r[0]), "=r"(r[1]) : "r"(addr));
}
__device__ __forceinline__ void ldm_x2_t(uint32_t* r, uint32_t addr) {
    asm volatile("ldmatrix.sync.aligned.m8n8.x2.trans.shared.b16 {%0,%1}, [%2];"
        : "=r"(r[0]), "=r"(r[1]) : "r"(addr));
}
__device__ __forceinline__ void mma_f16(float* c, const uint32_t* a, const uint32_t* b) {
    asm volatile(
        "mma.sync.aligned.m16n8k16.row.col.f32.f16.f16.f32 "
        "{%0,%1,%2,%3}, {%4,%5,%6,%7}, {%8,%9}, {%0,%1,%2,%3};"
        : "+f"(c[0]), "+f"(c[1]), "+f"(c[2]), "+f"(c[3])
        : "r"(a[0]), "r"(a[1]), "r"(a[2]), "r"(a[3]), "r"(b[0]), "r"(b[1]));
}

// ---------------- K1: h = relu(z@W_in^T + b_in) -> hcat[:,0:64] fp16 ----------
// 256 threads handle 16 rows per block (4 at a time); Win loaded once.
__global__ void __launch_bounds__(256) k_hidden(const float* __restrict__ z,
                         const float* __restrict__ Win,
                         const float* __restrict__ bin, const float* __restrict__ w1,
                         const float* __restrict__ w2) {
    __shared__ float Ws[4096];        // transposed: Ws[c*64+h]
    __shared__ float zs[4][64];
    __shared__ float red1[4][2], red2[4][2];
    __shared__ float binS[64], w1S[64], w2S[64];
    int tid = threadIdx.x;
    for (int i = tid; i < 4096; i += 256) {
        int h = i >> 6, c = i & 63;
        Ws[c*64 + h] = Win[i];
    }
    if (tid < 64) { binS[tid] = bin[tid]; w1S[tid] = w1[tid]; w2S[tid] = w2[tid]; }
    __syncthreads();
    int slice = tid >> 6, o = tid & 63;
    int wihalf = (tid >> 5) & 1;      // warp-within-slice
#pragma unroll 1
    for (int it = 0; it < 4; it++) {
        int row = blockIdx.x*16 + it*4 + slice;
        zs[slice][o] = z[(size_t)row*64 + o];
        __syncthreads();
        float acc = binS[o];
#pragma unroll 16
        for (int c = 0; c < 64; c++) acc += zs[slice][c] * Ws[c*64 + o];
        float hv = fmaxf(acc, 0.f);
        int b = row / NN, node = row % NN;
        d_hcat[((size_t)b*MP + node)*128 + o] = __float2half_rn(hv);
        float p1 = hv * w1S[o], p2 = hv * w2S[o];
#pragma unroll
        for (int s = 16; s > 0; s >>= 1) {
            p1 += __shfl_down_sync(0xffffffffu, p1, s);
            p2 += __shfl_down_sync(0xffffffffu, p2, s);
        }
        if ((tid & 31) == 0) { red1[slice][wihalf] = p1; red2[slice][wihalf] = p2; }
        __syncthreads();
        if (o == 0) {
            d_e1[row] = red1[slice][0] + red1[slice][1];
            d_e2[row] = red2[slice][0] + red2[slice][1];
        }
    }
}

// ---------------- K2: Adj = softmax(relu(emb@emb^T)) -> fp16 ------------------
__global__ void k_adj(const float* __restrict__ emb) {
    __shared__ float buf[NN];
    __shared__ float red[256];
    __shared__ float ei[16];
    int i = blockIdx.x, tid = threadIdx.x;
    if (tid < 16) ei[tid] = emb[i*16 + tid];
    __syncthreads();
    float mx = -1e30f;
    for (int j = tid; j < NN; j += 256) {
        const float* er = emb + (size_t)j*16;
        float dsum = 0.f;
#pragma unroll
        for (int d = 0; d < 16; d++) dsum += ei[d]*er[d];
        dsum = fmaxf(dsum, 0.f);
        buf[j] = dsum;
        mx = fmaxf(mx, dsum);
    }
    red[tid] = mx; __syncthreads();
    for (int s = 128; s > 0; s >>= 1) { if (tid < s) red[tid] = fmaxf(red[tid], red[tid+s]); __syncthreads(); }
    mx = red[0]; __syncthreads();
    float sum = 0.f;
    for (int j = tid; j < NN; j += 256) { float v = expf(buf[j]-mx); buf[j] = v; sum += v; }
    red[tid] = sum; __syncthreads();
    for (int s = 128; s > 0; s >>= 1) { if (tid < s) red[tid] += red[tid+s]; __syncthreads(); }
    float inv = 1.f/red[0];
    for (int j = tid; j < NN; j += 256)
        d_Adjbf[(size_t)i*KSEG + j] = __float2half_rn(buf[j]*inv);
}

// ---- K3a: A = fp16(vs) -------------------------------------------------------
__global__ void k_Avs(const float* __restrict__ vsM) {
    int k = blockIdx.x*256 + threadIdx.x;
    int m = blockIdx.y;
    float t = (m < NN && k < NN) ? vsM[(size_t)m*NN + k] : 0.f;
    d_Abf[(size_t)m*KSEG + k] = __float2half_rn(t);
}

// ---- K3b: B[b][n][k] = fp16(sigmoid(e1[b,k]*e2[b,n] + bs[k,n])) --------------
__global__ void k_T2(const float* __restrict__ bs) {
    __shared__ float sbs[32][33];
    int k0 = blockIdx.x*32, n0 = blockIdx.y*32;
    int tid = threadIdx.x;
#pragma unroll
    for (int l = 0; l < 4; l++) {
        int kk = (tid >> 5) + l*8, nn = tid & 31;
        int gk = k0 + kk, gn = n0 + nn;
        sbs[kk][nn] = (gk < NN && gn < NN) ? bs[(size_t)gk*NN + gn] : 0.f;
    }
    __syncthreads();
    int nnl = tid >> 4;
    int kl  = (tid & 15) * 2;
#pragma unroll
    for (int half = 0; half < 2; half++) {
        int nn = nnl + half*16;
        int gn = n0 + nn;
        bool nok = gn < NN;
        int gk0 = k0 + kl, gk1 = gk0 + 1;
        float b0 = sbs[kl][nn], b1 = sbs[kl+1][nn];
#pragma unroll
        for (int b = 0; b < NB; b++) {
            float v0 = 0.f, v1 = 0.f;
            if (nok) {
                float e2v = d_e2[b*NN + gn];
                if (gk0 < NN) { float x = d_e1[b*NN + gk0]*e2v + b0; v0 = 1.f/(1.f + expf(-x)); }
                if (gk1 < NN) { float x = d_e1[b*NN + gk1]*e2v + b1; v1 = 1.f/(1.f + expf(-x)); }
            }
            size_t base = ((size_t)b*NP + gn)*KSEG + gk0;
            *(__half2*)&d_Bbf[base] = __halves2half2(__float2half_rn(v0), __float2half_rn(v1));
        }
    }
}

// ---- K4: L[b] = A @ B^T via mma.sync fp16, CTA tile 128x256, 3-stage ---------
#define AROW 144
#define ABUF 18432
#define BBUF 36864
#define STAGE (ABUF + BBUF)            // 55296
#define SMEM_MMA (3*STAGE)             // 165888

__global__ void __launch_bounds__(256, 1) k_mma() {
    extern __shared__ __align__(16) char smem[];
    uint32_t sb = smem_u32(smem);
    int tid = threadIdx.x, lane = tid & 31, w = tid >> 5;
    int b  = blockIdx.z;
    int m0 = blockIdx.y * 128;
    int n0 = blockIdx.x * 256;
    const __half* Ag = d_Abf + (size_t)m0*KSEG;
    const __half* Bg = d_Bbf + ((size_t)b*NP + n0)*KSEG;

    auto issue = [&](int kc, int buf) {
        uint32_t sA = sb + buf*STAGE;
        uint32_t sB = sA + ABUF;
        int ka = kc * KCHUNK;
#pragma unroll
        for (int l = 0; l < 4; l++) {
            int seg = tid + l*256;
            int row = seg >> 3, c = seg & 7;
            cp16(sA + row*AROW + c*16, Ag + (size_t)row*KSEG + ka + c*8);
        }
#pragma unroll
        for (int l = 0; l < 8; l++) {
            int seg = tid + l*256;
            int row = seg >> 3, c = seg & 7;
            cp16(sB + row*AROW + c*16, Bg + (size_t)row*KSEG + ka + c*8);
        }
        CP_COMMIT();
    };

    issue(0, 0);
    issue(1, 1);
    issue(2, 2);

    float c[4][8][4];
#pragma unroll
    for (int mi = 0; mi < 4; mi++)
#pragma unroll
        for (int nj = 0; nj < 8; nj++)
#pragma unroll
            for (int q = 0; q < 4; q++) c[mi][nj][q] = 0.f;

    int wm = w & 1, wn = w >> 1;
    int a_row = (lane & 15), a_kh = (lane >> 4) * 16;
    int b_row = (lane & 7),  b_kh = ((lane >> 3) & 1) * 16;

    int buf = 0;
    for (int kc = 0; kc < NCHUNK; kc++) {
        CP_WAIT2();
        __syncthreads();
        uint32_t sA = sb + buf*STAGE          + (wm*64 + a_row)*AROW + a_kh;
        uint32_t sB = sb + buf*STAGE + ABUF   + (wn*64 + b_row)*AROW + b_kh;
#pragma unroll
        for (int ks = 0; ks < 4; ks++) {
            uint32_t af[4][4], bf[8][2];
#pragma unroll
            for (int mi = 0; mi < 4; mi++)
                ldm_x4(af[mi], sA + mi*16*AROW + ks*32);
#pragma unroll
            for (int nj = 0; nj < 8; nj++)
                ldm_x2(bf[nj], sB + nj*8*AROW + ks*32);
#pragma unroll
            for (int mi = 0; mi < 4; mi++)
#pragma unroll
                for (int nj = 0; nj < 8; nj++)
                    mma_f16(c[mi][nj], af[mi], bf[nj]);
        }
        __syncthreads();
        if (kc + 3 < NCHUNK) issue(kc + 3, buf);
        else CP_COMMIT();
        buf = (buf == 2) ? 0 : buf + 1;
    }

    __half* Cb = d_L16 + (size_t)b*NN*NN;
    int gid = lane >> 2, tig = lane & 3;
#pragma unroll
    for (int mi = 0; mi < 4; mi++) {
        int gm = m0 + wm*64 + mi*16 + gid;
#pragma unroll
        for (int nj = 0; nj < 8; nj++) {
            int gn = n0 + wn*64 + nj*8 + tig*2;
            if (gn < NN) {
                if (gm < NN)
                    *(__half2*)&Cb[(size_t)gm*NN + gn] =
                        __floats2half2_rn(c[mi][nj][0], c[mi][nj][1]);
                if (gm + 8 < NN)
                    *(__half2*)&Cb[(size_t)(gm+8)*NN + gn] =
                        __floats2half2_rn(c[mi][nj][2], c[mi][nj][3]);
            }
        }
    }
}

// ---------------- K5: row softmax of L16 -> E fp16 ----------------------------
__global__ void k_softmax(const __half* __restrict__ L) {
    __shared__ float buf[NN];
    __shared__ float red[256];
    int r = blockIdx.x, tid = threadIdx.x;
    const __half* row = L + (size_t)r*NN;
    float mx = -1e30f;
    for (int j = tid; j < NN; j += 256) { float v = __half2float(row[j]); buf[j] = v; mx = fmaxf(mx, v); }
    red[tid] = mx; __syncthreads();
    for (int s = 128; s > 0; s >>= 1) { if (tid < s) red[tid] = fmaxf(red[tid], red[tid+s]); __syncthreads(); }
    mx = red[0]; __syncthreads();
    float sum = 0.f;
    for (int j = tid; j < NN; j += 256) { float v = expf(buf[j]-mx); buf[j] = v; sum += v; }
    red[tid] = sum; __syncthreads();
    for (int s = 128; s > 0; s >>= 1) { if (tid < s) red[tid] += red[tid+s]; __syncthreads(); }
    float inv = 1.f/red[0];
    int b = r / NN, m = r % NN;
    __half* erow = d_Ebf + ((size_t)b*MP + m)*KSEG;
    for (int j = tid; j < NN; j += 256) erow[j] = __float2half_rn(buf[j]*inv);
}

// ---- K6a: hcat[:,64:128] = Adj @ h   (fp16 mma, tile 128x64) -----------------
#define AH_BROW 144
#define AH_BBUF (64*AH_BROW)               // 9216
#define AH_STAGE (ABUF + AH_BBUF)          // 27648
#define AH_SMEM (2*AH_STAGE)               // 55296

__global__ void __launch_bounds__(256) k_Ahmma() {
    extern __shared__ __align__(16) char smem[];
    uint32_t sb = smem_u32(smem);
    int tid = threadIdx.x, lane = tid & 31, w = tid >> 5;
    int b = blockIdx.y;
    int m0 = blockIdx.x * 128;
    const __half* Ag = d_Adjbf + (size_t)m0*KSEG;
    const __half* Bg = d_hcat + (size_t)b*MP*128;    // rows k, cols 0..63 (h)

    auto issue = [&](int kc, int buf) {
        uint32_t sA = sb + buf*AH_STAGE;
        uint32_t sB = sA + ABUF;
#pragma unroll
        for (int l = 0; l < 4; l++) {
            int seg = tid + l*256;
            int row = seg >> 3, c = seg & 7;
            cp16(sA + row*AROW + c*16, Ag + (size_t)row*KSEG + kc*KCHUNK + c*8);
        }
#pragma unroll
        for (int l = 0; l < 2; l++) {
            int seg = tid + l*256;
            int row = seg >> 3, c = seg & 7;
            cp16(sB + row*AH_BROW + c*16, Bg + (size_t)(kc*KCHUNK + row)*128 + c*8);
        }
        CP_COMMIT();
    };

    issue(0, 0);
    issue(1, 1);

    float c[2][4][4];
#pragma unroll
    for (int mi = 0; mi < 2; mi++)
#pragma unroll
        for (int nj = 0; nj < 4; nj++)
#pragma unroll
            for (int q = 0; q < 4; q++) c[mi][nj][q] = 0.f;

    int wm = w >> 1, wn = w & 1;      // 4x2 warp grid, warp tile 32x32
    for (int kc = 0; kc < NCHUNK; kc++) {
        CP_WAIT1();
        __syncthreads();
        int buf = kc & 1;
        uint32_t sA = sb + buf*AH_STAGE + (wm*32 + (lane & 15))*AROW + (lane >> 4)*16;
        uint32_t sB = sb + buf*AH_STAGE + ABUF;
#pragma unroll
        for (int ks = 0; ks < 4; ks++) {
            uint32_t af[2][4], bf[4][2];
#pragma unroll
            for (int mi = 0; mi < 2; mi++)
                ldm_x4(af[mi], sA + mi*16*AROW + ks*32);
#pragma unroll
            for (int nj = 0; nj < 4; nj++)
                ldm_x2_t(bf[nj], sB + (ks*16 + (lane & 15))*AH_BROW + (wn*32 + nj*8)*2);
#pragma unroll
            for (int mi = 0; mi < 2; mi++)
#pragma unroll
                for (int nj = 0; nj < 4; nj++)
                    mma_f16(c[mi][nj], af[mi], bf[nj]);
        }
        __syncthreads();
        if (kc + 2 < NCHUNK) issue(kc + 2, buf);
        else CP_COMMIT();
    }

    int gid = lane >> 2, tig = lane & 3;
#pragma unroll
    for (int mi = 0; mi < 2; mi++) {
        int gm = m0 + wm*32 + mi*16 + gid;
#pragma unroll
        for (int nj = 0; nj < 4; nj++) {
            int gn = wn*32 + nj*8 + tig*2;
            if (gm < NN)
                *(__half2*)&d_hcat[((size_t)b*MP + gm)*128 + 64 + gn] =
                    __halves2half2(__float2half_rn(c[mi][nj][0]), __float2half_rn(c[mi][nj][1]));
            if (gm + 8 < NN)
                *(__half2*)&d_hcat[((size_t)b*MP + gm + 8)*128 + 64 + gn] =
                    __halves2half2(__float2half_rn(c[mi][nj][2]), __float2half_rn(c[mi][nj][3]));
        }
    }
}

// ---- K6b: xg = E @ hcat   (fp16 mma, tile 128x128) ---------------------------
#define XG_BROW 272
#define XG_BBUF (64*XG_BROW)               // 17408
#define XG_STAGE (ABUF + XG_BBUF)          // 35840
#define XG_SMEM (2*XG_STAGE)               // 71680

__global__ void __launch_bounds__(256) k_xgmma() {
    extern __shared__ __align__(16) char smem[];
    uint32_t sb = smem_u32(smem);
    int tid = threadIdx.x, lane = tid & 31, w = tid >> 5;
    int b = blockIdx.y;
    int m0 = blockIdx.x * 128;
    const __half* Ag = d_Ebf + ((size_t)b*MP + m0)*KSEG;
    const __half* Bg = d_hcat + (size_t)b*MP*128;

    auto issue = [&](int kc, int buf) {
        uint32_t sA = sb + buf*XG_STAGE;
        uint32_t sB = sA + ABUF;
#pragma unroll
        for (int l = 0; l < 4; l++) {
            int seg = tid + l*256;
            int row = seg >> 3, c = seg & 7;
            cp16(sA + row*AROW + c*16, Ag + (size_t)row*KSEG + kc*KCHUNK + c*8);
        }
#pragma unroll
        for (int l = 0; l < 4; l++) {
            int seg = tid + l*256;
            int row = seg >> 4, c = seg & 15;
            cp16(sB + row*XG_BROW + c*16, Bg + (size_t)(kc*KCHUNK + row)*128 + c*8);
        }
        CP_COMMIT();
    };

    issue(0, 0);
    issue(1, 1);

    float c[2][8][4];
#pragma unroll
    for (int mi = 0; mi < 2; mi++)
#pragma unroll
        for (int nj = 0; nj < 8; nj++)
#pragma unroll
            for (int q = 0; q < 4; q++) c[mi][nj][q] = 0.f;

    int wm = w >> 1, wn = w & 1;      // 4x2 warp grid, warp tile 32x64
    for (int kc = 0; kc < NCHUNK; kc++) {
        CP_WAIT1();
        __syncthreads();
        int buf = kc & 1;
        uint32_t sA = sb + buf*XG_STAGE + (wm*32 + (lane & 15))*AROW + (lane >> 4)*16;
        uint32_t sB = sb + buf*XG_STAGE + ABUF;
#pragma unroll
        for (int ks = 0; ks < 4; ks++) {
            uint32_t af[2][4], bf[8][2];
#pragma unroll
            for (int mi = 0; mi < 2; mi++)
                ldm_x4(af[mi], sA + mi*16*AROW + ks*32);
#pragma unroll
            for (int nj = 0; nj < 8; nj++)
                ldm_x2_t(bf[nj], sB + (ks*16 + (lane & 15))*XG_BROW + (wn*64 + nj*8)*2);
#pragma unroll
            for (int mi = 0; mi < 2; mi++)
#pragma unroll
                for (int nj = 0; nj < 8; nj++)
                    mma_f16(c[mi][nj], af[mi], bf[nj]);
        }
        __syncthreads();
        if (kc + 2 < NCHUNK) issue(kc + 2, buf);
        else CP_COMMIT();
    }

    int gid = lane >> 2, tig = lane & 3;
#pragma unroll
    for (int mi = 0; mi < 2; mi++) {
        int gm = m0 + wm*32 + mi*16 + gid;
#pragma unroll
        for (int nj = 0; nj < 8; nj++) {
            int gn = wn*64 + nj*8 + tig*2;
            if (gm < NN)
                *(float2*)&d_xg[((size_t)b*NN + gm)*128 + gn] = make_float2(c[mi][nj][0], c[mi][nj][1]);
            if (gm + 8 < NN)
                *(float2*)&d_xg[((size_t)b*NN + gm + 8)*128 + gn] = make_float2(c[mi][nj][2], c[mi][nj][3]);
        }
    }
}

// ---------------- K7: weights = emb @ wp_flat ---------------------------------
__global__ void k_wn(const float* __restrict__ emb, const float* __restrict__ wp) {
    __shared__ float Es[64][16];
    __shared__ float Ws[16][128];
    int n0 = blockIdx.y*64, c0 = blockIdx.x*128;
    int tid = threadIdx.x;
    for (int i=tid;i<1024;i+=256){ int r=i>>4, d=i&15; int n=n0+r; Es[r][d] = (n<NN)? emb[(size_t)n*16+d] : 0.f; }
    for (int i=tid;i<2048;i+=256){ int kr=i>>7, c=i&127; Ws[kr][c] = wp[(size_t)kr*8192 + c0 + c]; }
    __syncthreads();
    int ty=tid>>4, tx=tid&15;
    float acc[4][8];
#pragma unroll
    for (int i=0;i<4;i++)
#pragma unroll
        for (int j=0;j<8;j++) acc[i][j]=0.f;
#pragma unroll
    for (int d=0; d<16; d++){
        float ev[4], wv[8];
#pragma unroll
        for (int i=0;i<4;i++) ev[i]=Es[ty*4+i][d];
#pragma unroll
        for (int j=0;j<8;j++) wv[j]=Ws[d][tx*8+j];
#pragma unroll
        for (int i=0;i<4;i++)
#pragma unroll
            for (int j=0;j<8;j++) acc[i][j] += ev[i]*wv[j];
    }
#pragma unroll
    for (int i=0;i<4;i++){
        int n = n0+ty*4+i;
        if (n >= NN) continue;
#pragma unroll
        for (int j=0;j<8;j++)
            d_wn[(size_t)n*8192 + c0 + tx*8 + j] = acc[i][j];
    }
}

// ---------------- K8: g = xg @ W_n + bias_n -> gcat fp16 [gh|gl|gh] -----------
__global__ void k_g(const float* __restrict__ emb, const float* __restrict__ bp) {
    __shared__ float Wns[8192];
    __shared__ float xgs[8][128];
    __shared__ float bias_s[64];
    __shared__ float es[16];
    int n = blockIdx.x, tid = threadIdx.x;
    if (tid < 16) es[tid] = emb[(size_t)n*16+tid];
    for (int i=tid;i<8192;i+=256) Wns[i] = d_wn[(size_t)n*8192 + i];
    for (int i=tid;i<1024;i+=256){
        int b=i>>7, ki=i&127;
        xgs[b][ki] = d_xg[((size_t)b*NN+n)*128 + ki];
    }
    __syncthreads();
    if (tid < 64) {
        float bv = 0.f;
#pragma unroll
        for (int d=0; d<16; d++) bv += es[d]*bp[d*64+tid];
        bias_s[tid] = bv;
    }
    __syncthreads();
    int o = tid & 63;
#pragma unroll
    for (int rep=0; rep<2; rep++){
        int b = (tid>>6) + rep*4;
        float acc = bias_s[o];
#pragma unroll 8
        for (int ki=0; ki<128; ki++) acc += xgs[b][ki]*Wns[ki*64+o];
        __half gh = __float2half_rn(acc);
        __half gl = __float2half_rn(acc - __half2float(gh));
        size_t base = ((size_t)b*NN + n)*192;
        d_gcat[base + o]       = gh;
        d_gcat[base + 64 + o]  = gl;
        d_gcat[base + 128 + o] = gh;
    }
}

// ---------------- K9a: WoutT = [Wh;Wh;Wl] fp16 --------------------------------
__global__ void k_wprep(const float* __restrict__ Wout) {
    int o = blockIdx.x*256 + threadIdx.x;     // 0..4095
    int h = blockIdx.y;                        // 0..63
    float w = Wout[(size_t)o*64 + h];
    __half wh = __float2half_rn(w);
    __half wl = __float2half_rn(w - __half2float(wh));
    d_WoutT[(size_t)h*OUTC + o]         = wh;
    d_WoutT[(size_t)(64+h)*OUTC + o]    = wh;
    d_WoutT[(size_t)(128+h)*OUTC + o]   = wl;
}

// ---------------- K9b: out = 0.1*tanh(gcat @ WoutT + b_out) -------------------
#define O_AROW 400
#define O_ABUF (128*O_AROW)    // 51200
#define O_BROW 272
#define O_BBUF (192*O_BROW)    // 52224
#define O_SMEM (O_ABUF + O_BBUF)

__global__ void __launch_bounds__(256) k_outmma(const float* __restrict__ bout,
                                                float* __restrict__ out) {
    extern __shared__ __align__(16) char smem[];
    uint32_t sb = smem_u32(smem);
    int tid = threadIdx.x, lane = tid & 31, w = tid >> 5;
    int n0 = blockIdx.x * 128;
    int m0 = blockIdx.y * 128;
#pragma unroll
    for (int l = 0; l < 12; l++) {
        int seg = tid + l*256;
        int row = seg / 24, c = seg % 24;
        cp16(sb + row*O_AROW + c*16, d_gcat + (size_t)(m0+row)*192 + c*8);
    }
#pragma unroll
    for (int l = 0; l < 12; l++) {
        int seg = tid + l*256;
        int row = seg >> 4, c = seg & 15;
        cp16(sb + O_ABUF + row*O_BROW + c*16, d_WoutT + (size_t)row*OUTC + n0 + c*8);
    }
    CP_COMMIT();
    CP_WAIT0();
    __syncthreads();

    int wm = w >> 1, wn = w & 1;      // warp tile 32x64
    float c[2][8][4];
#pragma unroll
    for (int mi = 0; mi < 2; mi++)
#pragma unroll
        for (int nj = 0; nj < 8; nj++)
#pragma unroll
            for (int q = 0; q < 4; q++) c[mi][nj][q] = 0.f;

    uint32_t sA = sb + (wm*32 + (lane & 15))*O_AROW + (lane >> 4)*16;
    uint32_t sB = sb + O_ABUF;
#pragma unroll
    for (int kk = 0; kk < 12; kk++) {
        uint32_t af[2][4], bf[8][2];
#pragma unroll
        for (int mi = 0; mi < 2; mi++)
            ldm_x4(af[mi], sA + mi*16*O_AROW + kk*32);
#pragma unroll
        for (int nj = 0; nj < 8; nj++)
            ldm_x2_t(bf[nj], sB + (kk*16 + (lane & 15))*O_BROW + (wn*64 + nj*8)*2);
#pragma unroll
        for (int mi = 0; mi < 2; mi++)
#pragma unroll
            for (int nj = 0; nj < 8; nj++)
                mma_f16(c[mi][nj], af[mi], bf[nj]);
    }

    int gid = lane >> 2, tig = lane & 3;
#pragma unroll
    for (int mi = 0; mi < 2; mi++) {
        int gm = m0 + wm*32 + mi*16 + gid;
#pragma unroll
        for (int nj = 0; nj < 8; nj++) {
            int gn = n0 + wn*64 + nj*8 + tig*2;
            float b0 = bout[gn], b1 = bout[gn+1];
            float2 v0 = make_float2(0.1f*tanhf(c[mi][nj][0] + b0), 0.1f*tanhf(c[mi][nj][1] + b1));
            float2 v1 = make_float2(0.1f*tanhf(c[mi][nj][2] + b0), 0.1f*tanhf(c[mi][nj][3] + b1));
            *(float2*)&out[(size_t)gm*OUTC + gn]       = v0;
            *(float2*)&out[(size_t)(gm+8)*OUTC + gn]   = v1;
        }
    }
}

// ---------------- launch ------------------------------------------------------
extern "C" void kernel_launch(void* const* d_in, const int* in_sizes, int n_in,
                              void* d_out, int out_size) {
    const float* z    = (const float*)d_in[0];
    const float* Win  = (const float*)d_in[1];
    const float* bin  = (const float*)d_in[2];
    const float* Wout = (const float*)d_in[3];
    const float* bout = (const float*)d_in[4];
    const float* emb  = (const float*)d_in[5];
    const float* wp   = (const float*)d_in[6];
    const float* bp   = (const float*)d_in[7];
    const float* w1   = (const float*)d_in[8];
    const float* w2   = (const float*)d_in[9];
    const float* vsM  = (const float*)d_in[10];
    const float* bs   = (const float*)d_in[11];
    float* out = (float*)d_out;
    (void)in_sizes; (void)n_in; (void)out_size;

    cudaFuncSetAttribute(k_mma,    cudaFuncAttributeMaxDynamicSharedMemorySize, SMEM_MMA);
    cudaFuncSetAttribute(k_Ahmma,  cudaFuncAttributeMaxDynamicSharedMemorySize, AH_SMEM);
    cudaFuncSetAttribute(k_xgmma,  cudaFuncAttributeMaxDynamicSharedMemorySize, XG_SMEM);
    cudaFuncSetAttribute(k_outmma, cudaFuncAttributeMaxDynamicSharedMemorySize, O_SMEM);

    k_hidden<<<(NB*NN)/16, 256>>>(z, Win, bin, w1, w2);
    k_adj<<<NN, 256>>>(emb);
    k_Avs<<<dim3(MP/256, MP), 256>>>(vsM);
    k_T2<<<dim3(NP/32, NP/32), 256>>>(bs);
    k_wprep<<<dim3(OUTC/256, 64), 256>>>(Wout);
    k_mma<<<dim3(NP/256, MP/128, NB), 256, SMEM_MMA>>>();

    __half* dLptr = nullptr;
    cudaGetSymbolAddress((void**)&dLptr, d_L16);
    k_softmax<<<NB*NN, 256>>>(dLptr);

    k_Ahmma<<<dim3(MP/128, NB), 256, AH_SMEM>>>();
    k_xgmma<<<dim3(MP/128, NB), 256, XG_SMEM>>>();
    k_wn<<<dim3(8192/128, (NN+63)/64), 256>>>(emb, wp);
    k_g<<<NN, 256>>>(emb, bp);
    k_outmma<<<dim3(OUTC/128, (NB*NN)/128), 256, O_SMEM>>>(bout, out);
}

// round 7
// speedup vs baseline: 4.4762x; 1.0418x over previous
#include <cuda_runtime.h>
#include <cuda_fp16.h>
#include <math.h>
#include <stdint.h>

#define NB 8
#define NN 2000
#define HH 64
#define DD 16
#define OUTC 4096

// padded GEMM dims
#define MP 2048
#define NP 2048
#define KSEG 2048            // K for the big GEMM (T_hi only)
#define KCHUNK 64
#define NCHUNK (KSEG/KCHUNK) // 32

// ---------------- scratch (static __device__ — zero-initialized) --------------
__device__ float d_e1 [NB*NN];
__device__ float d_e2 [NB*NN];
__device__ __align__(16) __half d_L16[(size_t)NB*NN*NN];  // big-GEMM logits (fp16)
__device__ __align__(16) float d_xg [(size_t)NB*NN*128];  // [b][node][128] fp32
__device__ __align__(16) __half d_wn16[(size_t)NN*128*HH];
// fp16 operands (pads never written -> stay zero from module init)
__device__ __align__(16) __half d_Abf  [(size_t)MP*KSEG];        // fp16(vs)
__device__ __align__(16) __half d_Bbf  [(size_t)NB*NP*KSEG];     // T_hi, [b][n][k]
__device__ __align__(16) __half d_Ebf  [(size_t)NB*MP*KSEG];     // fp16(E), [b][m][k]
__device__ __align__(16) __half d_Adjbf[(size_t)MP*KSEG];        // fp16(A adj), [m][k]
__device__ __align__(16) __half d_hcat [(size_t)NB*MP*128];      // [b][node][0:64=h,64:128=Ah]
__device__ __align__(16) __half d_gcat [(size_t)NB*NN*192];      // [m][gh|gl|gh]
__device__ __align__(16) __half d_WoutT[(size_t)192*OUTC];       // [Wh;Wh;Wl] rows k, cols o

// ======================= portable PTX helpers (base sm_103 OK) ================
__device__ __forceinline__ uint32_t smem_u32(const void* p) {
    uint32_t a;
    asm("{ .reg .u64 t; cvta.to.shared.u64 t, %1; cvt.u32.u64 %0, t; }" : "=r"(a) : "l"(p));
    return a;
}
__device__ __forceinline__ void cp16(uint32_t s, const void* g) {
    asm volatile("cp.async.cg.shared.global [%0], [%1], 16;" :: "r"(s), "l"(g));
}
#define CP_COMMIT() asm volatile("cp.async.commit_group;" ::: "memory")
#define CP_WAIT1()  asm volatile("cp.async.wait_group 1;" ::: "memory")
#define CP_WAIT2()  asm volatile("cp.async.wait_group 2;" ::: "memory")
#define CP_WAIT0()  asm volatile("cp.async.wait_group 0;" ::: "memory")
__device__ __forceinline__ void ldm_x4(uint32_t* r, uint32_t addr) {
    asm volatile("ldmatrix.sync.aligned.m8n8.x4.shared.b16 {%0,%1,%2,%3}, [%4];"
        : "=r"(r[0]), "=r"(r[1]), "=r"(r[2]), "=r"(r[3]) : "r"(addr));
}
__device__ __forceinline__ void ldm_x2(uint32_t* r, uint32_t addr) {
    asm volatile("ldmatrix.sync.aligned.m8n8.x2.shared.b16 {%0,%1}, [%2];"
        : "=r"(r[0]), "=r"(r[1]) : "r"(addr));
}
__device__ __forceinline__ void ldm_x2_t(uint32_t* r, uint32_t addr) {
    asm volatile("ldmatrix.sync.aligned.m8n8.x2.trans.shared.b16 {%0,%1}, [%2];"
        : "=r"(r[0]), "=r"(r[1]) : "r"(addr));
}
__device__ __forceinline__ void mma_f16(float* c, const uint32_t* a, const uint32_t* b) {
    asm volatile(
        "mma.sync.aligned.m16n8k16.row.col.f32.f16.f16.f32 "
        "{%0,%1,%2,%3}, {%4,%5,%6,%7}, {%8,%9}, {%0,%1,%2,%3};"
        : "+f"(c[0]), "+f"(c[1]), "+f"(c[2]), "+f"(c[3])
        : "r"(a[0]), "r"(a[1]), "r"(a[2]), "r"(a[3]), "r"(b[0]), "r"(b[1]));
}

// ---------------- K1: h = relu(z@W_in^T + b_in) -> hcat[:,0:64] fp16 ----------
__global__ void __launch_bounds__(256) k_hidden(const float* __restrict__ z,
                         const float* __restrict__ Win,
                         const float* __restrict__ bin, const float* __restrict__ w1,
                         const float* __restrict__ w2) {
    __shared__ float Ws[4096];        // transposed: Ws[c*64+h]
    __shared__ float zs[4][64];
    __shared__ float red1[4][2], red2[4][2];
    __shared__ float binS[64], w1S[64], w2S[64];
    int tid = threadIdx.x;
    for (int i = tid; i < 4096; i += 256) {
        int h = i >> 6, c = i & 63;
        Ws[c*64 + h] = Win[i];
    }
    if (tid < 64) { binS[tid] = bin[tid]; w1S[tid] = w1[tid]; w2S[tid] = w2[tid]; }
    __syncthreads();
    int slice = tid >> 6, o = tid & 63;
    int wihalf = (tid >> 5) & 1;
#pragma unroll 1
    for (int it = 0; it < 4; it++) {
        int row = blockIdx.x*16 + it*4 + slice;
        zs[slice][o] = z[(size_t)row*64 + o];
        __syncthreads();
        float acc = binS[o];
#pragma unroll 16
        for (int c = 0; c < 64; c++) acc += zs[slice][c] * Ws[c*64 + o];
        float hv = fmaxf(acc, 0.f);
        int b = row / NN, node = row % NN;
        d_hcat[((size_t)b*MP + node)*128 + o] = __float2half_rn(hv);
        float p1 = hv * w1S[o], p2 = hv * w2S[o];
#pragma unroll
        for (int s = 16; s > 0; s >>= 1) {
            p1 += __shfl_down_sync(0xffffffffu, p1, s);
            p2 += __shfl_down_sync(0xffffffffu, p2, s);
        }
        if ((tid & 31) == 0) { red1[slice][wihalf] = p1; red2[slice][wihalf] = p2; }
        __syncthreads();
        if (o == 0) {
            d_e1[row] = red1[slice][0] + red1[slice][1];
            d_e2[row] = red2[slice][0] + red2[slice][1];
        }
    }
}

// ---------------- K2: Adj = softmax(relu(emb@emb^T)) -> fp16 ------------------
__global__ void k_adj(const float* __restrict__ emb) {
    __shared__ float buf[NN];
    __shared__ float red[256];
    __shared__ float ei[16];
    int i = blockIdx.x, tid = threadIdx.x;
    if (tid < 16) ei[tid] = emb[i*16 + tid];
    __syncthreads();
    float mx = -1e30f;
    for (int j = tid; j < NN; j += 256) {
        const float* er = emb + (size_t)j*16;
        float dsum = 0.f;
#pragma unroll
        for (int d = 0; d < 16; d++) dsum += ei[d]*er[d];
        dsum = fmaxf(dsum, 0.f);
        buf[j] = dsum;
        mx = fmaxf(mx, dsum);
    }
    red[tid] = mx; __syncthreads();
    for (int s = 128; s > 0; s >>= 1) { if (tid < s) red[tid] = fmaxf(red[tid], red[tid+s]); __syncthreads(); }
    mx = red[0]; __syncthreads();
    float sum = 0.f;
    for (int j = tid; j < NN; j += 256) { float v = expf(buf[j]-mx); buf[j] = v; sum += v; }
    red[tid] = sum; __syncthreads();
    for (int s = 128; s > 0; s >>= 1) { if (tid < s) red[tid] += red[tid+s]; __syncthreads(); }
    float inv = 1.f/red[0];
    for (int j = tid; j < NN; j += 256)
        d_Adjbf[(size_t)i*KSEG + j] = __float2half_rn(buf[j]*inv);
}

// ---- K3a: A = fp16(vs) -------------------------------------------------------
__global__ void k_Avs(const float* __restrict__ vsM) {
    int k = blockIdx.x*256 + threadIdx.x;
    int m = blockIdx.y;
    float t = (m < NN && k < NN) ? vsM[(size_t)m*NN + k] : 0.f;
    d_Abf[(size_t)m*KSEG + k] = __float2half_rn(t);
}

// ---- K3b: B[b][n][k] = fp16(sigmoid(e1[b,k]*e2[b,n] + bs[k,n])) --------------
__global__ void k_T2(const float* __restrict__ bs) {
    __shared__ float sbs[32][33];
    int k0 = blockIdx.x*32, n0 = blockIdx.y*32;
    int tid = threadIdx.x;
#pragma unroll
    for (int l = 0; l < 4; l++) {
        int kk = (tid >> 5) + l*8, nn = tid & 31;
        int gk = k0 + kk, gn = n0 + nn;
        sbs[kk][nn] = (gk < NN && gn < NN) ? bs[(size_t)gk*NN + gn] : 0.f;
    }
    __syncthreads();
    int nnl = tid >> 4;
    int kl  = (tid & 15) * 2;
#pragma unroll
    for (int half = 0; half < 2; half++) {
        int nn = nnl + half*16;
        int gn = n0 + nn;
        bool nok = gn < NN;
        int gk0 = k0 + kl, gk1 = gk0 + 1;
        float b0 = sbs[kl][nn], b1 = sbs[kl+1][nn];
#pragma unroll
        for (int b = 0; b < NB; b++) {
            float v0 = 0.f, v1 = 0.f;
            if (nok) {
                float e2v = d_e2[b*NN + gn];
                if (gk0 < NN) { float x = d_e1[b*NN + gk0]*e2v + b0; v0 = 1.f/(1.f + expf(-x)); }
                if (gk1 < NN) { float x = d_e1[b*NN + gk1]*e2v + b1; v1 = 1.f/(1.f + expf(-x)); }
            }
            size_t base = ((size_t)b*NP + gn)*KSEG + gk0;
            *(__half2*)&d_Bbf[base] = __halves2half2(__float2half_rn(v0), __float2half_rn(v1));
        }
    }
}

// ---- K4: L[b] = A @ B^T via mma.sync fp16, CTA tile 128x256, 3-stage ---------
#define AROW 144
#define ABUF 18432
#define BBUF 36864
#define STAGE (ABUF + BBUF)            // 55296
#define SMEM_MMA (3*STAGE)             // 165888

__global__ void __launch_bounds__(256, 1) k_mma() {
    extern __shared__ __align__(16) char smem[];
    uint32_t sb = smem_u32(smem);
    int tid = threadIdx.x, lane = tid & 31, w = tid >> 5;
    int b  = blockIdx.z;
    int m0 = blockIdx.y * 128;
    int n0 = blockIdx.x * 256;
    const __half* Ag = d_Abf + (size_t)m0*KSEG;
    const __half* Bg = d_Bbf + ((size_t)b*NP + n0)*KSEG;

    auto issue = [&](int kc, int buf) {
        uint32_t sA = sb + buf*STAGE;
        uint32_t sB = sA + ABUF;
        int ka = kc * KCHUNK;
#pragma unroll
        for (int l = 0; l < 4; l++) {
            int seg = tid + l*256;
            int row = seg >> 3, c = seg & 7;
            cp16(sA + row*AROW + c*16, Ag + (size_t)row*KSEG + ka + c*8);
        }
#pragma unroll
        for (int l = 0; l < 8; l++) {
            int seg = tid + l*256;
            int row = seg >> 3, c = seg & 7;
            cp16(sB + row*AROW + c*16, Bg + (size_t)row*KSEG + ka + c*8);
        }
        CP_COMMIT();
    };

    issue(0, 0);
    issue(1, 1);
    issue(2, 2);

    float c[4][8][4];
#pragma unroll
    for (int mi = 0; mi < 4; mi++)
#pragma unroll
        for (int nj = 0; nj < 8; nj++)
#pragma unroll
            for (int q = 0; q < 4; q++) c[mi][nj][q] = 0.f;

    int wm = w & 1, wn = w >> 1;
    int a_row = (lane & 15), a_kh = (lane >> 4) * 16;
    // B x4 lane addressing: rows pairs of nj (16 rows), split k-halves
    int b_off = ((lane & 7) + ((lane >> 4) & 1)*8)*AROW + ((lane >> 3) & 1)*16;

    int buf = 0;
    for (int kc = 0; kc < NCHUNK; kc++) {
        CP_WAIT2();
        __syncthreads();
        uint32_t sA = sb + buf*STAGE          + (wm*64 + a_row)*AROW + a_kh;
        uint32_t sB = sb + buf*STAGE + ABUF   + (wn*64)*AROW + b_off;
#pragma unroll
        for (int ks = 0; ks < 4; ks++) {
            uint32_t af[4][4], bf[8][2];
#pragma unroll
            for (int mi = 0; mi < 4; mi++)
                ldm_x4(af[mi], sA + mi*16*AROW + ks*32);
#pragma unroll
            for (int j = 0; j < 4; j++) {
                uint32_t q[4];
                ldm_x4(q, sB + j*16*AROW + ks*32);
                bf[2*j][0] = q[0]; bf[2*j][1] = q[1];
                bf[2*j+1][0] = q[2]; bf[2*j+1][1] = q[3];
            }
#pragma unroll
            for (int mi = 0; mi < 4; mi++)
#pragma unroll
                for (int nj = 0; nj < 8; nj++)
                    mma_f16(c[mi][nj], af[mi], bf[nj]);
        }
        __syncthreads();
        if (kc + 3 < NCHUNK) issue(kc + 3, buf);
        else CP_COMMIT();
        buf = (buf == 2) ? 0 : buf + 1;
    }

    __half* Cb = d_L16 + (size_t)b*NN*NN;
    int gid = lane >> 2, tig = lane & 3;
#pragma unroll
    for (int mi = 0; mi < 4; mi++) {
        int gm = m0 + wm*64 + mi*16 + gid;
#pragma unroll
        for (int nj = 0; nj < 8; nj++) {
            int gn = n0 + wn*64 + nj*8 + tig*2;
            if (gn < NN) {
                if (gm < NN)
                    *(__half2*)&Cb[(size_t)gm*NN + gn] =
                        __floats2half2_rn(c[mi][nj][0], c[mi][nj][1]);
                if (gm + 8 < NN)
                    *(__half2*)&Cb[(size_t)(gm+8)*NN + gn] =
                        __floats2half2_rn(c[mi][nj][2], c[mi][nj][3]);
            }
        }
    }
}

// ---------------- K5: row softmax of L16 -> E fp16 (half2 vectorized) ---------
__global__ void k_softmax(const __half* __restrict__ L) {
    __shared__ float buf[NN];
    __shared__ float red[256];
    int r = blockIdx.x, tid = threadIdx.x;
    const __half2* row2 = (const __half2*)(L + (size_t)r*NN);
    float mx = -1e30f;
    for (int j = tid; j < NN/2; j += 256) {
        float2 v = __half22float2(row2[j]);
        buf[2*j] = v.x; buf[2*j+1] = v.y;
        mx = fmaxf(mx, fmaxf(v.x, v.y));
    }
    red[tid] = mx; __syncthreads();
    for (int s = 128; s > 0; s >>= 1) { if (tid < s) red[tid] = fmaxf(red[tid], red[tid+s]); __syncthreads(); }
    mx = red[0]; __syncthreads();
    float sum = 0.f;
    for (int j = tid; j < NN; j += 256) { float v = expf(buf[j]-mx); buf[j] = v; sum += v; }
    red[tid] = sum; __syncthreads();
    for (int s = 128; s > 0; s >>= 1) { if (tid < s) red[tid] += red[tid+s]; __syncthreads(); }
    float inv = 1.f/red[0];
    int b = r / NN, m = r % NN;
    __half2* erow2 = (__half2*)(d_Ebf + ((size_t)b*MP + m)*KSEG);
    for (int j = tid; j < NN/2; j += 256)
        erow2[j] = __floats2half2_rn(buf[2*j]*inv, buf[2*j+1]*inv);
}

// ---- K6a: hcat[:,64:128] = Adj @ h   (fp16 mma, tile 128x64) -----------------
#define AH_BROW 144
#define AH_BBUF (64*AH_BROW)               // 9216
#define AH_STAGE (ABUF + AH_BBUF)          // 27648
#define AH_SMEM (2*AH_STAGE)               // 55296

__global__ void __launch_bounds__(256) k_Ahmma() {
    extern __shared__ __align__(16) char smem[];
    uint32_t sb = smem_u32(smem);
    int tid = threadIdx.x, lane = tid & 31, w = tid >> 5;
    int b = blockIdx.y;
    int m0 = blockIdx.x * 128;
    const __half* Ag = d_Adjbf + (size_t)m0*KSEG;
    const __half* Bg = d_hcat + (size_t)b*MP*128;

    auto issue = [&](int kc, int buf) {
        uint32_t sA = sb + buf*AH_STAGE;
        uint32_t sB = sA + ABUF;
#pragma unroll
        for (int l = 0; l < 4; l++) {
            int seg = tid + l*256;
            int row = seg >> 3, c = seg & 7;
            cp16(sA + row*AROW + c*16, Ag + (size_t)row*KSEG + kc*KCHUNK + c*8);
        }
#pragma unroll
        for (int l = 0; l < 2; l++) {
            int seg = tid + l*256;
            int row = seg >> 3, c = seg & 7;
            cp16(sB + row*AH_BROW + c*16, Bg + (size_t)(kc*KCHUNK + row)*128 + c*8);
        }
        CP_COMMIT();
    };

    issue(0, 0);
    issue(1, 1);

    float c[2][4][4];
#pragma unroll
    for (int mi = 0; mi < 2; mi++)
#pragma unroll
        for (int nj = 0; nj < 4; nj++)
#pragma unroll
            for (int q = 0; q < 4; q++) c[mi][nj][q] = 0.f;

    int wm = w >> 1, wn = w & 1;
    for (int kc = 0; kc < NCHUNK; kc++) {
        CP_WAIT1();
        __syncthreads();
        int buf = kc & 1;
        uint32_t sA = sb + buf*AH_STAGE + (wm*32 + (lane & 15))*AROW + (lane >> 4)*16;
        uint32_t sB = sb + buf*AH_STAGE + ABUF;
#pragma unroll
        for (int ks = 0; ks < 4; ks++) {
            uint32_t af[2][4], bf[4][2];
#pragma unroll
            for (int mi = 0; mi < 2; mi++)
                ldm_x4(af[mi], sA + mi*16*AROW + ks*32);
#pragma unroll
            for (int nj = 0; nj < 4; nj++)
                ldm_x2_t(bf[nj], sB + (ks*16 + (lane & 15))*AH_BROW + (wn*32 + nj*8)*2);
#pragma unroll
            for (int mi = 0; mi < 2; mi++)
#pragma unroll
                for (int nj = 0; nj < 4; nj++)
                    mma_f16(c[mi][nj], af[mi], bf[nj]);
        }
        __syncthreads();
        if (kc + 2 < NCHUNK) issue(kc + 2, buf);
        else CP_COMMIT();
    }

    int gid = lane >> 2, tig = lane & 3;
#pragma unroll
    for (int mi = 0; mi < 2; mi++) {
        int gm = m0 + wm*32 + mi*16 + gid;
#pragma unroll
        for (int nj = 0; nj < 4; nj++) {
            int gn = wn*32 + nj*8 + tig*2;
            if (gm < NN)
                *(__half2*)&d_hcat[((size_t)b*MP + gm)*128 + 64 + gn] =
                    __halves2half2(__float2half_rn(c[mi][nj][0]), __float2half_rn(c[mi][nj][1]));
            if (gm + 8 < NN)
                *(__half2*)&d_hcat[((size_t)b*MP + gm + 8)*128 + 64 + gn] =
                    __halves2half2(__float2half_rn(c[mi][nj][2]), __float2half_rn(c[mi][nj][3]));
        }
    }
}

// ---- K6b: xg = E @ hcat   (fp16 mma, tile 128x128) ---------------------------
#define XG_BROW 272
#define XG_BBUF (64*XG_BROW)               // 17408
#define XG_STAGE (ABUF + XG_BBUF)          // 35840
#define XG_SMEM (2*XG_STAGE)               // 71680

__global__ void __launch_bounds__(256) k_xgmma() {
    extern __shared__ __align__(16) char smem[];
    uint32_t sb = smem_u32(smem);
    int tid = threadIdx.x, lane = tid & 31, w = tid >> 5;
    int b = blockIdx.y;
    int m0 = blockIdx.x * 128;
    const __half* Ag = d_Ebf + ((size_t)b*MP + m0)*KSEG;
    const __half* Bg = d_hcat + (size_t)b*MP*128;

    auto issue = [&](int kc, int buf) {
        uint32_t sA = sb + buf*XG_STAGE;
        uint32_t sB = sA + ABUF;
#pragma unroll
        for (int l = 0; l < 4; l++) {
            int seg = tid + l*256;
            int row = seg >> 3, c = seg & 7;
            cp16(sA + row*AROW + c*16, Ag + (size_t)row*KSEG + kc*KCHUNK + c*8);
        }
#pragma unroll
        for (int l = 0; l < 4; l++) {
            int seg = tid + l*256;
            int row = seg >> 4, c = seg & 15;
            cp16(sB + row*XG_BROW + c*16, Bg + (size_t)(kc*KCHUNK + row)*128 + c*8);
        }
        CP_COMMIT();
    };

    issue(0, 0);
    issue(1, 1);

    float c[2][8][4];
#pragma unroll
    for (int mi = 0; mi < 2; mi++)
#pragma unroll
        for (int nj = 0; nj < 8; nj++)
#pragma unroll
            for (int q = 0; q < 4; q++) c[mi][nj][q] = 0.f;

    int wm = w >> 1, wn = w & 1;
    for (int kc = 0; kc < NCHUNK; kc++) {
        CP_WAIT1();
        __syncthreads();
        int buf = kc & 1;
        uint32_t sA = sb + buf*XG_STAGE + (wm*32 + (lane & 15))*AROW + (lane >> 4)*16;
        uint32_t sB = sb + buf*XG_STAGE + ABUF;
#pragma unroll
        for (int ks = 0; ks < 4; ks++) {
            uint32_t af[2][4], bf[8][2];
#pragma unroll
            for (int mi = 0; mi < 2; mi++)
                ldm_x4(af[mi], sA + mi*16*AROW + ks*32);
#pragma unroll
            for (int nj = 0; nj < 8; nj++)
                ldm_x2_t(bf[nj], sB + (ks*16 + (lane & 15))*XG_BROW + (wn*64 + nj*8)*2);
#pragma unroll
            for (int mi = 0; mi < 2; mi++)
#pragma unroll
                for (int nj = 0; nj < 8; nj++)
                    mma_f16(c[mi][nj], af[mi], bf[nj]);
        }
        __syncthreads();
        if (kc + 2 < NCHUNK) issue(kc + 2, buf);
        else CP_COMMIT();
    }

    int gid = lane >> 2, tig = lane & 3;
#pragma unroll
    for (int mi = 0; mi < 2; mi++) {
        int gm = m0 + wm*32 + mi*16 + gid;
#pragma unroll
        for (int nj = 0; nj < 8; nj++) {
            int gn = wn*64 + nj*8 + tig*2;
            if (gm < NN)
                *(float2*)&d_xg[((size_t)b*NN + gm)*128 + gn] = make_float2(c[mi][nj][0], c[mi][nj][1]);
            if (gm + 8 < NN)
                *(float2*)&d_xg[((size_t)b*NN + gm + 8)*128 + gn] = make_float2(c[mi][nj][2], c[mi][nj][3]);
        }
    }
}

// ---------------- K7: weights = emb @ wp_flat -> fp16 -------------------------
__global__ void k_wn(const float* __restrict__ emb, const float* __restrict__ wp) {
    __shared__ float Es[64][16];
    __shared__ float Ws[16][128];
    int n0 = blockIdx.y*64, c0 = blockIdx.x*128;
    int tid = threadIdx.x;
    for (int i=tid;i<1024;i+=256){ int r=i>>4, d=i&15; int n=n0+r; Es[r][d] = (n<NN)? emb[(size_t)n*16+d] : 0.f; }
    for (int i=tid;i<2048;i+=256){ int kr=i>>7, c=i&127; Ws[kr][c] = wp[(size_t)kr*8192 + c0 + c]; }
    __syncthreads();
    int ty=tid>>4, tx=tid&15;
    float acc[4][8];
#pragma unroll
    for (int i=0;i<4;i++)
#pragma unroll
        for (int j=0;j<8;j++) acc[i][j]=0.f;
#pragma unroll
    for (int d=0; d<16; d++){
        float ev[4], wv[8];
#pragma unroll
        for (int i=0;i<4;i++) ev[i]=Es[ty*4+i][d];
#pragma unroll
        for (int j=0;j<8;j++) wv[j]=Ws[d][tx*8+j];
#pragma unroll
        for (int i=0;i<4;i++)
#pragma unroll
            for (int j=0;j<8;j++) acc[i][j] += ev[i]*wv[j];
    }
#pragma unroll
    for (int i=0;i<4;i++){
        int n = n0+ty*4+i;
        if (n >= NN) continue;
#pragma unroll
        for (int j=0;j<8;j+=2)
            *(__half2*)&d_wn16[(size_t)n*8192 + c0 + tx*8 + j] =
                __floats2half2_rn(acc[i][j], acc[i][j+1]);
    }
}

// ---------------- K8: g = xg @ W_n + bias_n -> gcat fp16 [gh|gl|gh] -----------
__global__ void k_g(const float* __restrict__ emb, const float* __restrict__ bp) {
    __shared__ __align__(16) float Wns[8192];
    __shared__ float xgs[8][128];
    __shared__ float bias_s[64];
    __shared__ float es[16];
    int n = blockIdx.x, tid = threadIdx.x;
    if (tid < 16) es[tid] = emb[(size_t)n*16+tid];
    {
        const __half2* src = (const __half2*)(d_wn16 + (size_t)n*8192);
        for (int i=tid;i<4096;i+=256){
            float2 v = __half22float2(src[i]);
            *(float2*)&Wns[2*i] = v;
        }
    }
    for (int i=tid;i<1024;i+=256){
        int b=i>>7, ki=i&127;
        xgs[b][ki] = d_xg[((size_t)b*NN+n)*128 + ki];
    }
    __syncthreads();
    if (tid < 64) {
        float bv = 0.f;
#pragma unroll
        for (int d=0; d<16; d++) bv += es[d]*bp[d*64+tid];
        bias_s[tid] = bv;
    }
    __syncthreads();
    int o = tid & 63;
#pragma unroll
    for (int rep=0; rep<2; rep++){
        int b = (tid>>6) + rep*4;
        float acc = bias_s[o];
#pragma unroll 8
        for (int ki=0; ki<128; ki++) acc += xgs[b][ki]*Wns[ki*64+o];
        __half gh = __float2half_rn(acc);
        __half gl = __float2half_rn(acc - __half2float(gh));
        size_t base = ((size_t)b*NN + n)*192;
        d_gcat[base + o]       = gh;
        d_gcat[base + 64 + o]  = gl;
        d_gcat[base + 128 + o] = gh;
    }
}

// ---------------- K9a: WoutT = [Wh;Wh;Wl] fp16 --------------------------------
__global__ void k_wprep(const float* __restrict__ Wout) {
    int o = blockIdx.x*256 + threadIdx.x;
    int h = blockIdx.y;
    float w = Wout[(size_t)o*64 + h];
    __half wh = __float2half_rn(w);
    __half wl = __float2half_rn(w - __half2float(wh));
    d_WoutT[(size_t)h*OUTC + o]         = wh;
    d_WoutT[(size_t)(64+h)*OUTC + o]    = wh;
    d_WoutT[(size_t)(128+h)*OUTC + o]   = wl;
}

// ---------------- K9b: out = 0.1*tanh(gcat @ WoutT + b_out) -------------------
// B (WoutT slice) pinned in smem; 5 m-tiles streamed with double-buffered A.
#define MT 5
#define O_AROW 400
#define O_ABUF (128*O_AROW)    // 51200
#define O_BROW 272
#define O_BBUF (192*O_BROW)    // 52224
#define O_SMEM (O_BBUF + 2*O_ABUF + 512)   // 155136

__global__ void __launch_bounds__(256) k_outmma(const float* __restrict__ bout,
                                                float* __restrict__ out) {
    extern __shared__ __align__(16) char smem[];
    uint32_t sb = smem_u32(smem);
    float* boS = (float*)(smem + O_BBUF + 2*O_ABUF);
    int tid = threadIdx.x, lane = tid & 31, w = tid >> 5;
    int n0 = blockIdx.x * 128;
    int mg = blockIdx.y * MT;

    // B: 192 rows x 16 segs, resident for all MT tiles
#pragma unroll
    for (int l = 0; l < 12; l++) {
        int seg = tid + l*256;
        int row = seg >> 4, c = seg & 15;
        cp16(sb + row*O_BROW + c*16, d_WoutT + (size_t)row*OUTC + n0 + c*8);
    }
    CP_COMMIT();
    if (tid < 128) boS[tid] = bout[n0 + tid];

    auto issueA = [&](int i, int buf) {
        uint32_t sA = sb + O_BBUF + buf*O_ABUF;
        int m0 = (mg + i)*128;
#pragma unroll
        for (int l = 0; l < 12; l++) {
            int seg = tid + l*256;
            int row = seg / 24, c = seg % 24;
            cp16(sA + row*O_AROW + c*16, d_gcat + (size_t)(m0+row)*192 + c*8);
        }
        CP_COMMIT();
    };
    issueA(0, 0);

    int wm = w >> 1, wn = w & 1;      // warp tile 32x64
    int gid = lane >> 2, tig = lane & 3;

    for (int i = 0; i < MT; i++) {
        CP_WAIT0();
        __syncthreads();
        if (i + 1 < MT) issueA(i + 1, (i + 1) & 1);

        uint32_t sA = sb + O_BBUF + (i & 1)*O_ABUF + (wm*32 + (lane & 15))*O_AROW + (lane >> 4)*16;
        uint32_t sB = sb;
        float c[2][8][4];
#pragma unroll
        for (int mi = 0; mi < 2; mi++)
#pragma unroll
            for (int nj = 0; nj < 8; nj++)
#pragma unroll
                for (int q = 0; q < 4; q++) c[mi][nj][q] = 0.f;

#pragma unroll
        for (int kk = 0; kk < 12; kk++) {
            uint32_t af[2][4], bf[8][2];
#pragma unroll
            for (int mi = 0; mi < 2; mi++)
                ldm_x4(af[mi], sA + mi*16*O_AROW + kk*32);
#pragma unroll
            for (int nj = 0; nj < 8; nj++)
                ldm_x2_t(bf[nj], sB + (kk*16 + (lane & 15))*O_BROW + (wn*64 + nj*8)*2);
#pragma unroll
            for (int mi = 0; mi < 2; mi++)
#pragma unroll
                for (int nj = 0; nj < 8; nj++)
                    mma_f16(c[mi][nj], af[mi], bf[nj]);
        }

        int m0 = (mg + i)*128;
#pragma unroll
        for (int mi = 0; mi < 2; mi++) {
            int gm = m0 + wm*32 + mi*16 + gid;
#pragma unroll
            for (int nj = 0; nj < 8; nj++) {
                int cn = wn*64 + nj*8 + tig*2;
                int gn = n0 + cn;
                float b0 = boS[cn], b1 = boS[cn+1];
                float2 v0 = make_float2(0.1f*tanhf(c[mi][nj][0] + b0), 0.1f*tanhf(c[mi][nj][1] + b1));
                float2 v1 = make_float2(0.1f*tanhf(c[mi][nj][2] + b0), 0.1f*tanhf(c[mi][nj][3] + b1));
                *(float2*)&out[(size_t)gm*OUTC + gn]       = v0;
                *(float2*)&out[(size_t)(gm+8)*OUTC + gn]   = v1;
            }
        }
        __syncthreads();   // all warps done with A buf before it is refilled
    }
}

// ---------------- launch ------------------------------------------------------
extern "C" void kernel_launch(void* const* d_in, const int* in_sizes, int n_in,
                              void* d_out, int out_size) {
    const float* z    = (const float*)d_in[0];
    const float* Win  = (const float*)d_in[1];
    const float* bin  = (const float*)d_in[2];
    const float* Wout = (const float*)d_in[3];
    const float* bout = (const float*)d_in[4];
    const float* emb  = (const float*)d_in[5];
    const float* wp   = (const float*)d_in[6];
    const float* bp   = (const float*)d_in[7];
    const float* w1   = (const float*)d_in[8];
    const float* w2   = (const float*)d_in[9];
    const float* vsM  = (const float*)d_in[10];
    const float* bs   = (const float*)d_in[11];
    float* out = (float*)d_out;
    (void)in_sizes; (void)n_in; (void)out_size;

    cudaFuncSetAttribute(k_mma,    cudaFuncAttributeMaxDynamicSharedMemorySize, SMEM_MMA);
    cudaFuncSetAttribute(k_Ahmma,  cudaFuncAttributeMaxDynamicSharedMemorySize, AH_SMEM);
    cudaFuncSetAttribute(k_xgmma,  cudaFuncAttributeMaxDynamicSharedMemorySize, XG_SMEM);
    cudaFuncSetAttribute(k_outmma, cudaFuncAttributeMaxDynamicSharedMemorySize, O_SMEM);

    k_hidden<<<(NB*NN)/16, 256>>>(z, Win, bin, w1, w2);
    k_adj<<<NN, 256>>>(emb);
    k_Avs<<<dim3(MP/256, MP), 256>>>(vsM);
    k_T2<<<dim3(NP/32, NP/32), 256>>>(bs);
    k_wprep<<<dim3(OUTC/256, 64), 256>>>(Wout);
    k_mma<<<dim3(NP/256, MP/128, NB), 256, SMEM_MMA>>>();

    __half* dLptr = nullptr;
    cudaGetSymbolAddress((void**)&dLptr, d_L16);
    k_softmax<<<NB*NN, 256>>>(dLptr);

    k_Ahmma<<<dim3(MP/128, NB), 256, AH_SMEM>>>();
    k_xgmma<<<dim3(MP/128, NB), 256, XG_SMEM>>>();
    k_wn<<<dim3(8192/128, (NN+63)/64), 256>>>(emb, wp);
    k_g<<<NN, 256>>>(emb, bp);
    k_outmma<<<dim3(OUTC/128, (NB*NN)/(128*MT)), 256, O_SMEM>>>(bout, out);
}

// round 8
// speedup vs baseline: 4.8858x; 1.0915x over previous
#include <cuda_runtime.h>
#include <cuda_fp16.h>
#include <math.h>
#include <stdint.h>

#define NB 8
#define NN 2000
#define HH 64
#define DD 16
#define OUTC 4096

// padded GEMM dims
#define MP 2048
#define NP 2048
#define KSEG 2048            // K for the big GEMM (T_hi only)
#define KCHUNK 64
#define NCHUNK (KSEG/KCHUNK) // 32

// ---------------- scratch (static __device__ — zero-initialized) --------------
__device__ float d_e1 [NB*NN];
__device__ float d_e2 [NB*NN];
__device__ __align__(16) float d_xg [(size_t)NB*NN*128];  // [b][node][128] fp32
__device__ float d_wn [(size_t)NN*128*HH];                // fp32 (accuracy-critical)
__device__ float d_psum[(size_t)NB*8*MP];                 // per-(batch,nblk,row) exp sums
// fp16 operands (pads never written -> stay zero from module init)
__device__ __align__(16) __half d_Abf  [(size_t)MP*KSEG];        // fp16(vs)
__device__ __align__(16) __half d_Bbf  [(size_t)NB*NP*KSEG];     // T_hi, [b][n][k]
__device__ __align__(16) __half d_Ebf  [(size_t)NB*MP*KSEG];     // exp(L) unnormalized
__device__ __align__(16) __half d_Adjbf[(size_t)MP*KSEG];        // fp16(A adj), [m][k]
__device__ __align__(16) __half d_hcat [(size_t)NB*MP*128];      // [b][node][0:64=h,64:128=Ah]
__device__ __align__(16) __half d_gcat [(size_t)NB*NN*192];      // [m][gh|gl|gh]
__device__ __align__(16) __half d_WoutT[(size_t)192*OUTC];       // [Wh;Wh;Wl] rows k, cols o

// ======================= portable PTX helpers (base sm_103 OK) ================
__device__ __forceinline__ uint32_t smem_u32(const void* p) {
    uint32_t a;
    asm("{ .reg .u64 t; cvta.to.shared.u64 t, %1; cvt.u32.u64 %0, t; }" : "=r"(a) : "l"(p));
    return a;
}
__device__ __forceinline__ void cp16(uint32_t s, const void* g) {
    asm volatile("cp.async.cg.shared.global [%0], [%1], 16;" :: "r"(s), "l"(g));
}
#define CP_COMMIT() asm volatile("cp.async.commit_group;" ::: "memory")
#define CP_WAIT1()  asm volatile("cp.async.wait_group 1;" ::: "memory")
#define CP_WAIT2()  asm volatile("cp.async.wait_group 2;" ::: "memory")
#define CP_WAIT0()  asm volatile("cp.async.wait_group 0;" ::: "memory")
__device__ __forceinline__ void ldm_x4(uint32_t* r, uint32_t addr) {
    asm volatile("ldmatrix.sync.aligned.m8n8.x4.shared.b16 {%0,%1,%2,%3}, [%4];"
        : "=r"(r[0]), "=r"(r[1]), "=r"(r[2]), "=r"(r[3]) : "r"(addr));
}
__device__ __forceinline__ void ldm_x2(uint32_t* r, uint32_t addr) {
    asm volatile("ldmatrix.sync.aligned.m8n8.x2.shared.b16 {%0,%1}, [%2];"
        : "=r"(r[0]), "=r"(r[1]) : "r"(addr));
}
__device__ __forceinline__ void ldm_x2_t(uint32_t* r, uint32_t addr) {
    asm volatile("ldmatrix.sync.aligned.m8n8.x2.trans.shared.b16 {%0,%1}, [%2];"
        : "=r"(r[0]), "=r"(r[1]) : "r"(addr));
}
__device__ __forceinline__ void mma_f16(float* c, const uint32_t* a, const uint32_t* b) {
    asm volatile(
        "mma.sync.aligned.m16n8k16.row.col.f32.f16.f16.f32 "
        "{%0,%1,%2,%3}, {%4,%5,%6,%7}, {%8,%9}, {%0,%1,%2,%3};"
        : "+f"(c[0]), "+f"(c[1]), "+f"(c[2]), "+f"(c[3])
        : "r"(a[0]), "r"(a[1]), "r"(a[2]), "r"(a[3]), "r"(b[0]), "r"(b[1]));
}

// ---------------- K1: h = relu(z@W_in^T + b_in) -> hcat[:,0:64] fp16 ----------
__global__ void __launch_bounds__(256) k_hidden(const float* __restrict__ z,
                         const float* __restrict__ Win,
                         const float* __restrict__ bin, const float* __restrict__ w1,
                         const float* __restrict__ w2) {
    __shared__ float Ws[4096];        // transposed: Ws[c*64+h]
    __shared__ float zs[4][64];
    __shared__ float red1[4][2], red2[4][2];
    __shared__ float binS[64], w1S[64], w2S[64];
    int tid = threadIdx.x;
    for (int i = tid; i < 4096; i += 256) {
        int h = i >> 6, c = i & 63;
        Ws[c*64 + h] = Win[i];
    }
    if (tid < 64) { binS[tid] = bin[tid]; w1S[tid] = w1[tid]; w2S[tid] = w2[tid]; }
    __syncthreads();
    int slice = tid >> 6, o = tid & 63;
    int wihalf = (tid >> 5) & 1;
#pragma unroll 1
    for (int it = 0; it < 4; it++) {
        int row = blockIdx.x*16 + it*4 + slice;
        zs[slice][o] = z[(size_t)row*64 + o];
        __syncthreads();
        float acc = binS[o];
#pragma unroll 16
        for (int c = 0; c < 64; c++) acc += zs[slice][c] * Ws[c*64 + o];
        float hv = fmaxf(acc, 0.f);
        int b = row / NN, node = row % NN;
        d_hcat[((size_t)b*MP + node)*128 + o] = __float2half_rn(hv);
        float p1 = hv * w1S[o], p2 = hv * w2S[o];
#pragma unroll
        for (int s = 16; s > 0; s >>= 1) {
            p1 += __shfl_down_sync(0xffffffffu, p1, s);
            p2 += __shfl_down_sync(0xffffffffu, p2, s);
        }
        if ((tid & 31) == 0) { red1[slice][wihalf] = p1; red2[slice][wihalf] = p2; }
        __syncthreads();
        if (o == 0) {
            d_e1[row] = red1[slice][0] + red1[slice][1];
            d_e2[row] = red2[slice][0] + red2[slice][1];
        }
    }
}

// ---------------- K2: Adj = softmax(relu(emb@emb^T)) -> fp16 ------------------
__global__ void k_adj(const float* __restrict__ emb) {
    __shared__ float buf[NN];
    __shared__ float red[256];
    __shared__ float ei[16];
    int i = blockIdx.x, tid = threadIdx.x;
    if (tid < 16) ei[tid] = emb[i*16 + tid];
    __syncthreads();
    float mx = -1e30f;
    for (int j = tid; j < NN; j += 256) {
        const float* er = emb + (size_t)j*16;
        float dsum = 0.f;
#pragma unroll
        for (int d = 0; d < 16; d++) dsum += ei[d]*er[d];
        dsum = fmaxf(dsum, 0.f);
        buf[j] = dsum;
        mx = fmaxf(mx, dsum);
    }
    red[tid] = mx; __syncthreads();
    for (int s = 128; s > 0; s >>= 1) { if (tid < s) red[tid] = fmaxf(red[tid], red[tid+s]); __syncthreads(); }
    mx = red[0]; __syncthreads();
    float sum = 0.f;
    for (int j = tid; j < NN; j += 256) { float v = __expf(buf[j]-mx); buf[j] = v; sum += v; }
    red[tid] = sum; __syncthreads();
    for (int s = 128; s > 0; s >>= 1) { if (tid < s) red[tid] += red[tid+s]; __syncthreads(); }
    float inv = 1.f/red[0];
    for (int j = tid; j < NN; j += 256)
        d_Adjbf[(size_t)i*KSEG + j] = __float2half_rn(buf[j]*inv);
}

// ---- K3a: A = fp16(vs) -------------------------------------------------------
__global__ void k_Avs(const float* __restrict__ vsM) {
    int k = blockIdx.x*256 + threadIdx.x;
    int m = blockIdx.y;
    float t = (m < NN && k < NN) ? vsM[(size_t)m*NN + k] : 0.f;
    d_Abf[(size_t)m*KSEG + k] = __float2half_rn(t);
}

// ---- K3b: B[b][n][k] = fp16(sigmoid(e1[b,k]*e2[b,n] + bs[k,n])) --------------
__global__ void k_T2(const float* __restrict__ bs) {
    __shared__ float sbs[32][33];
    int k0 = blockIdx.x*32, n0 = blockIdx.y*32;
    int tid = threadIdx.x;
#pragma unroll
    for (int l = 0; l < 4; l++) {
        int kk = (tid >> 5) + l*8, nn = tid & 31;
        int gk = k0 + kk, gn = n0 + nn;
        sbs[kk][nn] = (gk < NN && gn < NN) ? bs[(size_t)gk*NN + gn] : 0.f;
    }
    __syncthreads();
    int nnl = tid >> 4;
    int kl  = (tid & 15) * 2;
#pragma unroll
    for (int half = 0; half < 2; half++) {
        int nn = nnl + half*16;
        int gn = n0 + nn;
        bool nok = gn < NN;
        int gk0 = k0 + kl, gk1 = gk0 + 1;
        float b0 = sbs[kl][nn], b1 = sbs[kl+1][nn];
#pragma unroll
        for (int b = 0; b < NB; b++) {
            float v0 = 0.f, v1 = 0.f;
            if (nok) {
                float e2v = d_e2[b*NN + gn];
                if (gk0 < NN) { float x = d_e1[b*NN + gk0]*e2v + b0; v0 = 1.f/(1.f + __expf(-x)); }
                if (gk1 < NN) { float x = d_e1[b*NN + gk1]*e2v + b1; v1 = 1.f/(1.f + __expf(-x)); }
            }
            size_t base = ((size_t)b*NP + gn)*KSEG + gk0;
            *(__half2*)&d_Bbf[base] = __halves2half2(__float2half_rn(v0), __float2half_rn(v1));
        }
    }
}

// ---- K4: L[b]=A@B^T; epilogue: exp(L) -> d_Ebf fp16 + per-row partial sums ----
// 4-stage pipeline, single barrier per chunk.
#define AROW 144
#define ABUF 18432
#define BBUF 36864
#define STAGE (ABUF + BBUF)            // 55296
#define SMEM_MMA (4*STAGE)             // 221184

__global__ void __launch_bounds__(256, 1) k_mma() {
    extern __shared__ __align__(16) char smem[];
    __shared__ float rs[128][4];
    uint32_t sb = smem_u32(smem);
    int tid = threadIdx.x, lane = tid & 31, w = tid >> 5;
    int b  = blockIdx.z;
    int m0 = blockIdx.y * 128;
    int n0 = blockIdx.x * 256;
    const __half* Ag = d_Abf + (size_t)m0*KSEG;
    const __half* Bg = d_Bbf + ((size_t)b*NP + n0)*KSEG;

    auto issue = [&](int kc, int buf) {
        uint32_t sA = sb + buf*STAGE;
        uint32_t sB = sA + ABUF;
        int ka = kc * KCHUNK;
#pragma unroll
        for (int l = 0; l < 4; l++) {
            int seg = tid + l*256;
            int row = seg >> 3, c = seg & 7;
            cp16(sA + row*AROW + c*16, Ag + (size_t)row*KSEG + ka + c*8);
        }
#pragma unroll
        for (int l = 0; l < 8; l++) {
            int seg = tid + l*256;
            int row = seg >> 3, c = seg & 7;
            cp16(sB + row*AROW + c*16, Bg + (size_t)row*KSEG + ka + c*8);
        }
        CP_COMMIT();
    };

    issue(0, 0);
    issue(1, 1);
    issue(2, 2);

    float c[4][8][4];
#pragma unroll
    for (int mi = 0; mi < 4; mi++)
#pragma unroll
        for (int nj = 0; nj < 8; nj++)
#pragma unroll
            for (int q = 0; q < 4; q++) c[mi][nj][q] = 0.f;

    int wm = w & 1, wn = w >> 1;
    int a_row = (lane & 15), a_kh = (lane >> 4) * 16;
    int b_off = ((lane & 7) + ((lane >> 4) & 1)*8)*AROW + ((lane >> 3) & 1)*16;

    int buf = 0;
    for (int kc = 0; kc < NCHUNK; kc++) {
        CP_WAIT2();
        __syncthreads();
        uint32_t sA = sb + buf*STAGE          + (wm*64 + a_row)*AROW + a_kh;
        uint32_t sB = sb + buf*STAGE + ABUF   + (wn*64)*AROW + b_off;
#pragma unroll
        for (int ks = 0; ks < 4; ks++) {
            uint32_t af[4][4], bf[8][2];
#pragma unroll
            for (int mi = 0; mi < 4; mi++)
                ldm_x4(af[mi], sA + mi*16*AROW + ks*32);
#pragma unroll
            for (int j = 0; j < 4; j++) {
                uint32_t q[4];
                ldm_x4(q, sB + j*16*AROW + ks*32);
                bf[2*j][0] = q[0]; bf[2*j][1] = q[1];
                bf[2*j+1][0] = q[2]; bf[2*j+1][1] = q[3];
            }
#pragma unroll
            for (int mi = 0; mi < 4; mi++)
#pragma unroll
                for (int nj = 0; nj < 8; nj++)
                    mma_f16(c[mi][nj], af[mi], bf[nj]);
        }
        if (kc + 3 < NCHUNK) issue(kc + 3, (kc + 3) & 3);
        else CP_COMMIT();
        buf = (buf + 1) & 3;
        // no trailing barrier: 4 stages guarantee the refilled buffer was
        // consumed an iteration ago, and the top-of-loop barrier orders it.
    }

    // epilogue: exp + store unnormalized E + deterministic row partial sums
    __half* Eb = d_Ebf + (size_t)b*MP*KSEG;
    int gid = lane >> 2, tig = lane & 3;
#pragma unroll
    for (int mi = 0; mi < 4; mi++) {
        int gm = m0 + wm*64 + mi*16 + gid;
        float s0 = 0.f, s1 = 0.f;
#pragma unroll
        for (int nj = 0; nj < 8; nj++) {
            int gn = n0 + wn*64 + nj*8 + tig*2;
            bool nok = gn < NN;          // NN even => gn<NN implies gn+1<NN
            float e0 = nok ? __expf(c[mi][nj][0]) : 0.f;
            float e1 = nok ? __expf(c[mi][nj][1]) : 0.f;
            float e2 = nok ? __expf(c[mi][nj][2]) : 0.f;
            float e3 = nok ? __expf(c[mi][nj][3]) : 0.f;
            s0 += e0 + e1;
            s1 += e2 + e3;
            if (nok) {
                if (gm < NN)
                    *(__half2*)&Eb[(size_t)gm*KSEG + gn]     = __floats2half2_rn(e0, e1);
                if (gm + 8 < NN)
                    *(__half2*)&Eb[(size_t)(gm+8)*KSEG + gn] = __floats2half2_rn(e2, e3);
            }
        }
        s0 += __shfl_xor_sync(0xffffffffu, s0, 1);
        s0 += __shfl_xor_sync(0xffffffffu, s0, 2);
        s1 += __shfl_xor_sync(0xffffffffu, s1, 1);
        s1 += __shfl_xor_sync(0xffffffffu, s1, 2);
        if (tig == 0) {
            rs[wm*64 + mi*16 + gid][wn]     = s0;
            rs[wm*64 + mi*16 + gid + 8][wn] = s1;
        }
    }
    __syncthreads();
    if (tid < 128) {
        float tot = (rs[tid][0] + rs[tid][1]) + (rs[tid][2] + rs[tid][3]);
        d_psum[((size_t)b*8 + blockIdx.x)*MP + m0 + tid] = tot;
    }
}

// ---- K6a: hcat[:,64:128] = Adj @ h   (fp16 mma, tile 128x64) -----------------
#define AH_BROW 144
#define AH_BBUF (64*AH_BROW)               // 9216
#define AH_STAGE (ABUF + AH_BBUF)          // 27648
#define AH_SMEM (2*AH_STAGE)               // 55296

__global__ void __launch_bounds__(256) k_Ahmma() {
    extern __shared__ __align__(16) char smem[];
    uint32_t sb = smem_u32(smem);
    int tid = threadIdx.x, lane = tid & 31, w = tid >> 5;
    int b = blockIdx.y;
    int m0 = blockIdx.x * 128;
    const __half* Ag = d_Adjbf + (size_t)m0*KSEG;
    const __half* Bg = d_hcat + (size_t)b*MP*128;

    auto issue = [&](int kc, int buf) {
        uint32_t sA = sb + buf*AH_STAGE;
        uint32_t sB = sA + ABUF;
#pragma unroll
        for (int l = 0; l < 4; l++) {
            int seg = tid + l*256;
            int row = seg >> 3, c = seg & 7;
            cp16(sA + row*AROW + c*16, Ag + (size_t)row*KSEG + kc*KCHUNK + c*8);
        }
#pragma unroll
        for (int l = 0; l < 2; l++) {
            int seg = tid + l*256;
            int row = seg >> 3, c = seg & 7;
            cp16(sB + row*AH_BROW + c*16, Bg + (size_t)(kc*KCHUNK + row)*128 + c*8);
        }
        CP_COMMIT();
    };

    issue(0, 0);
    issue(1, 1);

    float c[2][4][4];
#pragma unroll
    for (int mi = 0; mi < 2; mi++)
#pragma unroll
        for (int nj = 0; nj < 4; nj++)
#pragma unroll
            for (int q = 0; q < 4; q++) c[mi][nj][q] = 0.f;

    int wm = w >> 1, wn = w & 1;
    for (int kc = 0; kc < NCHUNK; kc++) {
        CP_WAIT1();
        __syncthreads();
        int buf = kc & 1;
        uint32_t sA = sb + buf*AH_STAGE + (wm*32 + (lane & 15))*AROW + (lane >> 4)*16;
        uint32_t sB = sb + buf*AH_STAGE + ABUF;
#pragma unroll
        for (int ks = 0; ks < 4; ks++) {
            uint32_t af[2][4], bf[4][2];
#pragma unroll
            for (int mi = 0; mi < 2; mi++)
                ldm_x4(af[mi], sA + mi*16*AROW + ks*32);
#pragma unroll
            for (int nj = 0; nj < 4; nj++)
                ldm_x2_t(bf[nj], sB + (ks*16 + (lane & 15))*AH_BROW + (wn*32 + nj*8)*2);
#pragma unroll
            for (int mi = 0; mi < 2; mi++)
#pragma unroll
                for (int nj = 0; nj < 4; nj++)
                    mma_f16(c[mi][nj], af[mi], bf[nj]);
        }
        __syncthreads();
        if (kc + 2 < NCHUNK) issue(kc + 2, buf);
        else CP_COMMIT();
    }

    int gid = lane >> 2, tig = lane & 3;
#pragma unroll
    for (int mi = 0; mi < 2; mi++) {
        int gm = m0 + wm*32 + mi*16 + gid;
#pragma unroll
        for (int nj = 0; nj < 4; nj++) {
            int gn = wn*32 + nj*8 + tig*2;
            if (gm < NN)
                *(__half2*)&d_hcat[((size_t)b*MP + gm)*128 + 64 + gn] =
                    __halves2half2(__float2half_rn(c[mi][nj][0]), __float2half_rn(c[mi][nj][1]));
            if (gm + 8 < NN)
                *(__half2*)&d_hcat[((size_t)b*MP + gm + 8)*128 + 64 + gn] =
                    __halves2half2(__float2half_rn(c[mi][nj][2]), __float2half_rn(c[mi][nj][3]));
        }
    }
}

// ---- K6b: xg = softmax-normalized E @ hcat  (fp16 mma, tile 128x128) ---------
#define XG_BROW 272
#define XG_BBUF (64*XG_BROW)               // 17408
#define XG_STAGE (ABUF + XG_BBUF)          // 35840
#define XG_SMEM (2*XG_STAGE)               // 71680

__global__ void __launch_bounds__(256) k_xgmma() {
    extern __shared__ __align__(16) char smem[];
    __shared__ float invS[128];
    uint32_t sb = smem_u32(smem);
    int tid = threadIdx.x, lane = tid & 31, w = tid >> 5;
    int b = blockIdx.y;
    int m0 = blockIdx.x * 128;
    const __half* Ag = d_Ebf + ((size_t)b*MP + m0)*KSEG;
    const __half* Bg = d_hcat + (size_t)b*MP*128;

    auto issue = [&](int kc, int buf) {
        uint32_t sA = sb + buf*XG_STAGE;
        uint32_t sB = sA + ABUF;
#pragma unroll
        for (int l = 0; l < 4; l++) {
            int seg = tid + l*256;
            int row = seg >> 3, c = seg & 7;
            cp16(sA + row*AROW + c*16, Ag + (size_t)row*KSEG + kc*KCHUNK + c*8);
        }
#pragma unroll
        for (int l = 0; l < 4; l++) {
            int seg = tid + l*256;
            int row = seg >> 4, c = seg & 15;
            cp16(sB + row*XG_BROW + c*16, Bg + (size_t)(kc*KCHUNK + row)*128 + c*8);
        }
        CP_COMMIT();
    };

    issue(0, 0);
    issue(1, 1);

    // inverse row sums (fixed summation order -> deterministic)
    if (tid < 128) {
        float s = 0.f;
#pragma unroll
        for (int nb = 0; nb < 8; nb++)
            s += d_psum[((size_t)b*8 + nb)*MP + m0 + tid];
        invS[tid] = 1.f / s;   // pad rows: 1/0=inf, never stored
    }

    float c[2][8][4];
#pragma unroll
    for (int mi = 0; mi < 2; mi++)
#pragma unroll
        for (int nj = 0; nj < 8; nj++)
#pragma unroll
            for (int q = 0; q < 4; q++) c[mi][nj][q] = 0.f;

    int wm = w >> 1, wn = w & 1;
    for (int kc = 0; kc < NCHUNK; kc++) {
        CP_WAIT1();
        __syncthreads();
        int buf = kc & 1;
        uint32_t sA = sb + buf*XG_STAGE + (wm*32 + (lane & 15))*AROW + (lane >> 4)*16;
        uint32_t sB = sb + buf*XG_STAGE + ABUF;
#pragma unroll
        for (int ks = 0; ks < 4; ks++) {
            uint32_t af[2][4], bf[8][2];
#pragma unroll
            for (int mi = 0; mi < 2; mi++)
                ldm_x4(af[mi], sA + mi*16*AROW + ks*32);
#pragma unroll
            for (int nj = 0; nj < 8; nj++)
                ldm_x2_t(bf[nj], sB + (ks*16 + (lane & 15))*XG_BROW + (wn*64 + nj*8)*2);
#pragma unroll
            for (int mi = 0; mi < 2; mi++)
#pragma unroll
                for (int nj = 0; nj < 8; nj++)
                    mma_f16(c[mi][nj], af[mi], bf[nj]);
        }
        __syncthreads();
        if (kc + 2 < NCHUNK) issue(kc + 2, buf);
        else CP_COMMIT();
    }

    int gid = lane >> 2, tig = lane & 3;
#pragma unroll
    for (int mi = 0; mi < 2; mi++) {
        int lr = wm*32 + mi*16 + gid;
        int gm = m0 + lr;
        float inv0 = invS[lr], inv1 = invS[lr + 8];
#pragma unroll
        for (int nj = 0; nj < 8; nj++) {
            int gn = wn*64 + nj*8 + tig*2;
            if (gm < NN)
                *(float2*)&d_xg[((size_t)b*NN + gm)*128 + gn] =
                    make_float2(c[mi][nj][0]*inv0, c[mi][nj][1]*inv0);
            if (gm + 8 < NN)
                *(float2*)&d_xg[((size_t)b*NN + gm + 8)*128 + gn] =
                    make_float2(c[mi][nj][2]*inv1, c[mi][nj][3]*inv1);
        }
    }
}

// ---------------- K7: weights = emb @ wp_flat (fp32) --------------------------
__global__ void k_wn(const float* __restrict__ emb, const float* __restrict__ wp) {
    __shared__ float Es[64][16];
    __shared__ float Ws[16][128];
    int n0 = blockIdx.y*64, c0 = blockIdx.x*128;
    int tid = threadIdx.x;
    for (int i=tid;i<1024;i+=256){ int r=i>>4, d=i&15; int n=n0+r; Es[r][d] = (n<NN)? emb[(size_t)n*16+d] : 0.f; }
    for (int i=tid;i<2048;i+=256){ int kr=i>>7, c=i&127; Ws[kr][c] = wp[(size_t)kr*8192 + c0 + c]; }
    __syncthreads();
    int ty=tid>>4, tx=tid&15;
    float acc[4][8];
#pragma unroll
    for (int i=0;i<4;i++)
#pragma unroll
        for (int j=0;j<8;j++) acc[i][j]=0.f;
#pragma unroll
    for (int d=0; d<16; d++){
        float ev[4], wv[8];
#pragma unroll
        for (int i=0;i<4;i++) ev[i]=Es[ty*4+i][d];
#pragma unroll
        for (int j=0;j<8;j++) wv[j]=Ws[d][tx*8+j];
#pragma unroll
        for (int i=0;i<4;i++)
#pragma unroll
            for (int j=0;j<8;j++) acc[i][j] += ev[i]*wv[j];
    }
#pragma unroll
    for (int i=0;i<4;i++){
        int n = n0+ty*4+i;
        if (n >= NN) continue;
#pragma unroll
        for (int j=0;j<8;j++)
            d_wn[(size_t)n*8192 + c0 + tx*8 + j] = acc[i][j];
    }
}

// ---------------- K8: g = xg @ W_n + bias_n -> gcat fp16 [gh|gl|gh] -----------
__global__ void k_g(const float* __restrict__ emb, const float* __restrict__ bp) {
    __shared__ float Wns[8192];
    __shared__ float xgs[8][128];
    __shared__ float bias_s[64];
    __shared__ float es[16];
    int n = blockIdx.x, tid = threadIdx.x;
    if (tid < 16) es[tid] = emb[(size_t)n*16+tid];
    for (int i=tid;i<8192;i+=256) Wns[i] = d_wn[(size_t)n*8192 + i];
    for (int i=tid;i<1024;i+=256){
        int b=i>>7, ki=i&127;
        xgs[b][ki] = d_xg[((size_t)b*NN+n)*128 + ki];
    }
    __syncthreads();
    if (tid < 64) {
        float bv = 0.f;
#pragma unroll
        for (int d=0; d<16; d++) bv += es[d]*bp[d*64+tid];
        bias_s[tid] = bv;
    }
    __syncthreads();
    int o = tid & 63;
#pragma unroll
    for (int rep=0; rep<2; rep++){
        int b = (tid>>6) + rep*4;
        float acc = bias_s[o];
#pragma unroll 8
        for (int ki=0; ki<128; ki++) acc += xgs[b][ki]*Wns[ki*64+o];
        __half gh = __float2half_rn(acc);
        __half gl = __float2half_rn(acc - __half2float(gh));
        size_t base = ((size_t)b*NN + n)*192;
        d_gcat[base + o]       = gh;
        d_gcat[base + 64 + o]  = gl;
        d_gcat[base + 128 + o] = gh;
    }
}

// ---------------- K9a: WoutT = [Wh;Wh;Wl] fp16 --------------------------------
__global__ void k_wprep(const float* __restrict__ Wout) {
    int o = blockIdx.x*256 + threadIdx.x;
    int h = blockIdx.y;
    float w = Wout[(size_t)o*64 + h];
    __half wh = __float2half_rn(w);
    __half wl = __float2half_rn(w - __half2float(wh));
    d_WoutT[(size_t)h*OUTC + o]         = wh;
    d_WoutT[(size_t)(64+h)*OUTC + o]    = wh;
    d_WoutT[(size_t)(128+h)*OUTC + o]   = wl;
}

// ---------------- K9b: out = 0.1*tanh(gcat @ WoutT + b_out) -------------------
#define MT 5
#define O_AROW 400
#define O_ABUF (128*O_AROW)    // 51200
#define O_BROW 272
#define O_BBUF (192*O_BROW)    // 52224
#define O_SMEM (O_BBUF + 2*O_ABUF + 512)   // 155136

__global__ void __launch_bounds__(256) k_outmma(const float* __restrict__ bout,
                                                float* __restrict__ out) {
    extern __shared__ __align__(16) char smem[];
    uint32_t sb = smem_u32(smem);
    float* boS = (float*)(smem + O_BBUF + 2*O_ABUF);
    int tid = threadIdx.x, lane = tid & 31, w = tid >> 5;
    int n0 = blockIdx.x * 128;
    int mg = blockIdx.y * MT;

#pragma unroll
    for (int l = 0; l < 12; l++) {
        int seg = tid + l*256;
        int row = seg >> 4, c = seg & 15;
        cp16(sb + row*O_BROW + c*16, d_WoutT + (size_t)row*OUTC + n0 + c*8);
    }
    CP_COMMIT();
    if (tid < 128) boS[tid] = bout[n0 + tid];

    auto issueA = [&](int i, int buf) {
        uint32_t sA = sb + O_BBUF + buf*O_ABUF;
        int m0 = (mg + i)*128;
#pragma unroll
        for (int l = 0; l < 12; l++) {
            int seg = tid + l*256;
            int row = seg / 24, c = seg % 24;
            cp16(sA + row*O_AROW + c*16, d_gcat + (size_t)(m0+row)*192 + c*8);
        }
        CP_COMMIT();
    };
    issueA(0, 0);

    int wm = w >> 1, wn = w & 1;
    int gid = lane >> 2, tig = lane & 3;

    for (int i = 0; i < MT; i++) {
        CP_WAIT0();
        __syncthreads();
        if (i + 1 < MT) issueA(i + 1, (i + 1) & 1);

        uint32_t sA = sb + O_BBUF + (i & 1)*O_ABUF + (wm*32 + (lane & 15))*O_AROW + (lane >> 4)*16;
        uint32_t sB = sb;
        float c[2][8][4];
#pragma unroll
        for (int mi = 0; mi < 2; mi++)
#pragma unroll
            for (int nj = 0; nj < 8; nj++)
#pragma unroll
                for (int q = 0; q < 4; q++) c[mi][nj][q] = 0.f;

#pragma unroll
        for (int kk = 0; kk < 12; kk++) {
            uint32_t af[2][4], bf[8][2];
#pragma unroll
            for (int mi = 0; mi < 2; mi++)
                ldm_x4(af[mi], sA + mi*16*O_AROW + kk*32);
#pragma unroll
            for (int nj = 0; nj < 8; nj++)
                ldm_x2_t(bf[nj], sB + (kk*16 + (lane & 15))*O_BROW + (wn*64 + nj*8)*2);
#pragma unroll
            for (int mi = 0; mi < 2; mi++)
#pragma unroll
                for (int nj = 0; nj < 8; nj++)
                    mma_f16(c[mi][nj], af[mi], bf[nj]);
        }

        int m0 = (mg + i)*128;
#pragma unroll
        for (int mi = 0; mi < 2; mi++) {
            int gm = m0 + wm*32 + mi*16 + gid;
#pragma unroll
            for (int nj = 0; nj < 8; nj++) {
                int cn = wn*64 + nj*8 + tig*2;
                int gn = n0 + cn;
                float b0 = boS[cn], b1 = boS[cn+1];
                float2 v0 = make_float2(0.1f*tanhf(c[mi][nj][0] + b0), 0.1f*tanhf(c[mi][nj][1] + b1));
                float2 v1 = make_float2(0.1f*tanhf(c[mi][nj][2] + b0), 0.1f*tanhf(c[mi][nj][3] + b1));
                *(float2*)&out[(size_t)gm*OUTC + gn]       = v0;
                *(float2*)&out[(size_t)(gm+8)*OUTC + gn]   = v1;
            }
        }
        __syncthreads();
    }
}

// ---------------- launch ------------------------------------------------------
extern "C" void kernel_launch(void* const* d_in, const int* in_sizes, int n_in,
                              void* d_out, int out_size) {
    const float* z    = (const float*)d_in[0];
    const float* Win  = (const float*)d_in[1];
    const float* bin  = (const float*)d_in[2];
    const float* Wout = (const float*)d_in[3];
    const float* bout = (const float*)d_in[4];
    const float* emb  = (const float*)d_in[5];
    const float* wp   = (const float*)d_in[6];
    const float* bp   = (const float*)d_in[7];
    const float* w1   = (const float*)d_in[8];
    const float* w2   = (const float*)d_in[9];
    const float* vsM  = (const float*)d_in[10];
    const float* bs   = (const float*)d_in[11];
    float* out = (float*)d_out;
    (void)in_sizes; (void)n_in; (void)out_size;

    cudaFuncSetAttribute(k_mma,    cudaFuncAttributeMaxDynamicSharedMemorySize, SMEM_MMA);
    cudaFuncSetAttribute(k_Ahmma,  cudaFuncAttributeMaxDynamicSharedMemorySize, AH_SMEM);
    cudaFuncSetAttribute(k_xgmma,  cudaFuncAttributeMaxDynamicSharedMemorySize, XG_SMEM);
    cudaFuncSetAttribute(k_outmma, cudaFuncAttributeMaxDynamicSharedMemorySize, O_SMEM);

    k_hidden<<<(NB*NN)/16, 256>>>(z, Win, bin, w1, w2);
    k_adj<<<NN, 256>>>(emb);
    k_Avs<<<dim3(MP/256, MP), 256>>>(vsM);
    k_T2<<<dim3(NP/32, NP/32), 256>>>(bs);
    k_wprep<<<dim3(OUTC/256, 64), 256>>>(Wout);
    k_mma<<<dim3(NP/256, MP/128, NB), 256, SMEM_MMA>>>();

    k_Ahmma<<<dim3(MP/128, NB), 256, AH_SMEM>>>();
    k_xgmma<<<dim3(MP/128, NB), 256, XG_SMEM>>>();
    k_wn<<<dim3(8192/128, (NN+63)/64), 256>>>(emb, wp);
    k_g<<<NN, 256>>>(emb, bp);
    k_outmma<<<dim3(OUTC/128, (NB*NN)/(128*MT)), 256, O_SMEM>>>(bout, out);
}

// round 9
// speedup vs baseline: 4.9058x; 1.0041x over previous
#include <cuda_runtime.h>
#include <cuda_fp16.h>
#include <math.h>
#include <stdint.h>

#define NB 8
#define NN 2000
#define HH 64
#define DD 16
#define OUTC 4096

// padded GEMM dims
#define MP 2048
#define NP 2048
#define KSEG 2048            // K for the big GEMM (T_hi only)
#define KCHUNK 64
#define NCHUNK (KSEG/KCHUNK) // 32

// ---------------- scratch (static __device__ — zero-initialized) --------------
__device__ float d_e1 [NB*NN];
__device__ float d_e2 [NB*NN];
__device__ __align__(16) float d_xg [(size_t)NB*NN*128];  // [b][node][128] fp32
__device__ float d_wn [(size_t)NN*128*HH];                // fp32 (accuracy-critical)
__device__ float d_psum[(size_t)NB*8*MP];                 // per-(batch,nblk,row) exp sums
// fp16 operands (pads never written -> stay zero from module init)
__device__ __align__(16) __half d_Abf  [(size_t)MP*KSEG];        // fp16(vs)
__device__ __align__(16) __half d_Bbf  [(size_t)NB*NP*KSEG];     // T_hi, [b][n][k]
__device__ __align__(16) __half d_Ebf  [(size_t)NB*MP*KSEG];     // exp(L) unnormalized
__device__ __align__(16) __half d_Adjbf[(size_t)MP*KSEG];        // fp16(A adj), [m][k]
__device__ __align__(16) __half d_hcat [(size_t)NB*MP*128];      // [b][node][0:64=h,64:128=Ah]
__device__ __align__(16) __half d_gcat [(size_t)NB*NN*192];      // [m][gh|gl|gh]
__device__ __align__(16) __half d_WoutT[(size_t)192*OUTC];       // [Wh;Wh;Wl] rows k, cols o

// ======================= portable PTX helpers (base sm_103 OK) ================
__device__ __forceinline__ uint32_t smem_u32(const void* p) {
    uint32_t a;
    asm("{ .reg .u64 t; cvta.to.shared.u64 t, %1; cvt.u32.u64 %0, t; }" : "=r"(a) : "l"(p));
    return a;
}
__device__ __forceinline__ void cp16(uint32_t s, const void* g) {
    asm volatile("cp.async.cg.shared.global [%0], [%1], 16;" :: "r"(s), "l"(g));
}
#define CP_COMMIT() asm volatile("cp.async.commit_group;" ::: "memory")
#define CP_WAIT1()  asm volatile("cp.async.wait_group 1;" ::: "memory")
#define CP_WAIT2()  asm volatile("cp.async.wait_group 2;" ::: "memory")
#define CP_WAIT0()  asm volatile("cp.async.wait_group 0;" ::: "memory")
__device__ __forceinline__ void ldm_x4(uint32_t* r, uint32_t addr) {
    asm volatile("ldmatrix.sync.aligned.m8n8.x4.shared.b16 {%0,%1,%2,%3}, [%4];"
        : "=r"(r[0]), "=r"(r[1]), "=r"(r[2]), "=r"(r[3]) : "r"(addr));
}
__device__ __forceinline__ void ldm_x2(uint32_t* r, uint32_t addr) {
    asm volatile("ldmatrix.sync.aligned.m8n8.x2.shared.b16 {%0,%1}, [%2];"
        : "=r"(r[0]), "=r"(r[1]) : "r"(addr));
}
__device__ __forceinline__ void ldm_x2_t(uint32_t* r, uint32_t addr) {
    asm volatile("ldmatrix.sync.aligned.m8n8.x2.trans.shared.b16 {%0,%1}, [%2];"
        : "=r"(r[0]), "=r"(r[1]) : "r"(addr));
}
__device__ __forceinline__ void mma_f16(float* c, const uint32_t* a, const uint32_t* b) {
    asm volatile(
        "mma.sync.aligned.m16n8k16.row.col.f32.f16.f16.f32 "
        "{%0,%1,%2,%3}, {%4,%5,%6,%7}, {%8,%9}, {%0,%1,%2,%3};"
        : "+f"(c[0]), "+f"(c[1]), "+f"(c[2]), "+f"(c[3])
        : "r"(a[0]), "r"(a[1]), "r"(a[2]), "r"(a[3]), "r"(b[0]), "r"(b[1]));
}
// fast accurate tanh: 1 - 2/(e^{2x}+1); __expf rel err ~1e-6 (saturates correctly)
__device__ __forceinline__ float fast_tanh(float x) {
    float t = __expf(2.f*x);
    return 1.f - __fdividef(2.f, t + 1.f);
}

// ---------------- K1: h = relu(z@W_in^T + b_in) -> hcat[:,0:64] fp16 ----------
__global__ void __launch_bounds__(256) k_hidden(const float* __restrict__ z,
                         const float* __restrict__ Win,
                         const float* __restrict__ bin, const float* __restrict__ w1,
                         const float* __restrict__ w2) {
    __shared__ float Ws[4096];        // transposed: Ws[c*64+h]
    __shared__ float zs[4][64];
    __shared__ float red1[4][2], red2[4][2];
    __shared__ float binS[64], w1S[64], w2S[64];
    int tid = threadIdx.x;
    for (int i = tid; i < 4096; i += 256) {
        int h = i >> 6, c = i & 63;
        Ws[c*64 + h] = Win[i];
    }
    if (tid < 64) { binS[tid] = bin[tid]; w1S[tid] = w1[tid]; w2S[tid] = w2[tid]; }
    __syncthreads();
    int slice = tid >> 6, o = tid & 63;
    int wihalf = (tid >> 5) & 1;
#pragma unroll 1
    for (int it = 0; it < 4; it++) {
        int row = blockIdx.x*16 + it*4 + slice;
        zs[slice][o] = z[(size_t)row*64 + o];
        __syncthreads();
        float acc = binS[o];
#pragma unroll 16
        for (int c = 0; c < 64; c++) acc += zs[slice][c] * Ws[c*64 + o];
        float hv = fmaxf(acc, 0.f);
        int b = row / NN, node = row % NN;
        d_hcat[((size_t)b*MP + node)*128 + o] = __float2half_rn(hv);
        float p1 = hv * w1S[o], p2 = hv * w2S[o];
#pragma unroll
        for (int s = 16; s > 0; s >>= 1) {
            p1 += __shfl_down_sync(0xffffffffu, p1, s);
            p2 += __shfl_down_sync(0xffffffffu, p2, s);
        }
        if ((tid & 31) == 0) { red1[slice][wihalf] = p1; red2[slice][wihalf] = p2; }
        __syncthreads();
        if (o == 0) {
            d_e1[row] = red1[slice][0] + red1[slice][1];
            d_e2[row] = red2[slice][0] + red2[slice][1];
        }
    }
}

// ---------------- K2: Adj = softmax(relu(emb@emb^T)) -> fp16 ------------------
__global__ void k_adj(const float* __restrict__ emb) {
    __shared__ float buf[NN];
    __shared__ float red[256];
    __shared__ float ei[16];
    int i = blockIdx.x, tid = threadIdx.x;
    if (tid < 16) ei[tid] = emb[i*16 + tid];
    __syncthreads();
    float mx = -1e30f;
    for (int j = tid; j < NN; j += 256) {
        const float* er = emb + (size_t)j*16;
        float dsum = 0.f;
#pragma unroll
        for (int d = 0; d < 16; d++) dsum += ei[d]*er[d];
        dsum = fmaxf(dsum, 0.f);
        buf[j] = dsum;
        mx = fmaxf(mx, dsum);
    }
    red[tid] = mx; __syncthreads();
    for (int s = 128; s > 0; s >>= 1) { if (tid < s) red[tid] = fmaxf(red[tid], red[tid+s]); __syncthreads(); }
    mx = red[0]; __syncthreads();
    float sum = 0.f;
    for (int j = tid; j < NN; j += 256) { float v = __expf(buf[j]-mx); buf[j] = v; sum += v; }
    red[tid] = sum; __syncthreads();
    for (int s = 128; s > 0; s >>= 1) { if (tid < s) red[tid] += red[tid+s]; __syncthreads(); }
    float inv = 1.f/red[0];
    for (int j = tid; j < NN; j += 256)
        d_Adjbf[(size_t)i*KSEG + j] = __float2half_rn(buf[j]*inv);
}

// ---- K3a: A = fp16(vs) -------------------------------------------------------
__global__ void k_Avs(const float* __restrict__ vsM) {
    int k = blockIdx.x*256 + threadIdx.x;
    int m = blockIdx.y;
    float t = (m < NN && k < NN) ? vsM[(size_t)m*NN + k] : 0.f;
    d_Abf[(size_t)m*KSEG + k] = __float2half_rn(t);
}

// ---- K3b: B[b][n][k] = fp16(sigmoid(e1[b,k]*e2[b,n] + bs[k,n])) --------------
__global__ void k_T2(const float* __restrict__ bs) {
    __shared__ float sbs[32][33];
    int k0 = blockIdx.x*32, n0 = blockIdx.y*32;
    int tid = threadIdx.x;
#pragma unroll
    for (int l = 0; l < 4; l++) {
        int kk = (tid >> 5) + l*8, nn = tid & 31;
        int gk = k0 + kk, gn = n0 + nn;
        sbs[kk][nn] = (gk < NN && gn < NN) ? bs[(size_t)gk*NN + gn] : 0.f;
    }
    __syncthreads();
    int nnl = tid >> 4;
    int kl  = (tid & 15) * 2;
#pragma unroll
    for (int half = 0; half < 2; half++) {
        int nn = nnl + half*16;
        int gn = n0 + nn;
        bool nok = gn < NN;
        int gk0 = k0 + kl, gk1 = gk0 + 1;
        float b0 = sbs[kl][nn], b1 = sbs[kl+1][nn];
#pragma unroll
        for (int b = 0; b < NB; b++) {
            float v0 = 0.f, v1 = 0.f;
            if (nok) {
                float e2v = d_e2[b*NN + gn];
                if (gk0 < NN) { float x = d_e1[b*NN + gk0]*e2v + b0; v0 = 1.f/(1.f + __expf(-x)); }
                if (gk1 < NN) { float x = d_e1[b*NN + gk1]*e2v + b1; v1 = 1.f/(1.f + __expf(-x)); }
            }
            size_t base = ((size_t)b*NP + gn)*KSEG + gk0;
            *(__half2*)&d_Bbf[base] = __halves2half2(__float2half_rn(v0), __float2half_rn(v1));
        }
    }
}

// ---- K4: L[b]=A@B^T; epilogue: exp(L) -> d_Ebf fp16 + per-row partial sums ----
#define AROW 144
#define ABUF 18432
#define BBUF 36864
#define STAGE (ABUF + BBUF)            // 55296
#define SMEM_MMA (4*STAGE)             // 221184

__global__ void __launch_bounds__(256, 1) k_mma() {
    extern __shared__ __align__(16) char smem[];
    __shared__ float rs[128][4];
    uint32_t sb = smem_u32(smem);
    int tid = threadIdx.x, lane = tid & 31, w = tid >> 5;
    int b  = blockIdx.z;
    int m0 = blockIdx.y * 128;
    int n0 = blockIdx.x * 256;
    const __half* Ag = d_Abf + (size_t)m0*KSEG;
    const __half* Bg = d_Bbf + ((size_t)b*NP + n0)*KSEG;

    auto issue = [&](int kc, int buf) {
        uint32_t sA = sb + buf*STAGE;
        uint32_t sB = sA + ABUF;
        int ka = kc * KCHUNK;
#pragma unroll
        for (int l = 0; l < 4; l++) {
            int seg = tid + l*256;
            int row = seg >> 3, c = seg & 7;
            cp16(sA + row*AROW + c*16, Ag + (size_t)row*KSEG + ka + c*8);
        }
#pragma unroll
        for (int l = 0; l < 8; l++) {
            int seg = tid + l*256;
            int row = seg >> 3, c = seg & 7;
            cp16(sB + row*AROW + c*16, Bg + (size_t)row*KSEG + ka + c*8);
        }
        CP_COMMIT();
    };

    issue(0, 0);
    issue(1, 1);
    issue(2, 2);

    float c[4][8][4];
#pragma unroll
    for (int mi = 0; mi < 4; mi++)
#pragma unroll
        for (int nj = 0; nj < 8; nj++)
#pragma unroll
            for (int q = 0; q < 4; q++) c[mi][nj][q] = 0.f;

    int wm = w & 1, wn = w >> 1;
    int a_row = (lane & 15), a_kh = (lane >> 4) * 16;
    int b_off = ((lane & 7) + ((lane >> 4) & 1)*8)*AROW + ((lane >> 3) & 1)*16;

    int buf = 0;
    for (int kc = 0; kc < NCHUNK; kc++) {
        CP_WAIT2();
        __syncthreads();
        uint32_t sA = sb + buf*STAGE          + (wm*64 + a_row)*AROW + a_kh;
        uint32_t sB = sb + buf*STAGE + ABUF   + (wn*64)*AROW + b_off;
#pragma unroll
        for (int ks = 0; ks < 4; ks++) {
            uint32_t af[4][4], bf[8][2];
#pragma unroll
            for (int mi = 0; mi < 4; mi++)
                ldm_x4(af[mi], sA + mi*16*AROW + ks*32);
#pragma unroll
            for (int j = 0; j < 4; j++) {
                uint32_t q[4];
                ldm_x4(q, sB + j*16*AROW + ks*32);
                bf[2*j][0] = q[0]; bf[2*j][1] = q[1];
                bf[2*j+1][0] = q[2]; bf[2*j+1][1] = q[3];
            }
#pragma unroll
            for (int mi = 0; mi < 4; mi++)
#pragma unroll
                for (int nj = 0; nj < 8; nj++)
                    mma_f16(c[mi][nj], af[mi], bf[nj]);
        }
        if (kc + 3 < NCHUNK) issue(kc + 3, (kc + 3) & 3);
        else CP_COMMIT();
        buf = (buf + 1) & 3;
    }

    // epilogue: exp + store unnormalized E + deterministic row partial sums
    __half* Eb = d_Ebf + (size_t)b*MP*KSEG;
    int gid = lane >> 2, tig = lane & 3;
#pragma unroll
    for (int mi = 0; mi < 4; mi++) {
        int gm = m0 + wm*64 + mi*16 + gid;
        float s0 = 0.f, s1 = 0.f;
#pragma unroll
        for (int nj = 0; nj < 8; nj++) {
            int gn = n0 + wn*64 + nj*8 + tig*2;
            bool nok = gn < NN;
            float e0 = nok ? __expf(c[mi][nj][0]) : 0.f;
            float e1 = nok ? __expf(c[mi][nj][1]) : 0.f;
            float e2 = nok ? __expf(c[mi][nj][2]) : 0.f;
            float e3 = nok ? __expf(c[mi][nj][3]) : 0.f;
            s0 += e0 + e1;
            s1 += e2 + e3;
            if (nok) {
                if (gm < NN)
                    *(__half2*)&Eb[(size_t)gm*KSEG + gn]     = __floats2half2_rn(e0, e1);
                if (gm + 8 < NN)
                    *(__half2*)&Eb[(size_t)(gm+8)*KSEG + gn] = __floats2half2_rn(e2, e3);
            }
        }
        s0 += __shfl_xor_sync(0xffffffffu, s0, 1);
        s0 += __shfl_xor_sync(0xffffffffu, s0, 2);
        s1 += __shfl_xor_sync(0xffffffffu, s1, 1);
        s1 += __shfl_xor_sync(0xffffffffu, s1, 2);
        if (tig == 0) {
            rs[wm*64 + mi*16 + gid][wn]     = s0;
            rs[wm*64 + mi*16 + gid + 8][wn] = s1;
        }
    }
    __syncthreads();
    if (tid < 128) {
        float tot = (rs[tid][0] + rs[tid][1]) + (rs[tid][2] + rs[tid][3]);
        d_psum[((size_t)b*8 + blockIdx.x)*MP + m0 + tid] = tot;
    }
}

// ---- K6a: hcat[:,64:128] = Adj @ h   (fp16 mma, tile 128x64) -----------------
#define AH_BROW 144
#define AH_BBUF (64*AH_BROW)               // 9216
#define AH_STAGE (ABUF + AH_BBUF)          // 27648
#define AH_SMEM (2*AH_STAGE)               // 55296

__global__ void __launch_bounds__(256) k_Ahmma() {
    extern __shared__ __align__(16) char smem[];
    uint32_t sb = smem_u32(smem);
    int tid = threadIdx.x, lane = tid & 31, w = tid >> 5;
    int b = blockIdx.y;
    int m0 = blockIdx.x * 128;
    const __half* Ag = d_Adjbf + (size_t)m0*KSEG;
    const __half* Bg = d_hcat + (size_t)b*MP*128;

    auto issue = [&](int kc, int buf) {
        uint32_t sA = sb + buf*AH_STAGE;
        uint32_t sB = sA + ABUF;
#pragma unroll
        for (int l = 0; l < 4; l++) {
            int seg = tid + l*256;
            int row = seg >> 3, c = seg & 7;
            cp16(sA + row*AROW + c*16, Ag + (size_t)row*KSEG + kc*KCHUNK + c*8);
        }
#pragma unroll
        for (int l = 0; l < 2; l++) {
            int seg = tid + l*256;
            int row = seg >> 3, c = seg & 7;
            cp16(sB + row*AH_BROW + c*16, Bg + (size_t)(kc*KCHUNK + row)*128 + c*8);
        }
        CP_COMMIT();
    };

    issue(0, 0);
    issue(1, 1);

    float c[2][4][4];
#pragma unroll
    for (int mi = 0; mi < 2; mi++)
#pragma unroll
        for (int nj = 0; nj < 4; nj++)
#pragma unroll
            for (int q = 0; q < 4; q++) c[mi][nj][q] = 0.f;

    int wm = w >> 1, wn = w & 1;
    for (int kc = 0; kc < NCHUNK; kc++) {
        CP_WAIT1();
        __syncthreads();
        int buf = kc & 1;
        uint32_t sA = sb + buf*AH_STAGE + (wm*32 + (lane & 15))*AROW + (lane >> 4)*16;
        uint32_t sB = sb + buf*AH_STAGE + ABUF;
#pragma unroll
        for (int ks = 0; ks < 4; ks++) {
            uint32_t af[2][4], bf[4][2];
#pragma unroll
            for (int mi = 0; mi < 2; mi++)
                ldm_x4(af[mi], sA + mi*16*AROW + ks*32);
#pragma unroll
            for (int nj = 0; nj < 4; nj++)
                ldm_x2_t(bf[nj], sB + (ks*16 + (lane & 15))*AH_BROW + (wn*32 + nj*8)*2);
#pragma unroll
            for (int mi = 0; mi < 2; mi++)
#pragma unroll
                for (int nj = 0; nj < 4; nj++)
                    mma_f16(c[mi][nj], af[mi], bf[nj]);
        }
        __syncthreads();
        if (kc + 2 < NCHUNK) issue(kc + 2, buf);
        else CP_COMMIT();
    }

    int gid = lane >> 2, tig = lane & 3;
#pragma unroll
    for (int mi = 0; mi < 2; mi++) {
        int gm = m0 + wm*32 + mi*16 + gid;
#pragma unroll
        for (int nj = 0; nj < 4; nj++) {
            int gn = wn*32 + nj*8 + tig*2;
            if (gm < NN)
                *(__half2*)&d_hcat[((size_t)b*MP + gm)*128 + 64 + gn] =
                    __halves2half2(__float2half_rn(c[mi][nj][0]), __float2half_rn(c[mi][nj][1]));
            if (gm + 8 < NN)
                *(__half2*)&d_hcat[((size_t)b*MP + gm + 8)*128 + 64 + gn] =
                    __halves2half2(__float2half_rn(c[mi][nj][2]), __float2half_rn(c[mi][nj][3]));
        }
    }
}

// ---- K6b: xg = softmax-normalized E @ hcat  (fp16 mma, tile 128x128) ---------
#define XG_BROW 272
#define XG_BBUF (64*XG_BROW)               // 17408
#define XG_STAGE (ABUF + XG_BBUF)          // 35840
#define XG_SMEM (2*XG_STAGE)               // 71680

__global__ void __launch_bounds__(256) k_xgmma() {
    extern __shared__ __align__(16) char smem[];
    __shared__ float invS[128];
    uint32_t sb = smem_u32(smem);
    int tid = threadIdx.x, lane = tid & 31, w = tid >> 5;
    int b = blockIdx.y;
    int m0 = blockIdx.x * 128;
    const __half* Ag = d_Ebf + ((size_t)b*MP + m0)*KSEG;
    const __half* Bg = d_hcat + (size_t)b*MP*128;

    auto issue = [&](int kc, int buf) {
        uint32_t sA = sb + buf*XG_STAGE;
        uint32_t sB = sA + ABUF;
#pragma unroll
        for (int l = 0; l < 4; l++) {
            int seg = tid + l*256;
            int row = seg >> 3, c = seg & 7;
            cp16(sA + row*AROW + c*16, Ag + (size_t)row*KSEG + kc*KCHUNK + c*8);
        }
#pragma unroll
        for (int l = 0; l < 4; l++) {
            int seg = tid + l*256;
            int row = seg >> 4, c = seg & 15;
            cp16(sB + row*XG_BROW + c*16, Bg + (size_t)(kc*KCHUNK + row)*128 + c*8);
        }
        CP_COMMIT();
    };

    issue(0, 0);
    issue(1, 1);

    if (tid < 128) {
        float s = 0.f;
#pragma unroll
        for (int nb = 0; nb < 8; nb++)
            s += d_psum[((size_t)b*8 + nb)*MP + m0 + tid];
        invS[tid] = 1.f / s;
    }

    float c[2][8][4];
#pragma unroll
    for (int mi = 0; mi < 2; mi++)
#pragma unroll
        for (int nj = 0; nj < 8; nj++)
#pragma unroll
            for (int q = 0; q < 4; q++) c[mi][nj][q] = 0.f;

    int wm = w >> 1, wn = w & 1;
    for (int kc = 0; kc < NCHUNK; kc++) {
        CP_WAIT1();
        __syncthreads();
        int buf = kc & 1;
        uint32_t sA = sb + buf*XG_STAGE + (wm*32 + (lane & 15))*AROW + (lane >> 4)*16;
        uint32_t sB = sb + buf*XG_STAGE + ABUF;
#pragma unroll
        for (int ks = 0; ks < 4; ks++) {
            uint32_t af[2][4], bf[8][2];
#pragma unroll
            for (int mi = 0; mi < 2; mi++)
                ldm_x4(af[mi], sA + mi*16*AROW + ks*32);
#pragma unroll
            for (int nj = 0; nj < 8; nj++)
                ldm_x2_t(bf[nj], sB + (ks*16 + (lane & 15))*XG_BROW + (wn*64 + nj*8)*2);
#pragma unroll
            for (int mi = 0; mi < 2; mi++)
#pragma unroll
                for (int nj = 0; nj < 8; nj++)
                    mma_f16(c[mi][nj], af[mi], bf[nj]);
        }
        __syncthreads();
        if (kc + 2 < NCHUNK) issue(kc + 2, buf);
        else CP_COMMIT();
    }

    int gid = lane >> 2, tig = lane & 3;
#pragma unroll
    for (int mi = 0; mi < 2; mi++) {
        int lr = wm*32 + mi*16 + gid;
        int gm = m0 + lr;
        float inv0 = invS[lr], inv1 = invS[lr + 8];
#pragma unroll
        for (int nj = 0; nj < 8; nj++) {
            int gn = wn*64 + nj*8 + tig*2;
            if (gm < NN)
                *(float2*)&d_xg[((size_t)b*NN + gm)*128 + gn] =
                    make_float2(c[mi][nj][0]*inv0, c[mi][nj][1]*inv0);
            if (gm + 8 < NN)
                *(float2*)&d_xg[((size_t)b*NN + gm + 8)*128 + gn] =
                    make_float2(c[mi][nj][2]*inv1, c[mi][nj][3]*inv1);
        }
    }
}

// ---------------- K7: weights = emb @ wp_flat (fp32) --------------------------
__global__ void k_wn(const float* __restrict__ emb, const float* __restrict__ wp) {
    __shared__ float Es[64][16];
    __shared__ float Ws[16][128];
    int n0 = blockIdx.y*64, c0 = blockIdx.x*128;
    int tid = threadIdx.x;
    for (int i=tid;i<1024;i+=256){ int r=i>>4, d=i&15; int n=n0+r; Es[r][d] = (n<NN)? emb[(size_t)n*16+d] : 0.f; }
    for (int i=tid;i<2048;i+=256){ int kr=i>>7, c=i&127; Ws[kr][c] = wp[(size_t)kr*8192 + c0 + c]; }
    __syncthreads();
    int ty=tid>>4, tx=tid&15;
    float acc[4][8];
#pragma unroll
    for (int i=0;i<4;i++)
#pragma unroll
        for (int j=0;j<8;j++) acc[i][j]=0.f;
#pragma unroll
    for (int d=0; d<16; d++){
        float ev[4], wv[8];
#pragma unroll
        for (int i=0;i<4;i++) ev[i]=Es[ty*4+i][d];
#pragma unroll
        for (int j=0;j<8;j++) wv[j]=Ws[d][tx*8+j];
#pragma unroll
        for (int i=0;i<4;i++)
#pragma unroll
            for (int j=0;j<8;j++) acc[i][j] += ev[i]*wv[j];
    }
#pragma unroll
    for (int i=0;i<4;i++){
        int n = n0+ty*4+i;
        if (n >= NN) continue;
#pragma unroll
        for (int j=0;j<8;j++)
            d_wn[(size_t)n*8192 + c0 + tx*8 + j] = acc[i][j];
    }
}

// ---------------- K8: g = xg @ W_n + bias_n -> gcat fp16 [gh|gl|gh] -----------
__global__ void k_g(const float* __restrict__ emb, const float* __restrict__ bp) {
    __shared__ float Wns[8192];
    __shared__ float xgs[8][128];
    __shared__ float bias_s[64];
    __shared__ float es[16];
    int n = blockIdx.x, tid = threadIdx.x;
    if (tid < 16) es[tid] = emb[(size_t)n*16+tid];
    for (int i=tid;i<8192;i+=256) Wns[i] = d_wn[(size_t)n*8192 + i];
    for (int i=tid;i<1024;i+=256){
        int b=i>>7, ki=i&127;
        xgs[b][ki] = d_xg[((size_t)b*NN+n)*128 + ki];
    }
    __syncthreads();
    if (tid < 64) {
        float bv = 0.f;
#pragma unroll
        for (int d=0; d<16; d++) bv += es[d]*bp[d*64+tid];
        bias_s[tid] = bv;
    }
    __syncthreads();
    int o = tid & 63;
#pragma unroll
    for (int rep=0; rep<2; rep++){
        int b = (tid>>6) + rep*4;
        float acc = bias_s[o];
#pragma unroll 8
        for (int ki=0; ki<128; ki++) acc += xgs[b][ki]*Wns[ki*64+o];
        __half gh = __float2half_rn(acc);
        __half gl = __float2half_rn(acc - __half2float(gh));
        size_t base = ((size_t)b*NN + n)*192;
        d_gcat[base + o]       = gh;
        d_gcat[base + 64 + o]  = gl;
        d_gcat[base + 128 + o] = gh;
    }
}

// ---------------- K9a: WoutT = [Wh;Wh;Wl] fp16 --------------------------------
__global__ void k_wprep(const float* __restrict__ Wout) {
    int o = blockIdx.x*256 + threadIdx.x;
    int h = blockIdx.y;
    float w = Wout[(size_t)o*64 + h];
    __half wh = __float2half_rn(w);
    __half wl = __float2half_rn(w - __half2float(wh));
    d_WoutT[(size_t)h*OUTC + o]         = wh;
    d_WoutT[(size_t)(64+h)*OUTC + o]    = wh;
    d_WoutT[(size_t)(128+h)*OUTC + o]   = wl;
}

// ---------------- K9b: out = 0.1*tanh(gcat @ WoutT + b_out) -------------------
#define MT 5
#define O_AROW 400
#define O_ABUF (128*O_AROW)    // 51200
#define O_BROW 272
#define O_BBUF (192*O_BROW)    // 52224
#define O_SMEM (O_BBUF + 2*O_ABUF + 512)   // 155136

__global__ void __launch_bounds__(256) k_outmma(const float* __restrict__ bout,
                                                float* __restrict__ out) {
    extern __shared__ __align__(16) char smem[];
    uint32_t sb = smem_u32(smem);
    float* boS = (float*)(smem + O_BBUF + 2*O_ABUF);
    int tid = threadIdx.x, lane = tid & 31, w = tid >> 5;
    int n0 = blockIdx.x * 128;
    int mg = blockIdx.y * MT;

#pragma unroll
    for (int l = 0; l < 12; l++) {
        int seg = tid + l*256;
        int row = seg >> 4, c = seg & 15;
        cp16(sb + row*O_BROW + c*16, d_WoutT + (size_t)row*OUTC + n0 + c*8);
    }
    CP_COMMIT();
    if (tid < 128) boS[tid] = bout[n0 + tid];

    auto issueA = [&](int i, int buf) {
        uint32_t sA = sb + O_BBUF + buf*O_ABUF;
        int m0 = (mg + i)*128;
#pragma unroll
        for (int l = 0; l < 12; l++) {
            int seg = tid + l*256;
            int row = seg / 24, c = seg % 24;
            cp16(sA + row*O_AROW + c*16, d_gcat + (size_t)(m0+row)*192 + c*8);
        }
        CP_COMMIT();
    };
    issueA(0, 0);

    int wm = w >> 1, wn = w & 1;
    int gid = lane >> 2, tig = lane & 3;

    for (int i = 0; i < MT; i++) {
        CP_WAIT0();
        __syncthreads();
        if (i + 1 < MT) issueA(i + 1, (i + 1) & 1);

        uint32_t sA = sb + O_BBUF + (i & 1)*O_ABUF + (wm*32 + (lane & 15))*O_AROW + (lane >> 4)*16;
        uint32_t sB = sb;
        float c[2][8][4];
#pragma unroll
        for (int mi = 0; mi < 2; mi++)
#pragma unroll
            for (int nj = 0; nj < 8; nj++)
#pragma unroll
                for (int q = 0; q < 4; q++) c[mi][nj][q] = 0.f;

#pragma unroll
        for (int kk = 0; kk < 12; kk++) {
            uint32_t af[2][4], bf[8][2];
#pragma unroll
            for (int mi = 0; mi < 2; mi++)
                ldm_x4(af[mi], sA + mi*16*O_AROW + kk*32);
#pragma unroll
            for (int nj = 0; nj < 8; nj++)
                ldm_x2_t(bf[nj], sB + (kk*16 + (lane & 15))*O_BROW + (wn*64 + nj*8)*2);
#pragma unroll
            for (int mi = 0; mi < 2; mi++)
#pragma unroll
                for (int nj = 0; nj < 8; nj++)
                    mma_f16(c[mi][nj], af[mi], bf[nj]);
        }

        int m0 = (mg + i)*128;
#pragma unroll
        for (int mi = 0; mi < 2; mi++) {
            int gm = m0 + wm*32 + mi*16 + gid;
#pragma unroll
            for (int nj = 0; nj < 8; nj++) {
                int cn = wn*64 + nj*8 + tig*2;
                int gn = n0 + cn;
                float b0 = boS[cn], b1 = boS[cn+1];
                float2 v0 = make_float2(0.1f*fast_tanh(c[mi][nj][0] + b0), 0.1f*fast_tanh(c[mi][nj][1] + b1));
                float2 v1 = make_float2(0.1f*fast_tanh(c[mi][nj][2] + b0), 0.1f*fast_tanh(c[mi][nj][3] + b1));
                *(float2*)&out[(size_t)gm*OUTC + gn]       = v0;
                *(float2*)&out[(size_t)(gm+8)*OUTC + gn]   = v1;
            }
        }
        __syncthreads();
    }
}

// ---------------- launch ------------------------------------------------------
extern "C" void kernel_launch(void* const* d_in, const int* in_sizes, int n_in,
                              void* d_out, int out_size) {
    const float* z    = (const float*)d_in[0];
    const float* Win  = (const float*)d_in[1];
    const float* bin  = (const float*)d_in[2];
    const float* Wout = (const float*)d_in[3];
    const float* bout = (const float*)d_in[4];
    const float* emb  = (const float*)d_in[5];
    const float* wp   = (const float*)d_in[6];
    const float* bp   = (const float*)d_in[7];
    const float* w1   = (const float*)d_in[8];
    const float* w2   = (const float*)d_in[9];
    const float* vsM  = (const float*)d_in[10];
    const float* bs   = (const float*)d_in[11];
    float* out = (float*)d_out;
    (void)in_sizes; (void)n_in; (void)out_size;

    cudaFuncSetAttribute(k_mma,    cudaFuncAttributeMaxDynamicSharedMemorySize, SMEM_MMA);
    cudaFuncSetAttribute(k_Ahmma,  cudaFuncAttributeMaxDynamicSharedMemorySize, AH_SMEM);
    cudaFuncSetAttribute(k_xgmma,  cudaFuncAttributeMaxDynamicSharedMemorySize, XG_SMEM);
    cudaFuncSetAttribute(k_outmma, cudaFuncAttributeMaxDynamicSharedMemorySize, O_SMEM);

    k_hidden<<<(NB*NN)/16, 256>>>(z, Win, bin, w1, w2);
    k_adj<<<NN, 256>>>(emb);
    k_Avs<<<dim3(MP/256, MP), 256>>>(vsM);
    k_T2<<<dim3(NP/32, NP/32), 256>>>(bs);
    k_wprep<<<dim3(OUTC/256, 64), 256>>>(Wout);
    k_mma<<<dim3(NP/256, MP/128, NB), 256, SMEM_MMA>>>();

    k_Ahmma<<<dim3(MP/128, NB), 256, AH_SMEM>>>();
    k_xgmma<<<dim3(MP/128, NB), 256, XG_SMEM>>>();
    k_wn<<<dim3(8192/128, (NN+63)/64), 256>>>(emb, wp);
    k_g<<<NN, 256>>>(emb, bp);
    k_outmma<<<dim3(OUTC/128, (NB*NN)/(128*MT)), 256, O_SMEM>>>(bout, out);
}

// round 10
// speedup vs baseline: 5.1112x; 1.0418x over previous
#include <cuda_runtime.h>
#include <cuda_fp16.h>
#include <math.h>
#include <stdint.h>

#define NB 8
#define NN 2000
#define HH 64
#define DD 16
#define OUTC 4096

// padded GEMM dims
#define MP 2048
#define NP 2048
#define KSEG 2048            // K for the big GEMM (T_hi only)
#define KCHUNK 64
#define NCHUNK (KSEG/KCHUNK) // 32

// ---------------- scratch (static __device__ — zero-initialized) --------------
__device__ float d_e1 [NB*NN];
__device__ float d_e2 [NB*NN];
__device__ __align__(16) float d_xg [(size_t)NB*NN*128];  // [b][node][128] fp32
__device__ float d_wn [(size_t)NN*128*HH];                // fp32 (accuracy-critical)
__device__ float d_psum[(size_t)NB*8*MP];                 // per-(batch,nblk,row) exp sums
// fp16 operands (pads never written -> stay zero from module init)
__device__ __align__(16) __half d_Abf  [(size_t)MP*KSEG];        // fp16(vs)
__device__ __align__(16) __half d_Bbf  [(size_t)NB*NP*KSEG];     // T_hi, [b][n][k]
__device__ __align__(16) __half d_Ebf  [(size_t)NB*MP*KSEG];     // exp(L) unnormalized
__device__ __align__(16) __half d_Adjbf[(size_t)MP*KSEG];        // fp16(A adj), [m][k]
__device__ __align__(16) __half d_hcat [(size_t)NB*MP*128];      // [b][node][0:64=h,64:128=Ah]
__device__ __align__(16) __half d_gcat [(size_t)NB*NN*192];      // [m][gh|gl|gh]
__device__ __align__(16) __half d_WoutT[(size_t)192*OUTC];       // [Wh;Wh;Wl] rows k, cols o

// ======================= portable PTX helpers (base sm_103 OK) ================
__device__ __forceinline__ uint32_t smem_u32(const void* p) {
    uint32_t a;
    asm("{ .reg .u64 t; cvta.to.shared.u64 t, %1; cvt.u32.u64 %0, t; }" : "=r"(a) : "l"(p));
    return a;
}
__device__ __forceinline__ void cp16(uint32_t s, const void* g) {
    asm volatile("cp.async.cg.shared.global [%0], [%1], 16;" :: "r"(s), "l"(g));
}
#define CP_COMMIT() asm volatile("cp.async.commit_group;" ::: "memory")
#define CP_WAIT1()  asm volatile("cp.async.wait_group 1;" ::: "memory")
#define CP_WAIT2()  asm volatile("cp.async.wait_group 2;" ::: "memory")
#define CP_WAIT0()  asm volatile("cp.async.wait_group 0;" ::: "memory")
__device__ __forceinline__ void ldm_x4(uint32_t* r, uint32_t addr) {
    asm volatile("ldmatrix.sync.aligned.m8n8.x4.shared.b16 {%0,%1,%2,%3}, [%4];"
        : "=r"(r[0]), "=r"(r[1]), "=r"(r[2]), "=r"(r[3]) : "r"(addr));
}
__device__ __forceinline__ void ldm_x2(uint32_t* r, uint32_t addr) {
    asm volatile("ldmatrix.sync.aligned.m8n8.x2.shared.b16 {%0,%1}, [%2];"
        : "=r"(r[0]), "=r"(r[1]) : "r"(addr));
}
__device__ __forceinline__ void ldm_x2_t(uint32_t* r, uint32_t addr) {
    asm volatile("ldmatrix.sync.aligned.m8n8.x2.trans.shared.b16 {%0,%1}, [%2];"
        : "=r"(r[0]), "=r"(r[1]) : "r"(addr));
}
__device__ __forceinline__ void mma_f16(float* c, const uint32_t* a, const uint32_t* b) {
    asm volatile(
        "mma.sync.aligned.m16n8k16.row.col.f32.f16.f16.f32 "
        "{%0,%1,%2,%3}, {%4,%5,%6,%7}, {%8,%9}, {%0,%1,%2,%3};"
        : "+f"(c[0]), "+f"(c[1]), "+f"(c[2]), "+f"(c[3])
        : "r"(a[0]), "r"(a[1]), "r"(a[2]), "r"(a[3]), "r"(b[0]), "r"(b[1]));
}
// fast accurate tanh: 1 - 2/(e^{2x}+1); __expf rel err ~1e-6 (saturates correctly)
__device__ __forceinline__ float fast_tanh(float x) {
    float t = __expf(2.f*x);
    return 1.f - __fdividef(2.f, t + 1.f);
}

// ---------------- K1: h = relu(z@W_in^T + b_in) -> hcat[:,0:64] fp16 ----------
__global__ void __launch_bounds__(256) k_hidden(const float* __restrict__ z,
                         const float* __restrict__ Win,
                         const float* __restrict__ bin, const float* __restrict__ w1,
                         const float* __restrict__ w2) {
    __shared__ float Ws[4096];        // transposed: Ws[c*64+h]
    __shared__ float zs[4][64];
    __shared__ float red1[4][2], red2[4][2];
    __shared__ float binS[64], w1S[64], w2S[64];
    int tid = threadIdx.x;
    for (int i = tid; i < 4096; i += 256) {
        int h = i >> 6, c = i & 63;
        Ws[c*64 + h] = Win[i];
    }
    if (tid < 64) { binS[tid] = bin[tid]; w1S[tid] = w1[tid]; w2S[tid] = w2[tid]; }
    __syncthreads();
    int slice = tid >> 6, o = tid & 63;
    int wihalf = (tid >> 5) & 1;
#pragma unroll 1
    for (int it = 0; it < 4; it++) {
        int row = blockIdx.x*16 + it*4 + slice;
        zs[slice][o] = z[(size_t)row*64 + o];
        __syncthreads();
        float acc = binS[o];
#pragma unroll 16
        for (int c = 0; c < 64; c++) acc += zs[slice][c] * Ws[c*64 + o];
        float hv = fmaxf(acc, 0.f);
        int b = row / NN, node = row % NN;
        d_hcat[((size_t)b*MP + node)*128 + o] = __float2half_rn(hv);
        float p1 = hv * w1S[o], p2 = hv * w2S[o];
#pragma unroll
        for (int s = 16; s > 0; s >>= 1) {
            p1 += __shfl_down_sync(0xffffffffu, p1, s);
            p2 += __shfl_down_sync(0xffffffffu, p2, s);
        }
        if ((tid & 31) == 0) { red1[slice][wihalf] = p1; red2[slice][wihalf] = p2; }
        __syncthreads();
        if (o == 0) {
            d_e1[row] = red1[slice][0] + red1[slice][1];
            d_e2[row] = red2[slice][0] + red2[slice][1];
        }
    }
}

// ---------------- K2: Adj = softmax(relu(emb@emb^T)) -> fp16 ------------------
__global__ void k_adj(const float* __restrict__ emb) {
    __shared__ float buf[NN];
    __shared__ float red[256];
    __shared__ float ei[16];
    int i = blockIdx.x, tid = threadIdx.x;
    if (tid < 16) ei[tid] = emb[i*16 + tid];
    __syncthreads();
    float mx = -1e30f;
    for (int j = tid; j < NN; j += 256) {
        const float* er = emb + (size_t)j*16;
        float dsum = 0.f;
#pragma unroll
        for (int d = 0; d < 16; d++) dsum += ei[d]*er[d];
        dsum = fmaxf(dsum, 0.f);
        buf[j] = dsum;
        mx = fmaxf(mx, dsum);
    }
    red[tid] = mx; __syncthreads();
    for (int s = 128; s > 0; s >>= 1) { if (tid < s) red[tid] = fmaxf(red[tid], red[tid+s]); __syncthreads(); }
    mx = red[0]; __syncthreads();
    float sum = 0.f;
    for (int j = tid; j < NN; j += 256) { float v = __expf(buf[j]-mx); buf[j] = v; sum += v; }
    red[tid] = sum; __syncthreads();
    for (int s = 128; s > 0; s >>= 1) { if (tid < s) red[tid] += red[tid+s]; __syncthreads(); }
    float inv = 1.f/red[0];
    for (int j = tid; j < NN; j += 256)
        d_Adjbf[(size_t)i*KSEG + j] = __float2half_rn(buf[j]*inv);
}

// ---- K3a: A = fp16(vs) -------------------------------------------------------
__global__ void k_Avs(const float* __restrict__ vsM) {
    int k = blockIdx.x*256 + threadIdx.x;
    int m = blockIdx.y;
    float t = (m < NN && k < NN) ? vsM[(size_t)m*NN + k] : 0.f;
    d_Abf[(size_t)m*KSEG + k] = __float2half_rn(t);
}

// ---- K3b: B[b][n][k] = fp16(sigmoid(e1[b,k]*e2[b,n] + bs[k,n])) --------------
__global__ void k_T2(const float* __restrict__ bs) {
    __shared__ float sbs[32][33];
    int k0 = blockIdx.x*32, n0 = blockIdx.y*32;
    int tid = threadIdx.x;
#pragma unroll
    for (int l = 0; l < 4; l++) {
        int kk = (tid >> 5) + l*8, nn = tid & 31;
        int gk = k0 + kk, gn = n0 + nn;
        sbs[kk][nn] = (gk < NN && gn < NN) ? bs[(size_t)gk*NN + gn] : 0.f;
    }
    __syncthreads();
    int nnl = tid >> 4;
    int kl  = (tid & 15) * 2;
#pragma unroll
    for (int half = 0; half < 2; half++) {
        int nn = nnl + half*16;
        int gn = n0 + nn;
        bool nok = gn < NN;
        int gk0 = k0 + kl, gk1 = gk0 + 1;
        float b0 = sbs[kl][nn], b1 = sbs[kl+1][nn];
#pragma unroll
        for (int b = 0; b < NB; b++) {
            float v0 = 0.f, v1 = 0.f;
            if (nok) {
                float e2v = d_e2[b*NN + gn];
                if (gk0 < NN) { float x = d_e1[b*NN + gk0]*e2v + b0; v0 = 1.f/(1.f + __expf(-x)); }
                if (gk1 < NN) { float x = d_e1[b*NN + gk1]*e2v + b1; v1 = 1.f/(1.f + __expf(-x)); }
            }
            size_t base = ((size_t)b*NP + gn)*KSEG + gk0;
            *(__half2*)&d_Bbf[base] = __halves2half2(__float2half_rn(v0), __float2half_rn(v1));
        }
    }
}

// ---- K4: L[b]=A@B^T; epilogue: exp(L) -> d_Ebf fp16 + per-row partial sums ----
#define AROW 144
#define ABUF 18432
#define BBUF 36864
#define STAGE (ABUF + BBUF)            // 55296
#define SMEM_MMA (4*STAGE)             // 221184

__global__ void __launch_bounds__(256, 1) k_mma() {
    extern __shared__ __align__(16) char smem[];
    __shared__ float rs[128][4];
    uint32_t sb = smem_u32(smem);
    int tid = threadIdx.x, lane = tid & 31, w = tid >> 5;
    int b  = blockIdx.z;
    int m0 = blockIdx.y * 128;
    int n0 = blockIdx.x * 256;
    const __half* Ag = d_Abf + (size_t)m0*KSEG;
    const __half* Bg = d_Bbf + ((size_t)b*NP + n0)*KSEG;

    auto issue = [&](int kc, int buf) {
        uint32_t sA = sb + buf*STAGE;
        uint32_t sB = sA + ABUF;
        int ka = kc * KCHUNK;
#pragma unroll
        for (int l = 0; l < 4; l++) {
            int seg = tid + l*256;
            int row = seg >> 3, c = seg & 7;
            cp16(sA + row*AROW + c*16, Ag + (size_t)row*KSEG + ka + c*8);
        }
#pragma unroll
        for (int l = 0; l < 8; l++) {
            int seg = tid + l*256;
            int row = seg >> 3, c = seg & 7;
            cp16(sB + row*AROW + c*16, Bg + (size_t)row*KSEG + ka + c*8);
        }
        CP_COMMIT();
    };

    issue(0, 0);
    issue(1, 1);
    issue(2, 2);

    float c[4][8][4];
#pragma unroll
    for (int mi = 0; mi < 4; mi++)
#pragma unroll
        for (int nj = 0; nj < 8; nj++)
#pragma unroll
            for (int q = 0; q < 4; q++) c[mi][nj][q] = 0.f;

    int wm = w & 1, wn = w >> 1;
    int a_row = (lane & 15), a_kh = (lane >> 4) * 16;
    int b_off = ((lane & 7) + ((lane >> 4) & 1)*8)*AROW + ((lane >> 3) & 1)*16;

    int buf = 0;
    for (int kc = 0; kc < NCHUNK; kc++) {
        CP_WAIT2();
        __syncthreads();
        uint32_t sA = sb + buf*STAGE          + (wm*64 + a_row)*AROW + a_kh;
        uint32_t sB = sb + buf*STAGE + ABUF   + (wn*64)*AROW + b_off;
#pragma unroll
        for (int ks = 0; ks < 4; ks++) {
            uint32_t af[4][4], bf[8][2];
#pragma unroll
            for (int mi = 0; mi < 4; mi++)
                ldm_x4(af[mi], sA + mi*16*AROW + ks*32);
#pragma unroll
            for (int j = 0; j < 4; j++) {
                uint32_t q[4];
                ldm_x4(q, sB + j*16*AROW + ks*32);
                bf[2*j][0] = q[0]; bf[2*j][1] = q[1];
                bf[2*j+1][0] = q[2]; bf[2*j+1][1] = q[3];
            }
#pragma unroll
            for (int mi = 0; mi < 4; mi++)
#pragma unroll
                for (int nj = 0; nj < 8; nj++)
                    mma_f16(c[mi][nj], af[mi], bf[nj]);
        }
        if (kc + 3 < NCHUNK) issue(kc + 3, (kc + 3) & 3);
        else CP_COMMIT();
        buf = (buf + 1) & 3;
    }

    // epilogue: exp + store unnormalized E + deterministic row partial sums
    __half* Eb = d_Ebf + (size_t)b*MP*KSEG;
    int gid = lane >> 2, tig = lane & 3;
#pragma unroll
    for (int mi = 0; mi < 4; mi++) {
        int gm = m0 + wm*64 + mi*16 + gid;
        float s0 = 0.f, s1 = 0.f;
#pragma unroll
        for (int nj = 0; nj < 8; nj++) {
            int gn = n0 + wn*64 + nj*8 + tig*2;
            bool nok = gn < NN;
            float e0 = nok ? __expf(c[mi][nj][0]) : 0.f;
            float e1 = nok ? __expf(c[mi][nj][1]) : 0.f;
            float e2 = nok ? __expf(c[mi][nj][2]) : 0.f;
            float e3 = nok ? __expf(c[mi][nj][3]) : 0.f;
            s0 += e0 + e1;
            s1 += e2 + e3;
            if (nok) {
                if (gm < NN)
                    *(__half2*)&Eb[(size_t)gm*KSEG + gn]     = __floats2half2_rn(e0, e1);
                if (gm + 8 < NN)
                    *(__half2*)&Eb[(size_t)(gm+8)*KSEG + gn] = __floats2half2_rn(e2, e3);
            }
        }
        s0 += __shfl_xor_sync(0xffffffffu, s0, 1);
        s0 += __shfl_xor_sync(0xffffffffu, s0, 2);
        s1 += __shfl_xor_sync(0xffffffffu, s1, 1);
        s1 += __shfl_xor_sync(0xffffffffu, s1, 2);
        if (tig == 0) {
            rs[wm*64 + mi*16 + gid][wn]     = s0;
            rs[wm*64 + mi*16 + gid + 8][wn] = s1;
        }
    }
    __syncthreads();
    if (tid < 128) {
        float tot = (rs[tid][0] + rs[tid][1]) + (rs[tid][2] + rs[tid][3]);
        d_psum[((size_t)b*8 + blockIdx.x)*MP + m0 + tid] = tot;
    }
}

// ---- K6a: hcat[:,64:128] = Adj @ h   (fp16 mma, tile 128x64) -----------------
#define AH_BROW 144
#define AH_BBUF (64*AH_BROW)               // 9216
#define AH_STAGE (ABUF + AH_BBUF)          // 27648
#define AH_SMEM (2*AH_STAGE)               // 55296

__global__ void __launch_bounds__(256) k_Ahmma() {
    extern __shared__ __align__(16) char smem[];
    uint32_t sb = smem_u32(smem);
    int tid = threadIdx.x, lane = tid & 31, w = tid >> 5;
    int b = blockIdx.y;
    int m0 = blockIdx.x * 128;
    const __half* Ag = d_Adjbf + (size_t)m0*KSEG;
    const __half* Bg = d_hcat + (size_t)b*MP*128;

    auto issue = [&](int kc, int buf) {
        uint32_t sA = sb + buf*AH_STAGE;
        uint32_t sB = sA + ABUF;
#pragma unroll
        for (int l = 0; l < 4; l++) {
            int seg = tid + l*256;
            int row = seg >> 3, c = seg & 7;
            cp16(sA + row*AROW + c*16, Ag + (size_t)row*KSEG + kc*KCHUNK + c*8);
        }
#pragma unroll
        for (int l = 0; l < 2; l++) {
            int seg = tid + l*256;
            int row = seg >> 3, c = seg & 7;
            cp16(sB + row*AH_BROW + c*16, Bg + (size_t)(kc*KCHUNK + row)*128 + c*8);
        }
        CP_COMMIT();
    };

    issue(0, 0);
    issue(1, 1);

    float c[2][4][4];
#pragma unroll
    for (int mi = 0; mi < 2; mi++)
#pragma unroll
        for (int nj = 0; nj < 4; nj++)
#pragma unroll
            for (int q = 0; q < 4; q++) c[mi][nj][q] = 0.f;

    int wm = w >> 1, wn = w & 1;
    for (int kc = 0; kc < NCHUNK; kc++) {
        CP_WAIT1();
        __syncthreads();
        int buf = kc & 1;
        uint32_t sA = sb + buf*AH_STAGE + (wm*32 + (lane & 15))*AROW + (lane >> 4)*16;
        uint32_t sB = sb + buf*AH_STAGE + ABUF;
#pragma unroll
        for (int ks = 0; ks < 4; ks++) {
            uint32_t af[2][4], bf[4][2];
#pragma unroll
            for (int mi = 0; mi < 2; mi++)
                ldm_x4(af[mi], sA + mi*16*AROW + ks*32);
#pragma unroll
            for (int nj = 0; nj < 4; nj++)
                ldm_x2_t(bf[nj], sB + (ks*16 + (lane & 15))*AH_BROW + (wn*32 + nj*8)*2);
#pragma unroll
            for (int mi = 0; mi < 2; mi++)
#pragma unroll
                for (int nj = 0; nj < 4; nj++)
                    mma_f16(c[mi][nj], af[mi], bf[nj]);
        }
        __syncthreads();
        if (kc + 2 < NCHUNK) issue(kc + 2, buf);
        else CP_COMMIT();
    }

    int gid = lane >> 2, tig = lane & 3;
#pragma unroll
    for (int mi = 0; mi < 2; mi++) {
        int gm = m0 + wm*32 + mi*16 + gid;
#pragma unroll
        for (int nj = 0; nj < 4; nj++) {
            int gn = wn*32 + nj*8 + tig*2;
            if (gm < NN)
                *(__half2*)&d_hcat[((size_t)b*MP + gm)*128 + 64 + gn] =
                    __halves2half2(__float2half_rn(c[mi][nj][0]), __float2half_rn(c[mi][nj][1]));
            if (gm + 8 < NN)
                *(__half2*)&d_hcat[((size_t)b*MP + gm + 8)*128 + 64 + gn] =
                    __halves2half2(__float2half_rn(c[mi][nj][2]), __float2half_rn(c[mi][nj][3]));
        }
    }
}

// ---- K6b: xg = softmax-normalized E @ hcat  (fp16 mma, tile 128x128) ---------
#define XG_BROW 272
#define XG_BBUF (64*XG_BROW)               // 17408
#define XG_STAGE (ABUF + XG_BBUF)          // 35840
#define XG_SMEM (2*XG_STAGE)               // 71680

__global__ void __launch_bounds__(256) k_xgmma() {
    extern __shared__ __align__(16) char smem[];
    __shared__ float invS[128];
    uint32_t sb = smem_u32(smem);
    int tid = threadIdx.x, lane = tid & 31, w = tid >> 5;
    int b = blockIdx.y;
    int m0 = blockIdx.x * 128;
    const __half* Ag = d_Ebf + ((size_t)b*MP + m0)*KSEG;
    const __half* Bg = d_hcat + (size_t)b*MP*128;

    auto issue = [&](int kc, int buf) {
        uint32_t sA = sb + buf*XG_STAGE;
        uint32_t sB = sA + ABUF;
#pragma unroll
        for (int l = 0; l < 4; l++) {
            int seg = tid + l*256;
            int row = seg >> 3, c = seg & 7;
            cp16(sA + row*AROW + c*16, Ag + (size_t)row*KSEG + kc*KCHUNK + c*8);
        }
#pragma unroll
        for (int l = 0; l < 4; l++) {
            int seg = tid + l*256;
            int row = seg >> 4, c = seg & 15;
            cp16(sB + row*XG_BROW + c*16, Bg + (size_t)(kc*KCHUNK + row)*128 + c*8);
        }
        CP_COMMIT();
    };

    issue(0, 0);
    issue(1, 1);

    if (tid < 128) {
        float s = 0.f;
#pragma unroll
        for (int nb = 0; nb < 8; nb++)
            s += d_psum[((size_t)b*8 + nb)*MP + m0 + tid];
        invS[tid] = 1.f / s;
    }

    float c[2][8][4];
#pragma unroll
    for (int mi = 0; mi < 2; mi++)
#pragma unroll
        for (int nj = 0; nj < 8; nj++)
#pragma unroll
            for (int q = 0; q < 4; q++) c[mi][nj][q] = 0.f;

    int wm = w >> 1, wn = w & 1;
    for (int kc = 0; kc < NCHUNK; kc++) {
        CP_WAIT1();
        __syncthreads();
        int buf = kc & 1;
        uint32_t sA = sb + buf*XG_STAGE + (wm*32 + (lane & 15))*AROW + (lane >> 4)*16;
        uint32_t sB = sb + buf*XG_STAGE + ABUF;
#pragma unroll
        for (int ks = 0; ks < 4; ks++) {
            uint32_t af[2][4], bf[8][2];
#pragma unroll
            for (int mi = 0; mi < 2; mi++)
                ldm_x4(af[mi], sA + mi*16*AROW + ks*32);
#pragma unroll
            for (int nj = 0; nj < 8; nj++)
                ldm_x2_t(bf[nj], sB + (ks*16 + (lane & 15))*XG_BROW + (wn*64 + nj*8)*2);
#pragma unroll
            for (int mi = 0; mi < 2; mi++)
#pragma unroll
                for (int nj = 0; nj < 8; nj++)
                    mma_f16(c[mi][nj], af[mi], bf[nj]);
        }
        __syncthreads();
        if (kc + 2 < NCHUNK) issue(kc + 2, buf);
        else CP_COMMIT();
    }

    int gid = lane >> 2, tig = lane & 3;
#pragma unroll
    for (int mi = 0; mi < 2; mi++) {
        int lr = wm*32 + mi*16 + gid;
        int gm = m0 + lr;
        float inv0 = invS[lr], inv1 = invS[lr + 8];
#pragma unroll
        for (int nj = 0; nj < 8; nj++) {
            int gn = wn*64 + nj*8 + tig*2;
            if (gm < NN)
                *(float2*)&d_xg[((size_t)b*NN + gm)*128 + gn] =
                    make_float2(c[mi][nj][0]*inv0, c[mi][nj][1]*inv0);
            if (gm + 8 < NN)
                *(float2*)&d_xg[((size_t)b*NN + gm + 8)*128 + gn] =
                    make_float2(c[mi][nj][2]*inv1, c[mi][nj][3]*inv1);
        }
    }
}

// ---------------- K7: weights = emb @ wp_flat (fp32) --------------------------
__global__ void k_wn(const float* __restrict__ emb, const float* __restrict__ wp) {
    __shared__ float Es[64][16];
    __shared__ float Ws[16][128];
    int n0 = blockIdx.y*64, c0 = blockIdx.x*128;
    int tid = threadIdx.x;
    for (int i=tid;i<1024;i+=256){ int r=i>>4, d=i&15; int n=n0+r; Es[r][d] = (n<NN)? emb[(size_t)n*16+d] : 0.f; }
    for (int i=tid;i<2048;i+=256){ int kr=i>>7, c=i&127; Ws[kr][c] = wp[(size_t)kr*8192 + c0 + c]; }
    __syncthreads();
    int ty=tid>>4, tx=tid&15;
    float acc[4][8];
#pragma unroll
    for (int i=0;i<4;i++)
#pragma unroll
        for (int j=0;j<8;j++) acc[i][j]=0.f;
#pragma unroll
    for (int d=0; d<16; d++){
        float ev[4], wv[8];
#pragma unroll
        for (int i=0;i<4;i++) ev[i]=Es[ty*4+i][d];
#pragma unroll
        for (int j=0;j<8;j++) wv[j]=Ws[d][tx*8+j];
#pragma unroll
        for (int i=0;i<4;i++)
#pragma unroll
            for (int j=0;j<8;j++) acc[i][j] += ev[i]*wv[j];
    }
#pragma unroll
    for (int i=0;i<4;i++){
        int n = n0+ty*4+i;
        if (n >= NN) continue;
#pragma unroll
        for (int j=0;j<8;j++)
            d_wn[(size_t)n*8192 + c0 + tx*8 + j] = acc[i][j];
    }
}

// ---------------- K8: g = xg @ W_n + bias_n -> gcat fp16 [gh|gl|gh] -----------
__global__ void k_g(const float* __restrict__ emb, const float* __restrict__ bp) {
    __shared__ float Wns[8192];
    __shared__ float xgs[8][128];
    __shared__ float bias_s[64];
    __shared__ float es[16];
    int n = blockIdx.x, tid = threadIdx.x;
    if (tid < 16) es[tid] = emb[(size_t)n*16+tid];
    for (int i=tid;i<8192;i+=256) Wns[i] = d_wn[(size_t)n*8192 + i];
    for (int i=tid;i<1024;i+=256){
        int b=i>>7, ki=i&127;
        xgs[b][ki] = d_xg[((size_t)b*NN+n)*128 + ki];
    }
    __syncthreads();
    if (tid < 64) {
        float bv = 0.f;
#pragma unroll
        for (int d=0; d<16; d++) bv += es[d]*bp[d*64+tid];
        bias_s[tid] = bv;
    }
    __syncthreads();
    int o = tid & 63;
#pragma unroll
    for (int rep=0; rep<2; rep++){
        int b = (tid>>6) + rep*4;
        float acc = bias_s[o];
#pragma unroll 8
        for (int ki=0; ki<128; ki++) acc += xgs[b][ki]*Wns[ki*64+o];
        __half gh = __float2half_rn(acc);
        __half gl = __float2half_rn(acc - __half2float(gh));
        size_t base = ((size_t)b*NN + n)*192;
        d_gcat[base + o]       = gh;
        d_gcat[base + 64 + o]  = gl;
        d_gcat[base + 128 + o] = gh;
    }
}

// ---------------- K9a: WoutT = [Wh;Wh;Wl] fp16 --------------------------------
__global__ void k_wprep(const float* __restrict__ Wout) {
    int o = blockIdx.x*256 + threadIdx.x;
    int h = blockIdx.y;
    float w = Wout[(size_t)o*64 + h];
    __half wh = __float2half_rn(w);
    __half wl = __float2half_rn(w - __half2float(wh));
    d_WoutT[(size_t)h*OUTC + o]         = wh;
    d_WoutT[(size_t)(64+h)*OUTC + o]    = wh;
    d_WoutT[(size_t)(128+h)*OUTC + o]   = wl;
}

// ---------------- K9b: out = 0.1*tanh(gcat @ WoutT + b_out) -------------------
#define MT 5
#define O_AROW 400
#define O_ABUF (128*O_AROW)    // 51200
#define O_BROW 272
#define O_BBUF (192*O_BROW)    // 52224
#define O_SMEM (O_BBUF + 2*O_ABUF + 512)   // 155136

__global__ void __launch_bounds__(256) k_outmma(const float* __restrict__ bout,
                                                float* __restrict__ out) {
    extern __shared__ __align__(16) char smem[];
    uint32_t sb = smem_u32(smem);
    float* boS = (float*)(smem + O_BBUF + 2*O_ABUF);
    int tid = threadIdx.x, lane = tid & 31, w = tid >> 5;
    int n0 = blockIdx.x * 128;
    int mg = blockIdx.y * MT;

#pragma unroll
    for (int l = 0; l < 12; l++) {
        int seg = tid + l*256;
        int row = seg >> 4, c = seg & 15;
        cp16(sb + row*O_BROW + c*16, d_WoutT + (size_t)row*OUTC + n0 + c*8);
    }
    CP_COMMIT();
    if (tid < 128) boS[tid] = bout[n0 + tid];

    auto issueA = [&](int i, int buf) {
        uint32_t sA = sb + O_BBUF + buf*O_ABUF;
        int m0 = (mg + i)*128;
#pragma unroll
        for (int l = 0; l < 12; l++) {
            int seg = tid + l*256;
            int row = seg / 24, c = seg % 24;
            cp16(sA + row*O_AROW + c*16, d_gcat + (size_t)(m0+row)*192 + c*8);
        }
        CP_COMMIT();
    };
    issueA(0, 0);

    int wm = w >> 1, wn = w & 1;
    int gid = lane >> 2, tig = lane & 3;

    for (int i = 0; i < MT; i++) {
        CP_WAIT0();
        __syncthreads();
        if (i + 1 < MT) issueA(i + 1, (i + 1) & 1);

        uint32_t sA = sb + O_BBUF + (i & 1)*O_ABUF + (wm*32 + (lane & 15))*O_AROW + (lane >> 4)*16;
        uint32_t sB = sb;
        float c[2][8][4];
#pragma unroll
        for (int mi = 0; mi < 2; mi++)
#pragma unroll
            for (int nj = 0; nj < 8; nj++)
#pragma unroll
                for (int q = 0; q < 4; q++) c[mi][nj][q] = 0.f;

#pragma unroll
        for (int kk = 0; kk < 12; kk++) {
            uint32_t af[2][4], bf[8][2];
#pragma unroll
            for (int mi = 0; mi < 2; mi++)
                ldm_x4(af[mi], sA + mi*16*O_AROW + kk*32);
#pragma unroll
            for (int nj = 0; nj < 8; nj++)
                ldm_x2_t(bf[nj], sB + (kk*16 + (lane & 15))*O_BROW + (wn*64 + nj*8)*2);
#pragma unroll
            for (int mi = 0; mi < 2; mi++)
#pragma unroll
                for (int nj = 0; nj < 8; nj++)
                    mma_f16(c[mi][nj], af[mi], bf[nj]);
        }

        int m0 = (mg + i)*128;
#pragma unroll
        for (int mi = 0; mi < 2; mi++) {
            int gm = m0 + wm*32 + mi*16 + gid;
#pragma unroll
            for (int nj = 0; nj < 8; nj++) {
                int cn = wn*64 + nj*8 + tig*2;
                int gn = n0 + cn;
                float b0 = boS[cn], b1 = boS[cn+1];
                float2 v0 = make_float2(0.1f*fast_tanh(c[mi][nj][0] + b0), 0.1f*fast_tanh(c[mi][nj][1] + b1));
                float2 v1 = make_float2(0.1f*fast_tanh(c[mi][nj][2] + b0), 0.1f*fast_tanh(c[mi][nj][3] + b1));
                *(float2*)&out[(size_t)gm*OUTC + gn]       = v0;
                *(float2*)&out[(size_t)(gm+8)*OUTC + gn]   = v1;
            }
        }
        __syncthreads();
    }
}

// ---------------- launch: fork independent kernels onto a side stream ---------
extern "C" void kernel_launch(void* const* d_in, const int* in_sizes, int n_in,
                              void* d_out, int out_size) {
    const float* z    = (const float*)d_in[0];
    const float* Win  = (const float*)d_in[1];
    const float* bin  = (const float*)d_in[2];
    const float* Wout = (const float*)d_in[3];
    const float* bout = (const float*)d_in[4];
    const float* emb  = (const float*)d_in[5];
    const float* wp   = (const float*)d_in[6];
    const float* bp   = (const float*)d_in[7];
    const float* w1   = (const float*)d_in[8];
    const float* w2   = (const float*)d_in[9];
    const float* vsM  = (const float*)d_in[10];
    const float* bs   = (const float*)d_in[11];
    float* out = (float*)d_out;
    (void)in_sizes; (void)n_in; (void)out_size;

    cudaFuncSetAttribute(k_mma,    cudaFuncAttributeMaxDynamicSharedMemorySize, SMEM_MMA);
    cudaFuncSetAttribute(k_Ahmma,  cudaFuncAttributeMaxDynamicSharedMemorySize, AH_SMEM);
    cudaFuncSetAttribute(k_xgmma,  cudaFuncAttributeMaxDynamicSharedMemorySize, XG_SMEM);
    cudaFuncSetAttribute(k_outmma, cudaFuncAttributeMaxDynamicSharedMemorySize, O_SMEM);

    // fresh per-call stream/events (deterministic, no static state; not destroyed
    // because the surrounding graph capture still references them on return)
    cudaStream_t s2;
    cudaStreamCreateWithFlags(&s2, cudaStreamNonBlocking);
    cudaEvent_t evFork, evAvs, evH, evS2;
    cudaEventCreateWithFlags(&evFork, cudaEventDisableTiming);
    cudaEventCreateWithFlags(&evAvs,  cudaEventDisableTiming);
    cudaEventCreateWithFlags(&evH,    cudaEventDisableTiming);
    cudaEventCreateWithFlags(&evS2,   cudaEventDisableTiming);

    // fork side stream from the (capturing) default stream
    cudaEventRecord(evFork, 0);
    cudaStreamWaitEvent(s2, evFork, 0);

    // side stream: input-only producers
    k_Avs<<<dim3(MP/256, MP), 256, 0, s2>>>(vsM);
    cudaEventRecord(evAvs, s2);
    k_adj<<<NN, 256, 0, s2>>>(emb);
    k_wprep<<<dim3(OUTC/256, 64), 256, 0, s2>>>(Wout);
    k_wn<<<dim3(8192/128, (NN+63)/64), 256, 0, s2>>>(emb, wp);

    // main stream: critical path
    k_hidden<<<(NB*NN)/16, 256>>>(z, Win, bin, w1, w2);
    cudaEventRecord(evH, 0);
    k_T2<<<dim3(NP/32, NP/32), 256>>>(bs);
    cudaStreamWaitEvent(0, evAvs, 0);
    k_mma<<<dim3(NP/256, MP/128, NB), 256, SMEM_MMA>>>();

    // side stream: Ahmma needs {adj (program order on s2), hidden (evH)}
    cudaStreamWaitEvent(s2, evH, 0);
    k_Ahmma<<<dim3(MP/128, NB), 256, AH_SMEM, s2>>>();
    cudaEventRecord(evS2, s2);

    // join and finish on main stream
    cudaStreamWaitEvent(0, evS2, 0);
    k_xgmma<<<dim3(MP/128, NB), 256, XG_SMEM>>>();
    k_g<<<NN, 256>>>(emb, bp);
    k_outmma<<<dim3(OUTC/128, (NB*NN)/(128*MT)), 256, O_SMEM>>>(bout, out);
}

// round 11
// speedup vs baseline: 5.1374x; 1.0051x over previous
#include <cuda_runtime.h>
#include <cuda_fp16.h>
#include <math.h>
#include <stdint.h>

#define NB 8
#define NN 2000
#define HH 64
#define DD 16
#define OUTC 4096

// padded GEMM dims
#define MP 2048
#define NP 2048
#define KSEG 2048            // K for the big GEMM (T_hi only)
#define KCHUNK 64
#define NCHUNK (KSEG/KCHUNK) // 32

// ---------------- scratch (static __device__ — zero-initialized) --------------
__device__ float d_e1 [NB*NN];
__device__ float d_e2 [NB*NN];
__device__ __align__(16) float d_xg [(size_t)NB*NN*128];  // [b][node][128] fp32
__device__ float d_wn [(size_t)NN*128*HH];                // fp32 (accuracy-critical)
__device__ float d_psum[(size_t)NB*16*MP];                // per-(batch,nblk,row) exp sums
// fp16 operands (pads never written -> stay zero from module init)
__device__ __align__(16) __half d_Abf  [(size_t)MP*KSEG];        // fp16(vs)
__device__ __align__(16) __half d_Bbf  [(size_t)NB*NP*KSEG];     // T_hi, [b][n][k]
__device__ __align__(16) __half d_Ebf  [(size_t)NB*MP*KSEG];     // exp(L) unnormalized
__device__ __align__(16) __half d_Adjbf[(size_t)MP*KSEG];        // fp16(A adj), [m][k]
__device__ __align__(16) __half d_hcat [(size_t)NB*MP*128];      // [b][node][0:64=h,64:128=Ah]
__device__ __align__(16) __half d_gcat [(size_t)NB*NN*192];      // [m][gh|gl|gh]
__device__ __align__(16) __half d_WoutT[(size_t)192*OUTC];       // [Wh;Wh;Wl] rows k, cols o

// ======================= portable PTX helpers (base sm_103 OK) ================
__device__ __forceinline__ uint32_t smem_u32(const void* p) {
    uint32_t a;
    asm("{ .reg .u64 t; cvta.to.shared.u64 t, %1; cvt.u32.u64 %0, t; }" : "=r"(a) : "l"(p));
    return a;
}
__device__ __forceinline__ void cp16(uint32_t s, const void* g) {
    asm volatile("cp.async.cg.shared.global [%0], [%1], 16;" :: "r"(s), "l"(g));
}
#define CP_COMMIT() asm volatile("cp.async.commit_group;" ::: "memory")
#define CP_WAIT1()  asm volatile("cp.async.wait_group 1;" ::: "memory")
#define CP_WAIT2()  asm volatile("cp.async.wait_group 2;" ::: "memory")
#define CP_WAIT0()  asm volatile("cp.async.wait_group 0;" ::: "memory")
__device__ __forceinline__ void ldm_x4(uint32_t* r, uint32_t addr) {
    asm volatile("ldmatrix.sync.aligned.m8n8.x4.shared.b16 {%0,%1,%2,%3}, [%4];"
        : "=r"(r[0]), "=r"(r[1]), "=r"(r[2]), "=r"(r[3]) : "r"(addr));
}
__device__ __forceinline__ void ldm_x2(uint32_t* r, uint32_t addr) {
    asm volatile("ldmatrix.sync.aligned.m8n8.x2.shared.b16 {%0,%1}, [%2];"
        : "=r"(r[0]), "=r"(r[1]) : "r"(addr));
}
__device__ __forceinline__ void ldm_x2_t(uint32_t* r, uint32_t addr) {
    asm volatile("ldmatrix.sync.aligned.m8n8.x2.trans.shared.b16 {%0,%1}, [%2];"
        : "=r"(r[0]), "=r"(r[1]) : "r"(addr));
}
__device__ __forceinline__ void mma_f16(float* c, const uint32_t* a, const uint32_t* b) {
    asm volatile(
        "mma.sync.aligned.m16n8k16.row.col.f32.f16.f16.f32 "
        "{%0,%1,%2,%3}, {%4,%5,%6,%7}, {%8,%9}, {%0,%1,%2,%3};"
        : "+f"(c[0]), "+f"(c[1]), "+f"(c[2]), "+f"(c[3])
        : "r"(a[0]), "r"(a[1]), "r"(a[2]), "r"(a[3]), "r"(b[0]), "r"(b[1]));
}
// fast accurate tanh: 1 - 2/(e^{2x}+1); __expf rel err ~1e-6 (saturates correctly)
__device__ __forceinline__ float fast_tanh(float x) {
    float t = __expf(2.f*x);
    return 1.f - __fdividef(2.f, t + 1.f);
}

// ---------------- K1: h = relu(z@W_in^T + b_in) -> hcat[:,0:64] fp16 ----------
__global__ void __launch_bounds__(256) k_hidden(const float* __restrict__ z,
                         const float* __restrict__ Win,
                         const float* __restrict__ bin, const float* __restrict__ w1,
                         const float* __restrict__ w2) {
    __shared__ float Ws[4096];        // transposed: Ws[c*64+h]
    __shared__ float zs[4][64];
    __shared__ float red1[4][2], red2[4][2];
    __shared__ float binS[64], w1S[64], w2S[64];
    int tid = threadIdx.x;
    for (int i = tid; i < 4096; i += 256) {
        int h = i >> 6, c = i & 63;
        Ws[c*64 + h] = Win[i];
    }
    if (tid < 64) { binS[tid] = bin[tid]; w1S[tid] = w1[tid]; w2S[tid] = w2[tid]; }
    __syncthreads();
    int slice = tid >> 6, o = tid & 63;
    int wihalf = (tid >> 5) & 1;
#pragma unroll 1
    for (int it = 0; it < 4; it++) {
        int row = blockIdx.x*16 + it*4 + slice;
        zs[slice][o] = z[(size_t)row*64 + o];
        __syncthreads();
        float acc = binS[o];
#pragma unroll 16
        for (int c = 0; c < 64; c++) acc += zs[slice][c] * Ws[c*64 + o];
        float hv = fmaxf(acc, 0.f);
        int b = row / NN, node = row % NN;
        d_hcat[((size_t)b*MP + node)*128 + o] = __float2half_rn(hv);
        float p1 = hv * w1S[o], p2 = hv * w2S[o];
#pragma unroll
        for (int s = 16; s > 0; s >>= 1) {
            p1 += __shfl_down_sync(0xffffffffu, p1, s);
            p2 += __shfl_down_sync(0xffffffffu, p2, s);
        }
        if ((tid & 31) == 0) { red1[slice][wihalf] = p1; red2[slice][wihalf] = p2; }
        __syncthreads();
        if (o == 0) {
            d_e1[row] = red1[slice][0] + red1[slice][1];
            d_e2[row] = red2[slice][0] + red2[slice][1];
        }
    }
}

// ---------------- K2: Adj = softmax(relu(emb@emb^T)) -> fp16 ------------------
__global__ void k_adj(const float* __restrict__ emb) {
    __shared__ float buf[NN];
    __shared__ float red[256];
    __shared__ float ei[16];
    int i = blockIdx.x, tid = threadIdx.x;
    if (tid < 16) ei[tid] = emb[i*16 + tid];
    __syncthreads();
    float mx = -1e30f;
    for (int j = tid; j < NN; j += 256) {
        const float* er = emb + (size_t)j*16;
        float dsum = 0.f;
#pragma unroll
        for (int d = 0; d < 16; d++) dsum += ei[d]*er[d];
        dsum = fmaxf(dsum, 0.f);
        buf[j] = dsum;
        mx = fmaxf(mx, dsum);
    }
    red[tid] = mx; __syncthreads();
    for (int s = 128; s > 0; s >>= 1) { if (tid < s) red[tid] = fmaxf(red[tid], red[tid+s]); __syncthreads(); }
    mx = red[0]; __syncthreads();
    float sum = 0.f;
    for (int j = tid; j < NN; j += 256) { float v = __expf(buf[j]-mx); buf[j] = v; sum += v; }
    red[tid] = sum; __syncthreads();
    for (int s = 128; s > 0; s >>= 1) { if (tid < s) red[tid] += red[tid+s]; __syncthreads(); }
    float inv = 1.f/red[0];
    for (int j = tid; j < NN; j += 256)
        d_Adjbf[(size_t)i*KSEG + j] = __float2half_rn(buf[j]*inv);
}

// ---- K3a: A = fp16(vs) -------------------------------------------------------
__global__ void k_Avs(const float* __restrict__ vsM) {
    int k = blockIdx.x*256 + threadIdx.x;
    int m = blockIdx.y;
    float t = (m < NN && k < NN) ? vsM[(size_t)m*NN + k] : 0.f;
    d_Abf[(size_t)m*KSEG + k] = __float2half_rn(t);
}

// ---- K3b: B[b][n][k] = fp16(sigmoid(e1[b,k]*e2[b,n] + bs[k,n])) --------------
__global__ void k_T2(const float* __restrict__ bs) {
    __shared__ float sbs[32][33];
    int k0 = blockIdx.x*32, n0 = blockIdx.y*32;
    int tid = threadIdx.x;
#pragma unroll
    for (int l = 0; l < 4; l++) {
        int kk = (tid >> 5) + l*8, nn = tid & 31;
        int gk = k0 + kk, gn = n0 + nn;
        sbs[kk][nn] = (gk < NN && gn < NN) ? bs[(size_t)gk*NN + gn] : 0.f;
    }
    __syncthreads();
    int nnl = tid >> 4;
    int kl  = (tid & 15) * 2;
#pragma unroll
    for (int half = 0; half < 2; half++) {
        int nn = nnl + half*16;
        int gn = n0 + nn;
        bool nok = gn < NN;
        int gk0 = k0 + kl, gk1 = gk0 + 1;
        float b0 = sbs[kl][nn], b1 = sbs[kl+1][nn];
#pragma unroll
        for (int b = 0; b < NB; b++) {
            float v0 = 0.f, v1 = 0.f;
            if (nok) {
                float e2v = d_e2[b*NN + gn];
                if (gk0 < NN) { float x = d_e1[b*NN + gk0]*e2v + b0; v0 = 1.f/(1.f + __expf(-x)); }
                if (gk1 < NN) { float x = d_e1[b*NN + gk1]*e2v + b1; v1 = 1.f/(1.f + __expf(-x)); }
            }
            size_t base = ((size_t)b*NP + gn)*KSEG + gk0;
            *(__half2*)&d_Bbf[base] = __halves2half2(__float2half_rn(v0), __float2half_rn(v1));
        }
    }
}

// ---- K4: L[b]=A@B^T; CTA tile 128x128, 3-stage, 2 CTAs/SM ---------------------
// epilogue: exp(L) -> d_Ebf fp16 + per-row partial sums (16 n-blocks)
#define AROW 144
#define TBUF 18432                       // one 128x64 fp16 tile, padded
#define STAGE2 (2*TBUF)                  // A+B per stage = 36864
#define SMEM_MMA (3*STAGE2)              // 110592

__global__ void __launch_bounds__(256, 2) k_mma() {
    extern __shared__ __align__(16) char smem[];
    __shared__ float rs[128][2];
    uint32_t sb = smem_u32(smem);
    int tid = threadIdx.x, lane = tid & 31, w = tid >> 5;
    int b  = blockIdx.z;
    int m0 = blockIdx.y * 128;
    int n0 = blockIdx.x * 128;
    const __half* Ag = d_Abf + (size_t)m0*KSEG;
    const __half* Bg = d_Bbf + ((size_t)b*NP + n0)*KSEG;

    auto issue = [&](int kc, int buf) {
        uint32_t sA = sb + buf*STAGE2;
        uint32_t sB = sA + TBUF;
        int ka = kc * KCHUNK;
#pragma unroll
        for (int l = 0; l < 4; l++) {
            int seg = tid + l*256;
            int row = seg >> 3, c = seg & 7;
            cp16(sA + row*AROW + c*16, Ag + (size_t)row*KSEG + ka + c*8);
        }
#pragma unroll
        for (int l = 0; l < 4; l++) {
            int seg = tid + l*256;
            int row = seg >> 3, c = seg & 7;
            cp16(sB + row*AROW + c*16, Bg + (size_t)row*KSEG + ka + c*8);
        }
        CP_COMMIT();
    };

    issue(0, 0);
    issue(1, 1);
    issue(2, 2);

    float c[2][8][4];
#pragma unroll
    for (int mi = 0; mi < 2; mi++)
#pragma unroll
        for (int nj = 0; nj < 8; nj++)
#pragma unroll
            for (int q = 0; q < 4; q++) c[mi][nj][q] = 0.f;

    int wm = w >> 1, wn = w & 1;          // warp tile 32x64
    int a_row = (lane & 15), a_kh = (lane >> 4) * 16;
    int b_off = ((lane & 7) + ((lane >> 4) & 1)*8)*AROW + ((lane >> 3) & 1)*16;

    int buf = 0;
    for (int kc = 0; kc < NCHUNK; kc++) {
        CP_WAIT2();
        __syncthreads();
        uint32_t sA = sb + buf*STAGE2        + (wm*32 + a_row)*AROW + a_kh;
        uint32_t sB = sb + buf*STAGE2 + TBUF + (wn*64)*AROW + b_off;
#pragma unroll
        for (int ks = 0; ks < 4; ks++) {
            uint32_t af[2][4], bf[8][2];
#pragma unroll
            for (int mi = 0; mi < 2; mi++)
                ldm_x4(af[mi], sA + mi*16*AROW + ks*32);
#pragma unroll
            for (int j = 0; j < 4; j++) {
                uint32_t q[4];
                ldm_x4(q, sB + j*16*AROW + ks*32);
                bf[2*j][0] = q[0]; bf[2*j][1] = q[1];
                bf[2*j+1][0] = q[2]; bf[2*j+1][1] = q[3];
            }
#pragma unroll
            for (int mi = 0; mi < 2; mi++)
#pragma unroll
                for (int nj = 0; nj < 8; nj++)
                    mma_f16(c[mi][nj], af[mi], bf[nj]);
        }
        __syncthreads();
        if (kc + 3 < NCHUNK) issue(kc + 3, buf);
        else CP_COMMIT();
        buf = (buf == 2) ? 0 : buf + 1;
    }

    // epilogue: exp + store unnormalized E + deterministic row partial sums
    __half* Eb = d_Ebf + (size_t)b*MP*KSEG;
    int gid = lane >> 2, tig = lane & 3;
#pragma unroll
    for (int mi = 0; mi < 2; mi++) {
        int gm = m0 + wm*32 + mi*16 + gid;
        float s0 = 0.f, s1 = 0.f;
#pragma unroll
        for (int nj = 0; nj < 8; nj++) {
            int gn = n0 + wn*64 + nj*8 + tig*2;
            bool nok = gn < NN;          // NN even => gn<NN implies gn+1<NN
            float e0 = nok ? __expf(c[mi][nj][0]) : 0.f;
            float e1 = nok ? __expf(c[mi][nj][1]) : 0.f;
            float e2 = nok ? __expf(c[mi][nj][2]) : 0.f;
            float e3 = nok ? __expf(c[mi][nj][3]) : 0.f;
            s0 += e0 + e1;
            s1 += e2 + e3;
            if (nok) {
                if (gm < NN)
                    *(__half2*)&Eb[(size_t)gm*KSEG + gn]     = __floats2half2_rn(e0, e1);
                if (gm + 8 < NN)
                    *(__half2*)&Eb[(size_t)(gm+8)*KSEG + gn] = __floats2half2_rn(e2, e3);
            }
        }
        s0 += __shfl_xor_sync(0xffffffffu, s0, 1);
        s0 += __shfl_xor_sync(0xffffffffu, s0, 2);
        s1 += __shfl_xor_sync(0xffffffffu, s1, 1);
        s1 += __shfl_xor_sync(0xffffffffu, s1, 2);
        if (tig == 0) {
            rs[wm*32 + mi*16 + gid][wn]     = s0;
            rs[wm*32 + mi*16 + gid + 8][wn] = s1;
        }
    }
    __syncthreads();
    if (tid < 128) {
        float tot = rs[tid][0] + rs[tid][1];
        d_psum[((size_t)b*16 + blockIdx.x)*MP + m0 + tid] = tot;
    }
}

// ---- K6a: hcat[:,64:128] = Adj @ h   (fp16 mma, tile 128x64) -----------------
#define ABUF 18432
#define AH_BROW 144
#define AH_BBUF (64*AH_BROW)               // 9216
#define AH_STAGE (ABUF + AH_BBUF)          // 27648
#define AH_SMEM (2*AH_STAGE)               // 55296

__global__ void __launch_bounds__(256) k_Ahmma() {
    extern __shared__ __align__(16) char smem[];
    uint32_t sb = smem_u32(smem);
    int tid = threadIdx.x, lane = tid & 31, w = tid >> 5;
    int b = blockIdx.y;
    int m0 = blockIdx.x * 128;
    const __half* Ag = d_Adjbf + (size_t)m0*KSEG;
    const __half* Bg = d_hcat + (size_t)b*MP*128;

    auto issue = [&](int kc, int buf) {
        uint32_t sA = sb + buf*AH_STAGE;
        uint32_t sB = sA + ABUF;
#pragma unroll
        for (int l = 0; l < 4; l++) {
            int seg = tid + l*256;
            int row = seg >> 3, c = seg & 7;
            cp16(sA + row*AROW + c*16, Ag + (size_t)row*KSEG + kc*KCHUNK + c*8);
        }
#pragma unroll
        for (int l = 0; l < 2; l++) {
            int seg = tid + l*256;
            int row = seg >> 3, c = seg & 7;
            cp16(sB + row*AH_BROW + c*16, Bg + (size_t)(kc*KCHUNK + row)*128 + c*8);
        }
        CP_COMMIT();
    };

    issue(0, 0);
    issue(1, 1);

    float c[2][4][4];
#pragma unroll
    for (int mi = 0; mi < 2; mi++)
#pragma unroll
        for (int nj = 0; nj < 4; nj++)
#pragma unroll
            for (int q = 0; q < 4; q++) c[mi][nj][q] = 0.f;

    int wm = w >> 1, wn = w & 1;
    for (int kc = 0; kc < NCHUNK; kc++) {
        CP_WAIT1();
        __syncthreads();
        int buf = kc & 1;
        uint32_t sA = sb + buf*AH_STAGE + (wm*32 + (lane & 15))*AROW + (lane >> 4)*16;
        uint32_t sB = sb + buf*AH_STAGE + ABUF;
#pragma unroll
        for (int ks = 0; ks < 4; ks++) {
            uint32_t af[2][4], bf[4][2];
#pragma unroll
            for (int mi = 0; mi < 2; mi++)
                ldm_x4(af[mi], sA + mi*16*AROW + ks*32);
#pragma unroll
            for (int nj = 0; nj < 4; nj++)
                ldm_x2_t(bf[nj], sB + (ks*16 + (lane & 15))*AH_BROW + (wn*32 + nj*8)*2);
#pragma unroll
            for (int mi = 0; mi < 2; mi++)
#pragma unroll
                for (int nj = 0; nj < 4; nj++)
                    mma_f16(c[mi][nj], af[mi], bf[nj]);
        }
        __syncthreads();
        if (kc + 2 < NCHUNK) issue(kc + 2, buf);
        else CP_COMMIT();
    }

    int gid = lane >> 2, tig = lane & 3;
#pragma unroll
    for (int mi = 0; mi < 2; mi++) {
        int gm = m0 + wm*32 + mi*16 + gid;
#pragma unroll
        for (int nj = 0; nj < 4; nj++) {
            int gn = wn*32 + nj*8 + tig*2;
            if (gm < NN)
                *(__half2*)&d_hcat[((size_t)b*MP + gm)*128 + 64 + gn] =
                    __halves2half2(__float2half_rn(c[mi][nj][0]), __float2half_rn(c[mi][nj][1]));
            if (gm + 8 < NN)
                *(__half2*)&d_hcat[((size_t)b*MP + gm + 8)*128 + 64 + gn] =
                    __halves2half2(__float2half_rn(c[mi][nj][2]), __float2half_rn(c[mi][nj][3]));
        }
    }
}

// ---- K6b: xg = softmax-normalized E @ hcat  (fp16 mma, tile 128x128) ---------
#define XG_BROW 272
#define XG_BBUF (64*XG_BROW)               // 17408
#define XG_STAGE (ABUF + XG_BBUF)          // 35840
#define XG_SMEM (2*XG_STAGE)               // 71680

__global__ void __launch_bounds__(256) k_xgmma() {
    extern __shared__ __align__(16) char smem[];
    __shared__ float invS[128];
    uint32_t sb = smem_u32(smem);
    int tid = threadIdx.x, lane = tid & 31, w = tid >> 5;
    int b = blockIdx.y;
    int m0 = blockIdx.x * 128;
    const __half* Ag = d_Ebf + ((size_t)b*MP + m0)*KSEG;
    const __half* Bg = d_hcat + (size_t)b*MP*128;

    auto issue = [&](int kc, int buf) {
        uint32_t sA = sb + buf*XG_STAGE;
        uint32_t sB = sA + ABUF;
#pragma unroll
        for (int l = 0; l < 4; l++) {
            int seg = tid + l*256;
            int row = seg >> 3, c = seg & 7;
            cp16(sA + row*AROW + c*16, Ag + (size_t)row*KSEG + kc*KCHUNK + c*8);
        }
#pragma unroll
        for (int l = 0; l < 4; l++) {
            int seg = tid + l*256;
            int row = seg >> 4, c = seg & 15;
            cp16(sB + row*XG_BROW + c*16, Bg + (size_t)(kc*KCHUNK + row)*128 + c*8);
        }
        CP_COMMIT();
    };

    issue(0, 0);
    issue(1, 1);

    if (tid < 128) {
        float s = 0.f;
#pragma unroll
        for (int nb = 0; nb < 16; nb++)
            s += d_psum[((size_t)b*16 + nb)*MP + m0 + tid];
        invS[tid] = 1.f / s;
    }

    float c[2][8][4];
#pragma unroll
    for (int mi = 0; mi < 2; mi++)
#pragma unroll
        for (int nj = 0; nj < 8; nj++)
#pragma unroll
            for (int q = 0; q < 4; q++) c[mi][nj][q] = 0.f;

    int wm = w >> 1, wn = w & 1;
    for (int kc = 0; kc < NCHUNK; kc++) {
        CP_WAIT1();
        __syncthreads();
        int buf = kc & 1;
        uint32_t sA = sb + buf*XG_STAGE + (wm*32 + (lane & 15))*AROW + (lane >> 4)*16;
        uint32_t sB = sb + buf*XG_STAGE + ABUF;
#pragma unroll
        for (int ks = 0; ks < 4; ks++) {
            uint32_t af[2][4], bf[8][2];
#pragma unroll
            for (int mi = 0; mi < 2; mi++)
                ldm_x4(af[mi], sA + mi*16*AROW + ks*32);
#pragma unroll
            for (int nj = 0; nj < 8; nj++)
                ldm_x2_t(bf[nj], sB + (ks*16 + (lane & 15))*XG_BROW + (wn*64 + nj*8)*2);
#pragma unroll
            for (int mi = 0; mi < 2; mi++)
#pragma unroll
                for (int nj = 0; nj < 8; nj++)
                    mma_f16(c[mi][nj], af[mi], bf[nj]);
        }
        __syncthreads();
        if (kc + 2 < NCHUNK) issue(kc + 2, buf);
        else CP_COMMIT();
    }

    int gid = lane >> 2, tig = lane & 3;
#pragma unroll
    for (int mi = 0; mi < 2; mi++) {
        int lr = wm*32 + mi*16 + gid;
        int gm = m0 + lr;
        float inv0 = invS[lr], inv1 = invS[lr + 8];
#pragma unroll
        for (int nj = 0; nj < 8; nj++) {
            int gn = wn*64 + nj*8 + tig*2;
            if (gm < NN)
                *(float2*)&d_xg[((size_t)b*NN + gm)*128 + gn] =
                    make_float2(c[mi][nj][0]*inv0, c[mi][nj][1]*inv0);
            if (gm + 8 < NN)
                *(float2*)&d_xg[((size_t)b*NN + gm + 8)*128 + gn] =
                    make_float2(c[mi][nj][2]*inv1, c[mi][nj][3]*inv1);
        }
    }
}

// ---------------- K7: weights = emb @ wp_flat (fp32) --------------------------
__global__ void k_wn(const float* __restrict__ emb, const float* __restrict__ wp) {
    __shared__ float Es[64][16];
    __shared__ float Ws[16][128];
    int n0 = blockIdx.y*64, c0 = blockIdx.x*128;
    int tid = threadIdx.x;
    for (int i=tid;i<1024;i+=256){ int r=i>>4, d=i&15; int n=n0+r; Es[r][d] = (n<NN)? emb[(size_t)n*16+d] : 0.f; }
    for (int i=tid;i<2048;i+=256){ int kr=i>>7, c=i&127; Ws[kr][c] = wp[(size_t)kr*8192 + c0 + c]; }
    __syncthreads();
    int ty=tid>>4, tx=tid&15;
    float acc[4][8];
#pragma unroll
    for (int i=0;i<4;i++)
#pragma unroll
        for (int j=0;j<8;j++) acc[i][j]=0.f;
#pragma unroll
    for (int d=0; d<16; d++){
        float ev[4], wv[8];
#pragma unroll
        for (int i=0;i<4;i++) ev[i]=Es[ty*4+i][d];
#pragma unroll
        for (int j=0;j<8;j++) wv[j]=Ws[d][tx*8+j];
#pragma unroll
        for (int i=0;i<4;i++)
#pragma unroll
            for (int j=0;j<8;j++) acc[i][j] += ev[i]*wv[j];
    }
#pragma unroll
    for (int i=0;i<4;i++){
        int n = n0+ty*4+i;
        if (n >= NN) continue;
#pragma unroll
        for (int j=0;j<8;j++)
            d_wn[(size_t)n*8192 + c0 + tx*8 + j] = acc[i][j];
    }
}

// ---------------- K8: g = xg @ W_n + bias_n -> gcat fp16 [gh|gl|gh] -----------
__global__ void k_g(const float* __restrict__ emb, const float* __restrict__ bp) {
    __shared__ float Wns[8192];
    __shared__ float xgs[8][128];
    __shared__ float bias_s[64];
    __shared__ float es[16];
    int n = blockIdx.x, tid = threadIdx.x;
    if (tid < 16) es[tid] = emb[(size_t)n*16+tid];
    for (int i=tid;i<8192;i+=256) Wns[i] = d_wn[(size_t)n*8192 + i];
    for (int i=tid;i<1024;i+=256){
        int b=i>>7, ki=i&127;
        xgs[b][ki] = d_xg[((size_t)b*NN+n)*128 + ki];
    }
    __syncthreads();
    if (tid < 64) {
        float bv = 0.f;
#pragma unroll
        for (int d=0; d<16; d++) bv += es[d]*bp[d*64+tid];
        bias_s[tid] = bv;
    }
    __syncthreads();
    int o = tid & 63;
#pragma unroll
    for (int rep=0; rep<2; rep++){
        int b = (tid>>6) + rep*4;
        float acc = bias_s[o];
#pragma unroll 8
        for (int ki=0; ki<128; ki++) acc += xgs[b][ki]*Wns[ki*64+o];
        __half gh = __float2half_rn(acc);
        __half gl = __float2half_rn(acc - __half2float(gh));
        size_t base = ((size_t)b*NN + n)*192;
        d_gcat[base + o]       = gh;
        d_gcat[base + 64 + o]  = gl;
        d_gcat[base + 128 + o] = gh;
    }
}

// ---------------- K9a: WoutT = [Wh;Wh;Wl] fp16 --------------------------------
__global__ void k_wprep(const float* __restrict__ Wout) {
    int o = blockIdx.x*256 + threadIdx.x;
    int h = blockIdx.y;
    float w = Wout[(size_t)o*64 + h];
    __half wh = __float2half_rn(w);
    __half wl = __float2half_rn(w - __half2float(wh));
    d_WoutT[(size_t)h*OUTC + o]         = wh;
    d_WoutT[(size_t)(64+h)*OUTC + o]    = wh;
    d_WoutT[(size_t)(128+h)*OUTC + o]   = wl;
}

// ---------------- K9b: out = 0.1*tanh(gcat @ WoutT + b_out) -------------------
#define MT 5
#define O_AROW 400
#define O_ABUF (128*O_AROW)    // 51200
#define O_BROW 272
#define O_BBUF (192*O_BROW)    // 52224
#define O_SMEM (O_BBUF + 2*O_ABUF + 512)   // 155136

__global__ void __launch_bounds__(256) k_outmma(const float* __restrict__ bout,
                                                float* __restrict__ out) {
    extern __shared__ __align__(16) char smem[];
    uint32_t sb = smem_u32(smem);
    float* boS = (float*)(smem + O_BBUF + 2*O_ABUF);
    int tid = threadIdx.x, lane = tid & 31, w = tid >> 5;
    int n0 = blockIdx.x * 128;
    int mg = blockIdx.y * MT;

#pragma unroll
    for (int l = 0; l < 12; l++) {
        int seg = tid + l*256;
        int row = seg >> 4, c = seg & 15;
        cp16(sb + row*O_BROW + c*16, d_WoutT + (size_t)row*OUTC + n0 + c*8);
    }
    CP_COMMIT();
    if (tid < 128) boS[tid] = bout[n0 + tid];

    auto issueA = [&](int i, int buf) {
        uint32_t sA = sb + O_BBUF + buf*O_ABUF;
        int m0 = (mg + i)*128;
#pragma unroll
        for (int l = 0; l < 12; l++) {
            int seg = tid + l*256;
            int row = seg / 24, c = seg % 24;
            cp16(sA + row*O_AROW + c*16, d_gcat + (size_t)(m0+row)*192 + c*8);
        }
        CP_COMMIT();
    };
    issueA(0, 0);

    int wm = w >> 1, wn = w & 1;
    int gid = lane >> 2, tig = lane & 3;

    for (int i = 0; i < MT; i++) {
        CP_WAIT0();
        __syncthreads();
        if (i + 1 < MT) issueA(i + 1, (i + 1) & 1);

        uint32_t sA = sb + O_BBUF + (i & 1)*O_ABUF + (wm*32 + (lane & 15))*O_AROW + (lane >> 4)*16;
        uint32_t sB = sb;
        float c[2][8][4];
#pragma unroll
        for (int mi = 0; mi < 2; mi++)
#pragma unroll
            for (int nj = 0; nj < 8; nj++)
#pragma unroll
                for (int q = 0; q < 4; q++) c[mi][nj][q] = 0.f;

#pragma unroll
        for (int kk = 0; kk < 12; kk++) {
            uint32_t af[2][4], bf[8][2];
#pragma unroll
            for (int mi = 0; mi < 2; mi++)
                ldm_x4(af[mi], sA + mi*16*O_AROW + kk*32);
#pragma unroll
            for (int nj = 0; nj < 8; nj++)
                ldm_x2_t(bf[nj], sB + (kk*16 + (lane & 15))*O_BROW + (wn*64 + nj*8)*2);
#pragma unroll
            for (int mi = 0; mi < 2; mi++)
#pragma unroll
                for (int nj = 0; nj < 8; nj++)
                    mma_f16(c[mi][nj], af[mi], bf[nj]);
        }

        int m0 = (mg + i)*128;
#pragma unroll
        for (int mi = 0; mi < 2; mi++) {
            int gm = m0 + wm*32 + mi*16 + gid;
#pragma unroll
            for (int nj = 0; nj < 8; nj++) {
                int cn = wn*64 + nj*8 + tig*2;
                int gn = n0 + cn;
                float b0 = boS[cn], b1 = boS[cn+1];
                float2 v0 = make_float2(0.1f*fast_tanh(c[mi][nj][0] + b0), 0.1f*fast_tanh(c[mi][nj][1] + b1));
                float2 v1 = make_float2(0.1f*fast_tanh(c[mi][nj][2] + b0), 0.1f*fast_tanh(c[mi][nj][3] + b1));
                *(float2*)&out[(size_t)gm*OUTC + gn]       = v0;
                *(float2*)&out[(size_t)(gm+8)*OUTC + gn]   = v1;
            }
        }
        __syncthreads();
    }
}

// ---------------- launch: fork independent kernels onto a side stream ---------
extern "C" void kernel_launch(void* const* d_in, const int* in_sizes, int n_in,
                              void* d_out, int out_size) {
    const float* z    = (const float*)d_in[0];
    const float* Win  = (const float*)d_in[1];
    const float* bin  = (const float*)d_in[2];
    const float* Wout = (const float*)d_in[3];
    const float* bout = (const float*)d_in[4];
    const float* emb  = (const float*)d_in[5];
    const float* wp   = (const float*)d_in[6];
    const float* bp   = (const float*)d_in[7];
    const float* w1   = (const float*)d_in[8];
    const float* w2   = (const float*)d_in[9];
    const float* vsM  = (const float*)d_in[10];
    const float* bs   = (const float*)d_in[11];
    float* out = (float*)d_out;
    (void)in_sizes; (void)n_in; (void)out_size;

    cudaFuncSetAttribute(k_mma,    cudaFuncAttributeMaxDynamicSharedMemorySize, SMEM_MMA);
    cudaFuncSetAttribute(k_Ahmma,  cudaFuncAttributeMaxDynamicSharedMemorySize, AH_SMEM);
    cudaFuncSetAttribute(k_xgmma,  cudaFuncAttributeMaxDynamicSharedMemorySize, XG_SMEM);
    cudaFuncSetAttribute(k_outmma, cudaFuncAttributeMaxDynamicSharedMemorySize, O_SMEM);

    // fresh per-call stream/events (deterministic, no static state)
    cudaStream_t s2;
    cudaStreamCreateWithFlags(&s2, cudaStreamNonBlocking);
    cudaEvent_t evFork, evAvs, evH, evS2;
    cudaEventCreateWithFlags(&evFork, cudaEventDisableTiming);
    cudaEventCreateWithFlags(&evAvs,  cudaEventDisableTiming);
    cudaEventCreateWithFlags(&evH,    cudaEventDisableTiming);
    cudaEventCreateWithFlags(&evS2,   cudaEventDisableTiming);

    cudaEventRecord(evFork, 0);
    cudaStreamWaitEvent(s2, evFork, 0);

    // side stream: input-only producers
    k_Avs<<<dim3(MP/256, MP), 256, 0, s2>>>(vsM);
    cudaEventRecord(evAvs, s2);
    k_adj<<<NN, 256, 0, s2>>>(emb);
    k_wprep<<<dim3(OUTC/256, 64), 256, 0, s2>>>(Wout);
    k_wn<<<dim3(8192/128, (NN+63)/64), 256, 0, s2>>>(emb, wp);

    // main stream: critical path
    k_hidden<<<(NB*NN)/16, 256>>>(z, Win, bin, w1, w2);
    cudaEventRecord(evH, 0);
    k_T2<<<dim3(NP/32, NP/32), 256>>>(bs);
    cudaStreamWaitEvent(0, evAvs, 0);
    k_mma<<<dim3(NP/128, MP/128, NB), 256, SMEM_MMA>>>();

    // side stream: Ahmma needs {adj (program order on s2), hidden (evH)}
    cudaStreamWaitEvent(s2, evH, 0);
    k_Ahmma<<<dim3(MP/128, NB), 256, AH_SMEM, s2>>>();
    cudaEventRecord(evS2, s2);

    // join and finish on main stream
    cudaStreamWaitEvent(0, evS2, 0);
    k_xgmma<<<dim3(MP/128, NB), 256, XG_SMEM>>>();
    k_g<<<NN, 256>>>(emb, bp);
    k_outmma<<<dim3(OUTC/128, (NB*NN)/(128*MT)), 256, O_SMEM>>>(bout, out);
}